// round 2
// baseline (speedup 1.0000x reference)
#include <cuda_runtime.h>
#include <math.h>

#define BB 2
#define TT 2048
#define DD 1024
#define HH 16
#define HD 64
#define NTOK (BB*TT)

#define THRESH_C 0.29514f
#define SHARP_C  15.0f

// ---------------- scratch (global __device__ arrays; no allocation) ----------------
__device__ float g_xn[NTOK*DD];
__device__ float g_qraw[NTOK*DD];
__device__ float g_kraw[NTOK*DD];
__device__ float g_qn[NTOK*DD];
__device__ float g_kn[NTOK*DD];
__device__ float g_v[NTOK*DD];
__device__ float g_gateq[BB*HH*TT];
__device__ float g_gatek[BB*HH*TT];
__device__ float g_coll[NTOK*DD];

// ---------------- LayerNorm: one block (256 thr) per token row ----------------
__global__ __launch_bounds__(256) void ln_kernel(const float* __restrict__ x,
                                                 const float* __restrict__ w,
                                                 const float* __restrict__ b) {
    int row = blockIdx.x;
    int tid = threadIdx.x;
    const float4* xr = (const float4*)(x + (size_t)row * DD);
    float4 v = xr[tid];
    float s  = v.x + v.y + v.z + v.w;
    float sq = v.x*v.x + v.y*v.y + v.z*v.z + v.w*v.w;
    #pragma unroll
    for (int o = 16; o > 0; o >>= 1) {
        s  += __shfl_xor_sync(0xffffffffu, s,  o);
        sq += __shfl_xor_sync(0xffffffffu, sq, o);
    }
    __shared__ float ss[8], ssq[8];
    int wid = tid >> 5, lid = tid & 31;
    if (lid == 0) { ss[wid] = s; ssq[wid] = sq; }
    __syncthreads();
    float ts = 0.f, tsq = 0.f;
    #pragma unroll
    for (int i = 0; i < 8; i++) { ts += ss[i]; tsq += ssq[i]; }
    float mu  = ts * (1.0f/DD);
    float var = tsq * (1.0f/DD) - mu*mu;
    float inv = rsqrtf(var + 1e-5f);
    float4 wv = ((const float4*)w)[tid];
    float4 bv = ((const float4*)b)[tid];
    float4 o;
    o.x = (v.x - mu) * inv * wv.x + bv.x;
    o.y = (v.y - mu) * inv * wv.y + bv.y;
    o.z = (v.z - mu) * inv * wv.z + bv.z;
    o.w = (v.w - mu) * inv * wv.w + bv.w;
    ((float4*)(g_xn + (size_t)row * DD))[tid] = o;
}

// ---------------- 128x128x8 fp32 SGEMM, 256 threads, 8x8 microtile ----------------
// C[M,N] = A[M,K] @ W[K,N] (+ bias)
__global__ __launch_bounds__(256) void sgemm128(const float* __restrict__ A,
                                                const float* __restrict__ W,
                                                float* __restrict__ C,
                                                const float* __restrict__ bias,
                                                int M, int N, int K) {
    __shared__ float As[8][128];
    __shared__ float Bs[8][128];
    int tid = threadIdx.x;
    int m0 = blockIdx.y * 128;
    int n0 = blockIdx.x * 128;
    int tx = tid & 15, ty = tid >> 4;

    float acc[8][8];
    #pragma unroll
    for (int i = 0; i < 8; i++)
        #pragma unroll
        for (int j = 0; j < 8; j++) acc[i][j] = 0.f;

    int arow = tid >> 1;           // 0..127
    int acol = (tid & 1) * 4;      // 0 or 4
    int brow = tid >> 5;           // 0..7
    int bcol = (tid & 31) * 4;     // 0..124
    const float* Aptr = A + (size_t)(m0 + arow) * K + acol;
    const float* Wptr = W + (size_t)brow * N + n0 + bcol;

    for (int k0 = 0; k0 < K; k0 += 8) {
        float4 a = *(const float4*)(Aptr + k0);
        float4 bb = *(const float4*)(Wptr + (size_t)k0 * N);
        As[acol+0][arow] = a.x;
        As[acol+1][arow] = a.y;
        As[acol+2][arow] = a.z;
        As[acol+3][arow] = a.w;
        *(float4*)&Bs[brow][bcol] = bb;
        __syncthreads();
        #pragma unroll
        for (int kk = 0; kk < 8; kk++) {
            float4 a0 = *(const float4*)&As[kk][ty*4];
            float4 a1 = *(const float4*)&As[kk][64 + ty*4];
            float4 b0 = *(const float4*)&Bs[kk][tx*4];
            float4 b1 = *(const float4*)&Bs[kk][64 + tx*4];
            float av[8] = {a0.x,a0.y,a0.z,a0.w,a1.x,a1.y,a1.z,a1.w};
            float bv[8] = {b0.x,b0.y,b0.z,b0.w,b1.x,b1.y,b1.z,b1.w};
            #pragma unroll
            for (int i = 0; i < 8; i++)
                #pragma unroll
                for (int j = 0; j < 8; j++)
                    acc[i][j] = fmaf(av[i], bv[j], acc[i][j]);
        }
        __syncthreads();
    }
    #pragma unroll
    for (int i = 0; i < 8; i++) {
        int m = m0 + ((i < 4) ? (ty*4 + i) : (64 + ty*4 + i - 4));
        #pragma unroll
        for (int j = 0; j < 8; j++) {
            int n = n0 + ((j < 4) ? (tx*4 + j) : (64 + tx*4 + j - 4));
            float val = acc[i][j];
            if (bias) val += bias[n];
            C[(size_t)m * N + n] = val;
        }
    }
}

// ---------------- per (token, head) l2-normalize + gate dot ----------------
// one warp per (token, head); 8 warps per block
__global__ __launch_bounds__(256) void norm_gate_kernel(const float* __restrict__ raw,
                                                        const float* __restrict__ g,
                                                        float* __restrict__ outp,
                                                        float* __restrict__ gate) {
    int task = blockIdx.x * 8 + (threadIdx.x >> 5);
    int lane = threadIdx.x & 31;
    int token = task >> 4;
    int h = task & 15;
    size_t base = (size_t)token * DD + h * HD;
    float2 v = ((const float2*)(raw + base))[lane];
    float sq = v.x*v.x + v.y*v.y;
    #pragma unroll
    for (int o = 16; o > 0; o >>= 1) sq += __shfl_xor_sync(0xffffffffu, sq, o);
    float nrm = sqrtf(sq);
    float inv = 1.0f / fmaxf(nrm, 1e-12f);
    float2 nv; nv.x = v.x * inv; nv.y = v.y * inv;
    ((float2*)(outp + base))[lane] = nv;
    float2 gv = ((const float2*)g)[lane];
    float gp = nv.x*gv.x + nv.y*gv.y;
    #pragma unroll
    for (int o = 16; o > 0; o >>= 1) gp += __shfl_xor_sync(0xffffffffu, gp, o);
    if (lane == 0) {
        int b = token / TT, t = token % TT;
        gate[((size_t)(b*HH + h)) * TT + t] = gp;
    }
}

// ---------------- attention: per (b,h), 128 t-rows per block, s-chunks of 64 ----------------
// smem floats: Qs 64*128 + Ks 64*64 + Vs 64*64 + Ms 64*128 + gq 128 + gk 64 = 24768
#define ATTN_SMEM_FLOATS 24768
__global__ __launch_bounds__(256) void attn_kernel() {
    extern __shared__ float sm[];
    float* Qs  = sm;                 // [d][t]  64 x 128
    float* Ks  = Qs + 64*128;        // [d][s]  64 x 64
    float* Vs  = Ks + 64*64;         // [s][d]  64 x 64
    float* Ms  = Vs + 64*64;         // [s][t]  64 x 128
    float* gqs = Ms + 64*128;        // [128]
    float* gks = gqs + 128;          // [64]

    int tid = threadIdx.x;
    int bh = blockIdx.y;
    int b = bh >> 4, h = bh & 15;
    int t0 = blockIdx.x * 128;

    size_t tokbase = ((size_t)b * TT) * DD + h * HD;   // + t*DD + d
    size_t gatebase = ((size_t)(b*HH + h)) * TT;

    int tx = tid & 15, ty = tid >> 4;

    // load Q tile transposed + gq
    {
        int tl0 = tid >> 4;
        int dc = (tid & 15) * 4;
        #pragma unroll
        for (int i = 0; i < 8; i++) {
            int tl = tl0 + i*16;
            float4 a = *(const float4*)(g_qn + tokbase + (size_t)(t0 + tl) * DD + dc);
            Qs[(dc+0)*128 + tl] = a.x;
            Qs[(dc+1)*128 + tl] = a.y;
            Qs[(dc+2)*128 + tl] = a.z;
            Qs[(dc+3)*128 + tl] = a.w;
        }
        if (tid < 128) gqs[tid] = g_gateq[gatebase + t0 + tid];
    }

    float cacc[8][4];
    #pragma unroll
    for (int i = 0; i < 8; i++)
        #pragma unroll
        for (int j = 0; j < 4; j++) cacc[i][j] = 0.f;

    for (int s0 = 0; s0 < TT; s0 += 64) {
        __syncthreads();   // prev phase C done (and, first iter, Q tile visible)
        // load K tile transposed, V tile direct, gk
        {
            int sl0 = tid >> 4;
            int dc = (tid & 15) * 4;
            #pragma unroll
            for (int i = 0; i < 4; i++) {
                int sl = sl0 + i*16;
                float4 a = *(const float4*)(g_kn + tokbase + (size_t)(s0 + sl) * DD + dc);
                Ks[(dc+0)*64 + sl] = a.x;
                Ks[(dc+1)*64 + sl] = a.y;
                Ks[(dc+2)*64 + sl] = a.z;
                Ks[(dc+3)*64 + sl] = a.w;
                float4 vv = *(const float4*)(g_v + tokbase + (size_t)(s0 + sl) * DD + dc);
                *(float4*)&Vs[sl*64 + dc] = vv;
            }
            if (tid < 64) gks[tid] = g_gatek[gatebase + s0 + tid];
        }
        __syncthreads();

        // phase A: S[t][s] = sum_d q k
        float sacc[8][4];
        #pragma unroll
        for (int i = 0; i < 8; i++)
            #pragma unroll
            for (int j = 0; j < 4; j++) sacc[i][j] = 0.f;
        #pragma unroll 8
        for (int d = 0; d < 64; d++) {
            float4 a0 = *(const float4*)&Qs[d*128 + ty*4];
            float4 a1 = *(const float4*)&Qs[d*128 + 64 + ty*4];
            float4 bb = *(const float4*)&Ks[d*64 + tx*4];
            float av[8] = {a0.x,a0.y,a0.z,a0.w,a1.x,a1.y,a1.z,a1.w};
            float bv[4] = {bb.x,bb.y,bb.z,bb.w};
            #pragma unroll
            for (int i = 0; i < 8; i++)
                #pragma unroll
                for (int j = 0; j < 4; j++)
                    sacc[i][j] = fmaf(av[i], bv[j], sacc[i][j]);
        }

        // phase B: modulation, write Ms[s][t]
        {
            float gkv[4];
            #pragma unroll
            for (int j = 0; j < 4; j++) gkv[j] = gks[tx*4 + j];
            float gqv[8];
            #pragma unroll
            for (int i = 0; i < 8; i++) {
                int tl = (i < 4) ? (ty*4 + i) : (64 + ty*4 + i - 4);
                gqv[i] = gqs[tl];
            }
            #pragma unroll
            for (int i = 0; i < 8; i++) {
                int tl = (i < 4) ? (ty*4 + i) : (64 + ty*4 + i - 4);
                #pragma unroll
                for (int j = 0; j < 4; j++) {
                    float z = (sacc[i][j] - THRESH_C) * SHARP_C;
                    float sig = __fdividef(1.0f, 1.0f + __expf(-z));
                    Ms[(tx*4 + j)*128 + tl] = sig * gqv[i] * gkv[j];
                }
            }
        }
        __syncthreads();

        // phase C: C[t][dd] += sum_s M[t][s] * V[s][dd]
        #pragma unroll 8
        for (int s = 0; s < 64; s++) {
            float4 m0 = *(const float4*)&Ms[s*128 + ty*4];
            float4 m1 = *(const float4*)&Ms[s*128 + 64 + ty*4];
            float4 vv = *(const float4*)&Vs[s*64 + tx*4];
            float mv[8] = {m0.x,m0.y,m0.z,m0.w,m1.x,m1.y,m1.z,m1.w};
            float vvv[4] = {vv.x,vv.y,vv.z,vv.w};
            #pragma unroll
            for (int i = 0; i < 8; i++)
                #pragma unroll
                for (int j = 0; j < 4; j++)
                    cacc[i][j] = fmaf(mv[i], vvv[j], cacc[i][j]);
        }
    }

    // write collapse into [B,T,D] layout (head-concat)
    #pragma unroll
    for (int i = 0; i < 8; i++) {
        int tl = (i < 4) ? (ty*4 + i) : (64 + ty*4 + i - 4);
        #pragma unroll
        for (int j = 0; j < 4; j++) {
            g_coll[tokbase + (size_t)(t0 + tl) * DD + tx*4 + j] = cacc[i][j];
        }
    }
}

// ---------------- launch ----------------
extern "C" void kernel_launch(void* const* d_in, const int* in_sizes, int n_in,
                              void* d_out, int out_size) {
    const float* x    = (const float*)d_in[0];
    const float* Wq   = (const float*)d_in[1];
    const float* Wk   = (const float*)d_in[2];
    const float* Wv   = (const float*)d_in[3];
    const float* gq   = (const float*)d_in[4];
    const float* gk   = (const float*)d_in[5];
    const float* Wo   = (const float*)d_in[6];
    const float* bo   = (const float*)d_in[7];
    const float* ln_w = (const float*)d_in[8];
    const float* ln_b = (const float*)d_in[9];
    float* out = (float*)d_out;

    float *p_xn, *p_qraw, *p_kraw, *p_qn, *p_kn, *p_v, *p_gq, *p_gk, *p_coll;
    cudaGetSymbolAddress((void**)&p_xn,   g_xn);
    cudaGetSymbolAddress((void**)&p_qraw, g_qraw);
    cudaGetSymbolAddress((void**)&p_kraw, g_kraw);
    cudaGetSymbolAddress((void**)&p_qn,   g_qn);
    cudaGetSymbolAddress((void**)&p_kn,   g_kn);
    cudaGetSymbolAddress((void**)&p_v,    g_v);
    cudaGetSymbolAddress((void**)&p_gq,   g_gateq);
    cudaGetSymbolAddress((void**)&p_gk,   g_gatek);
    cudaGetSymbolAddress((void**)&p_coll, g_coll);

    // 1. LayerNorm
    ln_kernel<<<NTOK, 256>>>(x, ln_w, ln_b);

    // 2. QKV projections
    dim3 gemm_grid(DD/128, NTOK/128);
    sgemm128<<<gemm_grid, 256>>>(p_xn, Wq, p_qraw, nullptr, NTOK, DD, DD);
    sgemm128<<<gemm_grid, 256>>>(p_xn, Wk, p_kraw, nullptr, NTOK, DD, DD);
    sgemm128<<<gemm_grid, 256>>>(x,    Wv, p_v,    nullptr, NTOK, DD, DD);

    // 3. l2 normalize q,k + gates
    norm_gate_kernel<<<(NTOK*HH)/8, 256>>>(p_qraw, gq, p_qn, p_gq);
    norm_gate_kernel<<<(NTOK*HH)/8, 256>>>(p_kraw, gk, p_kn, p_gk);

    // 4. attention
    int attn_smem = ATTN_SMEM_FLOATS * (int)sizeof(float);
    cudaFuncSetAttribute(attn_kernel, cudaFuncAttributeMaxDynamicSharedMemorySize, attn_smem);
    attn_kernel<<<dim3(TT/128, BB*HH), 256, attn_smem>>>();

    // 5. output projection + bias
    sgemm128<<<gemm_grid, 256>>>(p_coll, Wo, out, bo, NTOK, DD, DD);
}

// round 4
// speedup vs baseline: 1.2842x; 1.2842x over previous
#include <cuda_runtime.h>
#include <cuda_bf16.h>
#include <cstdint>
#include <math.h>

#define BB 2
#define TT 2048
#define DD 1024
#define HH 16
#define HD 64
#define NTOK (BB*TT)

#define GM 4096
#define GN 1024
#define GK 1024

#define THRESH_C 0.29514f
#define SHARP_C  15.0f

// ================= cp.async helpers =================
#define CP_ASYNC16(dst_u32, src_ptr) \
    asm volatile("cp.async.cg.shared.global [%0], [%1], 16;" \
        :: "r"(dst_u32), "l"(src_ptr) : "memory")
#define CP_COMMIT() asm volatile("cp.async.commit_group;" ::: "memory")
#define CP_WAIT0()  asm volatile("cp.async.wait_group 0;" ::: "memory")

__device__ __forceinline__ uint32_t smem_to_u32(const void* smem_ptr) {
    uint32_t addr;
    asm("{ .reg .u64 tmp; cvta.to.shared.u64 tmp, %1; cvt.u32.u64 %0, tmp; }"
        : "=r"(addr) : "l"(smem_ptr));
    return addr;
}

// mma.sync m16n8k16 bf16 (sm_80+ baseline; assembles at compute_103)
#define MMA16816(d, a0, a1, a2, a3, b0, b1) \
    asm volatile("mma.sync.aligned.m16n8k16.row.col.f32.bf16.bf16.f32 " \
        "{%0,%1,%2,%3}, {%4,%5,%6,%7}, {%8,%9}, {%0,%1,%2,%3};" \
        : "+f"((d)[0]), "+f"((d)[1]), "+f"((d)[2]), "+f"((d)[3]) \
        : "r"(a0), "r"(a1), "r"(a2), "r"(a3), "r"(b0), "r"(b1))

// ================= scratch (__device__ globals; no allocation) =================
__device__ float g_xn[NTOK*DD];
__device__ float g_qraw[NTOK*DD];
__device__ float g_kraw[NTOK*DD];
__device__ float g_qn[NTOK*DD];
__device__ float g_kn[NTOK*DD];
__device__ float g_v[NTOK*DD];
__device__ float g_gateq[BB*HH*TT];
__device__ float g_gatek[BB*HH*TT];
__device__ float g_coll[NTOK*DD];

// bf16 hi/lo splits
__device__ __nv_bfloat16 g_xh[NTOK*DD],  g_xl[NTOK*DD];
__device__ __nv_bfloat16 g_xnh[NTOK*DD], g_xnl[NTOK*DD];
__device__ __nv_bfloat16 g_ch[NTOK*DD],  g_cl[NTOK*DD];
// transposed weights [N,K] hi/lo
__device__ __nv_bfloat16 g_wqh[DD*DD], g_wql[DD*DD];
__device__ __nv_bfloat16 g_wkh[DD*DD], g_wkl[DD*DD];
__device__ __nv_bfloat16 g_wvh[DD*DD], g_wvl[DD*DD];
__device__ __nv_bfloat16 g_woh[DD*DD], g_wol[DD*DD];

// ================= LayerNorm =================
__global__ __launch_bounds__(256) void ln_kernel(const float* __restrict__ x,
                                                 const float* __restrict__ w,
                                                 const float* __restrict__ b) {
    int row = blockIdx.x;
    int tid = threadIdx.x;
    const float4* xr = (const float4*)(x + (size_t)row * DD);
    float4 v = xr[tid];
    float s  = v.x + v.y + v.z + v.w;
    float sq = v.x*v.x + v.y*v.y + v.z*v.z + v.w*v.w;
    #pragma unroll
    for (int o = 16; o > 0; o >>= 1) {
        s  += __shfl_xor_sync(0xffffffffu, s,  o);
        sq += __shfl_xor_sync(0xffffffffu, sq, o);
    }
    __shared__ float ss[8], ssq[8];
    int wid = tid >> 5, lid = tid & 31;
    if (lid == 0) { ss[wid] = s; ssq[wid] = sq; }
    __syncthreads();
    float ts = 0.f, tsq = 0.f;
    #pragma unroll
    for (int i = 0; i < 8; i++) { ts += ss[i]; tsq += ssq[i]; }
    float mu  = ts * (1.0f/DD);
    float var = tsq * (1.0f/DD) - mu*mu;
    float inv = rsqrtf(var + 1e-5f);
    float4 wv = ((const float4*)w)[tid];
    float4 bv = ((const float4*)b)[tid];
    float4 o;
    o.x = (v.x - mu) * inv * wv.x + bv.x;
    o.y = (v.y - mu) * inv * wv.y + bv.y;
    o.z = (v.z - mu) * inv * wv.z + bv.z;
    o.w = (v.w - mu) * inv * wv.w + bv.w;
    ((float4*)(g_xn + (size_t)row * DD))[tid] = o;
}

// ================= fp32 -> bf16 hi/lo split =================
__global__ __launch_bounds__(256) void split_kernel(const float* __restrict__ src,
                                                    __nv_bfloat16* __restrict__ hi,
                                                    __nv_bfloat16* __restrict__ lo) {
    int i = blockIdx.x * blockDim.x + threadIdx.x;   // per float4
    float4 v = ((const float4*)src)[i];
    __nv_bfloat16 h0 = __float2bfloat16(v.x);
    __nv_bfloat16 h1 = __float2bfloat16(v.y);
    __nv_bfloat16 h2 = __float2bfloat16(v.z);
    __nv_bfloat16 h3 = __float2bfloat16(v.w);
    __nv_bfloat16 l0 = __float2bfloat16(v.x - __bfloat162float(h0));
    __nv_bfloat16 l1 = __float2bfloat16(v.y - __bfloat162float(h1));
    __nv_bfloat16 l2 = __float2bfloat16(v.z - __bfloat162float(h2));
    __nv_bfloat16 l3 = __float2bfloat16(v.w - __bfloat162float(h3));
    __nv_bfloat162 hp0 = {h0, h1}, hp1 = {h2, h3};
    __nv_bfloat162 lp0 = {l0, l1}, lp1 = {l2, l3};
    uint2 hw, lw;
    hw.x = *(uint32_t*)&hp0; hw.y = *(uint32_t*)&hp1;
    lw.x = *(uint32_t*)&lp0; lw.y = *(uint32_t*)&lp1;
    ((uint2*)hi)[i] = hw;
    ((uint2*)lo)[i] = lw;
}

// ================= W[K,N] -> Wt[N,K] transpose + hi/lo split =================
__global__ __launch_bounds__(256) void tsplit_kernel(const float* __restrict__ W,
                                                     __nv_bfloat16* __restrict__ th,
                                                     __nv_bfloat16* __restrict__ tl) {
    __shared__ float tile[32][33];
    int bx = blockIdx.x * 32;   // n-block
    int by = blockIdx.y * 32;   // k-block
    int tx = threadIdx.x & 31;
    int ty = threadIdx.x >> 5;  // 0..7
    #pragma unroll
    for (int i = 0; i < 4; i++) {
        int k = by + ty + i*8;
        tile[ty + i*8][tx] = W[(size_t)k * DD + bx + tx];
    }
    __syncthreads();
    #pragma unroll
    for (int i = 0; i < 4; i++) {
        int n = bx + ty + i*8;
        int k = by + tx;
        float v = tile[tx][ty + i*8];
        __nv_bfloat16 h = __float2bfloat16(v);
        __nv_bfloat16 l = __float2bfloat16(v - __bfloat162float(h));
        th[(size_t)n * DD + k] = h;
        tl[(size_t)n * DD + k] = l;
    }
}

// ================= mma.sync bf16x3 GEMM: C[M,N] = A @ B^T (+bias) =================
// A: [GM, GK] K-major hi/lo. B: [GN, GK] K-major hi/lo (i.e. W^T).
// Block tile 128x128, K-chunk 32, double-buffered via cp.async.
// SMEM layout (bf16 units): per stage 4 arrays of 128 rows x PAD_K(=40) stride.
#define PAD_K 40
#define ARR_ELEMS (128*PAD_K)                 // 5120 bf16 = 10240 B
#define STAGE_ELEMS (4*ARR_ELEMS)             // 20480 bf16 = 40960 B
#define GEMM_SMEM_BYTES (2*STAGE_ELEMS*2)     // 81920 B

__device__ __forceinline__ void gemm_load_stage(uint32_t sm_u32, int stage,
        const __nv_bfloat16* __restrict__ Ah, const __nv_bfloat16* __restrict__ Al,
        const __nv_bfloat16* __restrict__ Bh, const __nv_bfloat16* __restrict__ Bl,
        int m0, int n0, int k0, int t) {
    uint32_t sbase = sm_u32 + (uint32_t)stage * (STAGE_ELEMS*2);
    #pragma unroll
    for (int o = 0; o < 2; o++) {
        int linear = t + o*256;          // 0..511
        int r  = linear >> 2;            // 0..127
        int c8 = linear & 3;             // 16B chunk within 64B row
        uint32_t soff = (uint32_t)(r*(PAD_K*2) + c8*16);
        size_t goffA = (size_t)(m0 + r) * GK + k0 + c8*8;
        size_t goffB = (size_t)(n0 + r) * GK + k0 + c8*8;
        CP_ASYNC16(sbase +              soff, Ah + goffA);
        CP_ASYNC16(sbase + 1*ARR_ELEMS*2 + soff, Al + goffA);
        CP_ASYNC16(sbase + 2*ARR_ELEMS*2 + soff, Bh + goffB);
        CP_ASYNC16(sbase + 3*ARR_ELEMS*2 + soff, Bl + goffB);
    }
}

__global__ __launch_bounds__(256) void mma_gemm(const __nv_bfloat16* __restrict__ Ah,
                                                const __nv_bfloat16* __restrict__ Al,
                                                const __nv_bfloat16* __restrict__ Bh,
                                                const __nv_bfloat16* __restrict__ Bl,
                                                float* __restrict__ C,
                                                const float* __restrict__ bias) {
    extern __shared__ __nv_bfloat16 smb[];
    uint32_t sm_u32 = smem_to_u32(smb);
    int t = threadIdx.x;
    int wid = t >> 5, lane = t & 31;
    int wm = wid & 1;          // 0..1 -> 64 M rows each
    int wn = wid >> 1;         // 0..3 -> 32 N cols each
    int g  = lane >> 2;        // groupID 0..7
    int tq = lane & 3;         // threadID_in_group

    int m0 = blockIdx.y * 128, n0 = blockIdx.x * 128;

    float acc[4][4][4];
    #pragma unroll
    for (int mi = 0; mi < 4; mi++)
        #pragma unroll
        for (int ni = 0; ni < 4; ni++)
            #pragma unroll
            for (int r = 0; r < 4; r++) acc[mi][ni][r] = 0.f;

    // prologue: stage 0
    gemm_load_stage(sm_u32, 0, Ah, Al, Bh, Bl, m0, n0, 0, t);
    CP_COMMIT();

    const int NIT = GK / 32;   // 32
    for (int it = 0; it < NIT; it++) {
        CP_WAIT0();
        __syncthreads();
        if (it + 1 < NIT) {
            gemm_load_stage(sm_u32, (it+1) & 1, Ah, Al, Bh, Bl, m0, n0, (it+1)*32, t);
            CP_COMMIT();
        }
        const __nv_bfloat16* S   = smb + (it & 1) * STAGE_ELEMS;
        const __nv_bfloat16* sAh = S;
        const __nv_bfloat16* sAl = S + ARR_ELEMS;
        const __nv_bfloat16* sBh = S + 2*ARR_ELEMS;
        const __nv_bfloat16* sBl = S + 3*ARR_ELEMS;

        #pragma unroll
        for (int kk = 0; kk < 32; kk += 16) {
            // A fragments for 4 m-tiles (hi & lo)
            uint32_t ah[4][4], al[4][4];
            #pragma unroll
            for (int mi = 0; mi < 4; mi++) {
                int base = (wm*64 + mi*16 + g) * PAD_K + kk + tq*2;
                ah[mi][0] = *(const uint32_t*)(sAh + base);
                ah[mi][1] = *(const uint32_t*)(sAh + base + 8*PAD_K);
                ah[mi][2] = *(const uint32_t*)(sAh + base + 8);
                ah[mi][3] = *(const uint32_t*)(sAh + base + 8*PAD_K + 8);
                al[mi][0] = *(const uint32_t*)(sAl + base);
                al[mi][1] = *(const uint32_t*)(sAl + base + 8*PAD_K);
                al[mi][2] = *(const uint32_t*)(sAl + base + 8);
                al[mi][3] = *(const uint32_t*)(sAl + base + 8*PAD_K + 8);
            }
            #pragma unroll
            for (int ni = 0; ni < 4; ni++) {
                int bb = (wn*32 + ni*8 + g) * PAD_K + kk + tq*2;
                uint32_t bh0 = *(const uint32_t*)(sBh + bb);
                uint32_t bh1 = *(const uint32_t*)(sBh + bb + 8);
                uint32_t bl0 = *(const uint32_t*)(sBl + bb);
                uint32_t bl1 = *(const uint32_t*)(sBl + bb + 8);
                #pragma unroll
                for (int mi = 0; mi < 4; mi++) {
                    MMA16816(acc[mi][ni], ah[mi][0], ah[mi][1], ah[mi][2], ah[mi][3], bh0, bh1);
                    MMA16816(acc[mi][ni], al[mi][0], al[mi][1], al[mi][2], al[mi][3], bh0, bh1);
                    MMA16816(acc[mi][ni], ah[mi][0], ah[mi][1], ah[mi][2], ah[mi][3], bl0, bl1);
                }
            }
        }
    }

    // epilogue
    #pragma unroll
    for (int mi = 0; mi < 4; mi++) {
        int row = m0 + wm*64 + mi*16 + g;
        #pragma unroll
        for (int ni = 0; ni < 4; ni++) {
            int col = n0 + wn*32 + ni*8 + tq*2;
            float b0 = 0.f, b1 = 0.f;
            if (bias) { b0 = bias[col]; b1 = bias[col+1]; }
            float2 v0 = { acc[mi][ni][0] + b0, acc[mi][ni][1] + b1 };
            float2 v1 = { acc[mi][ni][2] + b0, acc[mi][ni][3] + b1 };
            *(float2*)(C + (size_t)row * GN + col)       = v0;
            *(float2*)(C + (size_t)(row+8) * GN + col)   = v1;
        }
    }
}

// ================= per (token, head) l2-normalize + gate dot =================
__global__ __launch_bounds__(256) void norm_gate_kernel(const float* __restrict__ raw,
                                                        const float* __restrict__ g,
                                                        float* __restrict__ outp,
                                                        float* __restrict__ gate) {
    int task = blockIdx.x * 8 + (threadIdx.x >> 5);
    int lane = threadIdx.x & 31;
    int token = task >> 4;
    int h = task & 15;
    size_t base = (size_t)token * DD + h * HD;
    float2 v = ((const float2*)(raw + base))[lane];
    float sq = v.x*v.x + v.y*v.y;
    #pragma unroll
    for (int o = 16; o > 0; o >>= 1) sq += __shfl_xor_sync(0xffffffffu, sq, o);
    float nrm = sqrtf(sq);
    float inv = 1.0f / fmaxf(nrm, 1e-12f);
    float2 nv; nv.x = v.x * inv; nv.y = v.y * inv;
    ((float2*)(outp + base))[lane] = nv;
    float2 gv = ((const float2*)g)[lane];
    float gp = nv.x*gv.x + nv.y*gv.y;
    #pragma unroll
    for (int o = 16; o > 0; o >>= 1) gp += __shfl_xor_sync(0xffffffffu, gp, o);
    if (lane == 0) {
        int b = token / TT, t = token % TT;
        gate[((size_t)(b*HH + h)) * TT + t] = gp;
    }
}

// ================= attention (fp32 SIMT) =================
#define ATTN_SMEM_FLOATS 24768
__global__ __launch_bounds__(256) void attn_kernel() {
    extern __shared__ float smf[];
    float* Qs  = smf;
    float* Ks  = Qs + 64*128;
    float* Vs  = Ks + 64*64;
    float* Ms  = Vs + 64*64;
    float* gqs = Ms + 64*128;
    float* gks = gqs + 128;

    int tid = threadIdx.x;
    int bh = blockIdx.y;
    int b = bh >> 4, h = bh & 15;
    int t0 = blockIdx.x * 128;

    size_t tokbase = ((size_t)b * TT) * DD + h * HD;
    size_t gatebase = ((size_t)(b*HH + h)) * TT;

    int tx = tid & 15, ty = tid >> 4;

    {
        int tl0 = tid >> 4;
        int dc = (tid & 15) * 4;
        #pragma unroll
        for (int i = 0; i < 8; i++) {
            int tl = tl0 + i*16;
            float4 a = *(const float4*)(g_qn + tokbase + (size_t)(t0 + tl) * DD + dc);
            Qs[(dc+0)*128 + tl] = a.x;
            Qs[(dc+1)*128 + tl] = a.y;
            Qs[(dc+2)*128 + tl] = a.z;
            Qs[(dc+3)*128 + tl] = a.w;
        }
        if (tid < 128) gqs[tid] = g_gateq[gatebase + t0 + tid];
    }

    float cacc[8][4];
    #pragma unroll
    for (int i = 0; i < 8; i++)
        #pragma unroll
        for (int j = 0; j < 4; j++) cacc[i][j] = 0.f;

    for (int s0 = 0; s0 < TT; s0 += 64) {
        __syncthreads();
        {
            int sl0 = tid >> 4;
            int dc = (tid & 15) * 4;
            #pragma unroll
            for (int i = 0; i < 4; i++) {
                int sl = sl0 + i*16;
                float4 a = *(const float4*)(g_kn + tokbase + (size_t)(s0 + sl) * DD + dc);
                Ks[(dc+0)*64 + sl] = a.x;
                Ks[(dc+1)*64 + sl] = a.y;
                Ks[(dc+2)*64 + sl] = a.z;
                Ks[(dc+3)*64 + sl] = a.w;
                float4 vv = *(const float4*)(g_v + tokbase + (size_t)(s0 + sl) * DD + dc);
                *(float4*)&Vs[sl*64 + dc] = vv;
            }
            if (tid < 64) gks[tid] = g_gatek[gatebase + s0 + tid];
        }
        __syncthreads();

        float sacc[8][4];
        #pragma unroll
        for (int i = 0; i < 8; i++)
            #pragma unroll
            for (int j = 0; j < 4; j++) sacc[i][j] = 0.f;
        #pragma unroll 8
        for (int d = 0; d < 64; d++) {
            float4 a0 = *(const float4*)&Qs[d*128 + ty*4];
            float4 a1 = *(const float4*)&Qs[d*128 + 64 + ty*4];
            float4 bb = *(const float4*)&Ks[d*64 + tx*4];
            float av[8] = {a0.x,a0.y,a0.z,a0.w,a1.x,a1.y,a1.z,a1.w};
            float bv[4] = {bb.x,bb.y,bb.z,bb.w};
            #pragma unroll
            for (int i = 0; i < 8; i++)
                #pragma unroll
                for (int j = 0; j < 4; j++)
                    sacc[i][j] = fmaf(av[i], bv[j], sacc[i][j]);
        }

        {
            float gkv[4];
            #pragma unroll
            for (int j = 0; j < 4; j++) gkv[j] = gks[tx*4 + j];
            float gqv[8];
            #pragma unroll
            for (int i = 0; i < 8; i++) {
                int tl = (i < 4) ? (ty*4 + i) : (64 + ty*4 + i - 4);
                gqv[i] = gqs[tl];
            }
            #pragma unroll
            for (int i = 0; i < 8; i++) {
                int tl = (i < 4) ? (ty*4 + i) : (64 + ty*4 + i - 4);
                #pragma unroll
                for (int j = 0; j < 4; j++) {
                    float z = (sacc[i][j] - THRESH_C) * SHARP_C;
                    float sig = __fdividef(1.0f, 1.0f + __expf(-z));
                    Ms[(tx*4 + j)*128 + tl] = sig * gqv[i] * gkv[j];
                }
            }
        }
        __syncthreads();

        #pragma unroll 8
        for (int s = 0; s < 64; s++) {
            float4 m0v = *(const float4*)&Ms[s*128 + ty*4];
            float4 m1v = *(const float4*)&Ms[s*128 + 64 + ty*4];
            float4 vv = *(const float4*)&Vs[s*64 + tx*4];
            float mv[8] = {m0v.x,m0v.y,m0v.z,m0v.w,m1v.x,m1v.y,m1v.z,m1v.w};
            float vvv[4] = {vv.x,vv.y,vv.z,vv.w};
            #pragma unroll
            for (int i = 0; i < 8; i++)
                #pragma unroll
                for (int j = 0; j < 4; j++)
                    cacc[i][j] = fmaf(mv[i], vvv[j], cacc[i][j]);
        }
    }

    #pragma unroll
    for (int i = 0; i < 8; i++) {
        int tl = (i < 4) ? (ty*4 + i) : (64 + ty*4 + i - 4);
        #pragma unroll
        for (int j = 0; j < 4; j++) {
            g_coll[tokbase + (size_t)(t0 + tl) * DD + tx*4 + j] = cacc[i][j];
        }
    }
}

// ================= launch =================
extern "C" void kernel_launch(void* const* d_in, const int* in_sizes, int n_in,
                              void* d_out, int out_size) {
    const float* x    = (const float*)d_in[0];
    const float* Wq   = (const float*)d_in[1];
    const float* Wk   = (const float*)d_in[2];
    const float* Wv   = (const float*)d_in[3];
    const float* gq   = (const float*)d_in[4];
    const float* gk   = (const float*)d_in[5];
    const float* Wo   = (const float*)d_in[6];
    const float* bo   = (const float*)d_in[7];
    const float* ln_w = (const float*)d_in[8];
    const float* ln_b = (const float*)d_in[9];
    float* out = (float*)d_out;

    float *p_xn, *p_qraw, *p_kraw, *p_qn, *p_kn, *p_v, *p_gq, *p_gk, *p_coll;
    cudaGetSymbolAddress((void**)&p_xn,   g_xn);
    cudaGetSymbolAddress((void**)&p_qraw, g_qraw);
    cudaGetSymbolAddress((void**)&p_kraw, g_kraw);
    cudaGetSymbolAddress((void**)&p_qn,   g_qn);
    cudaGetSymbolAddress((void**)&p_kn,   g_kn);
    cudaGetSymbolAddress((void**)&p_v,    g_v);
    cudaGetSymbolAddress((void**)&p_gq,   g_gateq);
    cudaGetSymbolAddress((void**)&p_gk,   g_gatek);
    cudaGetSymbolAddress((void**)&p_coll, g_coll);

    __nv_bfloat16 *p_xh,*p_xl,*p_xnh,*p_xnl,*p_ch,*p_cl;
    __nv_bfloat16 *p_wqh,*p_wql,*p_wkh,*p_wkl,*p_wvh,*p_wvl,*p_woh,*p_wol;
    cudaGetSymbolAddress((void**)&p_xh,  g_xh);
    cudaGetSymbolAddress((void**)&p_xl,  g_xl);
    cudaGetSymbolAddress((void**)&p_xnh, g_xnh);
    cudaGetSymbolAddress((void**)&p_xnl, g_xnl);
    cudaGetSymbolAddress((void**)&p_ch,  g_ch);
    cudaGetSymbolAddress((void**)&p_cl,  g_cl);
    cudaGetSymbolAddress((void**)&p_wqh, g_wqh);
    cudaGetSymbolAddress((void**)&p_wql, g_wql);
    cudaGetSymbolAddress((void**)&p_wkh, g_wkh);
    cudaGetSymbolAddress((void**)&p_wkl, g_wkl);
    cudaGetSymbolAddress((void**)&p_wvh, g_wvh);
    cudaGetSymbolAddress((void**)&p_wvl, g_wvl);
    cudaGetSymbolAddress((void**)&p_woh, g_woh);
    cudaGetSymbolAddress((void**)&p_wol, g_wol);

    cudaFuncSetAttribute(mma_gemm, cudaFuncAttributeMaxDynamicSharedMemorySize, GEMM_SMEM_BYTES);
    cudaFuncSetAttribute(attn_kernel, cudaFuncAttributeMaxDynamicSharedMemorySize,
                         ATTN_SMEM_FLOATS * (int)sizeof(float));

    // 1. LayerNorm
    ln_kernel<<<NTOK, 256>>>(x, ln_w, ln_b);

    // 2. bf16 splits: activations + weights (transposed)
    int split_blocks = (NTOK * DD / 4) / 256;
    split_kernel<<<split_blocks, 256>>>(x,    p_xh,  p_xl);
    split_kernel<<<split_blocks, 256>>>(p_xn, p_xnh, p_xnl);
    dim3 tgrid(DD/32, DD/32);
    tsplit_kernel<<<tgrid, 256>>>(Wq, p_wqh, p_wql);
    tsplit_kernel<<<tgrid, 256>>>(Wk, p_wkh, p_wkl);
    tsplit_kernel<<<tgrid, 256>>>(Wv, p_wvh, p_wvl);
    tsplit_kernel<<<tgrid, 256>>>(Wo, p_woh, p_wol);

    // 3. QKV projections via mma.sync bf16x3
    dim3 ggrid(GN/128, GM/128);
    mma_gemm<<<ggrid, 256, GEMM_SMEM_BYTES>>>(p_xnh, p_xnl, p_wqh, p_wql, p_qraw, nullptr);
    mma_gemm<<<ggrid, 256, GEMM_SMEM_BYTES>>>(p_xnh, p_xnl, p_wkh, p_wkl, p_kraw, nullptr);
    mma_gemm<<<ggrid, 256, GEMM_SMEM_BYTES>>>(p_xh,  p_xl,  p_wvh, p_wvl, p_v,    nullptr);

    // 4. l2 normalize q,k + gates
    norm_gate_kernel<<<(NTOK*HH)/8, 256>>>(p_qraw, gq, p_qn, p_gq);
    norm_gate_kernel<<<(NTOK*HH)/8, 256>>>(p_kraw, gk, p_kn, p_gk);

    // 5. attention (fp32 SIMT)
    attn_kernel<<<dim3(TT/128, BB*HH), 256, ATTN_SMEM_FLOATS * (int)sizeof(float)>>>();

    // 6. output projection: split collapse, then MMA with bias
    split_kernel<<<split_blocks, 256>>>(p_coll, p_ch, p_cl);
    mma_gemm<<<ggrid, 256, GEMM_SMEM_BYTES>>>(p_ch, p_cl, p_woh, p_wol, out, bo);
}

// round 5
// speedup vs baseline: 2.5279x; 1.9685x over previous
#include <cuda_runtime.h>
#include <cuda_bf16.h>
#include <cstdint>
#include <math.h>

#define BB 2
#define TT 2048
#define DD 1024
#define HH 16
#define HD 64
#define NTOK (BB*TT)

#define GM 4096
#define GN 1024
#define GK 1024

#define THRESH_C 0.29514f
#define SHARP_C  15.0f

// ================= cp.async helpers =================
#define CP_ASYNC16(dst_u32, src_ptr) \
    asm volatile("cp.async.cg.shared.global [%0], [%1], 16;" \
        :: "r"(dst_u32), "l"(src_ptr) : "memory")
#define CP_COMMIT() asm volatile("cp.async.commit_group;" ::: "memory")
#define CP_WAIT0()  asm volatile("cp.async.wait_group 0;" ::: "memory")

__device__ __forceinline__ uint32_t smem_to_u32(const void* smem_ptr) {
    uint32_t addr;
    asm("{ .reg .u64 tmp; cvta.to.shared.u64 tmp, %1; cvt.u32.u64 %0, tmp; }"
        : "=r"(addr) : "l"(smem_ptr));
    return addr;
}

// mma.sync m16n8k16 bf16
#define MMA16816(d, a0, a1, a2, a3, b0, b1) \
    asm volatile("mma.sync.aligned.m16n8k16.row.col.f32.bf16.bf16.f32 " \
        "{%0,%1,%2,%3}, {%4,%5,%6,%7}, {%8,%9}, {%0,%1,%2,%3};" \
        : "+f"((d)[0]), "+f"((d)[1]), "+f"((d)[2]), "+f"((d)[3]) \
        : "r"(a0), "r"(a1), "r"(a2), "r"(a3), "r"(b0), "r"(b1))

// pack two fp32 -> bf16x2 (flo -> low half, fhi -> high half)
__device__ __forceinline__ uint32_t packbf(float flo, float fhi) {
    uint32_t r;
    asm("cvt.rn.bf16x2.f32 %0, %1, %2;" : "=r"(r) : "f"(fhi), "f"(flo));
    return r;
}

// ================= scratch =================
__device__ float g_xn[NTOK*DD];
__device__ float g_qraw[NTOK*DD];
__device__ float g_kraw[NTOK*DD];
__device__ float g_v[NTOK*DD];
__device__ float g_gateq[BB*HH*TT];
__device__ float g_gatek[BB*HH*TT];
__device__ float g_coll[NTOK*DD];

__device__ __nv_bfloat16 g_xh[NTOK*DD],  g_xl[NTOK*DD];
__device__ __nv_bfloat16 g_xnh[NTOK*DD], g_xnl[NTOK*DD];
__device__ __nv_bfloat16 g_ch[NTOK*DD],  g_cl[NTOK*DD];
__device__ __nv_bfloat16 g_wqh[DD*DD], g_wql[DD*DD];
__device__ __nv_bfloat16 g_wkh[DD*DD], g_wkl[DD*DD];
__device__ __nv_bfloat16 g_wvh[DD*DD], g_wvl[DD*DD];
__device__ __nv_bfloat16 g_woh[DD*DD], g_wol[DD*DD];
// normalized q/k bf16 hi/lo (token-major, [token*DD + h*64 + d])
__device__ __nv_bfloat16 g_qbh[NTOK*DD], g_qbl[NTOK*DD];
__device__ __nv_bfloat16 g_kbh[NTOK*DD], g_kbl[NTOK*DD];
// V transposed per batch: [b*DD + col][t], bf16 hi/lo
__device__ __nv_bfloat16 g_vth[BB*DD*TT], g_vtl[BB*DD*TT];

// ================= LayerNorm =================
__global__ __launch_bounds__(256) void ln_kernel(const float* __restrict__ x,
                                                 const float* __restrict__ w,
                                                 const float* __restrict__ b) {
    int row = blockIdx.x;
    int tid = threadIdx.x;
    const float4* xr = (const float4*)(x + (size_t)row * DD);
    float4 v = xr[tid];
    float s  = v.x + v.y + v.z + v.w;
    float sq = v.x*v.x + v.y*v.y + v.z*v.z + v.w*v.w;
    #pragma unroll
    for (int o = 16; o > 0; o >>= 1) {
        s  += __shfl_xor_sync(0xffffffffu, s,  o);
        sq += __shfl_xor_sync(0xffffffffu, sq, o);
    }
    __shared__ float ss[8], ssq[8];
    int wid = tid >> 5, lid = tid & 31;
    if (lid == 0) { ss[wid] = s; ssq[wid] = sq; }
    __syncthreads();
    float ts = 0.f, tsq = 0.f;
    #pragma unroll
    for (int i = 0; i < 8; i++) { ts += ss[i]; tsq += ssq[i]; }
    float mu  = ts * (1.0f/DD);
    float var = tsq * (1.0f/DD) - mu*mu;
    float inv = rsqrtf(var + 1e-5f);
    float4 wv = ((const float4*)w)[tid];
    float4 bv = ((const float4*)b)[tid];
    float4 o;
    o.x = (v.x - mu) * inv * wv.x + bv.x;
    o.y = (v.y - mu) * inv * wv.y + bv.y;
    o.z = (v.z - mu) * inv * wv.z + bv.z;
    o.w = (v.w - mu) * inv * wv.w + bv.w;
    ((float4*)(g_xn + (size_t)row * DD))[tid] = o;
}

// ================= fp32 -> bf16 hi/lo split =================
__global__ __launch_bounds__(256) void split_kernel(const float* __restrict__ src,
                                                    __nv_bfloat16* __restrict__ hi,
                                                    __nv_bfloat16* __restrict__ lo) {
    int i = blockIdx.x * blockDim.x + threadIdx.x;
    float4 v = ((const float4*)src)[i];
    uint32_t h0 = packbf(v.x, v.y);
    uint32_t h1 = packbf(v.z, v.w);
    float lx = v.x - __uint_as_float(h0 << 16);
    float ly = v.y - __uint_as_float(h0 & 0xffff0000u);
    float lz = v.z - __uint_as_float(h1 << 16);
    float lw = v.w - __uint_as_float(h1 & 0xffff0000u);
    uint2 hw = { h0, h1 };
    uint2 lw2 = { packbf(lx, ly), packbf(lz, lw) };
    ((uint2*)hi)[i] = hw;
    ((uint2*)lo)[i] = lw2;
}

// ================= W[K,N] -> Wt[N,K] transpose + hi/lo split =================
__global__ __launch_bounds__(256) void tsplit_kernel(const float* __restrict__ W,
                                                     __nv_bfloat16* __restrict__ th,
                                                     __nv_bfloat16* __restrict__ tl) {
    __shared__ float tile[32][33];
    int bx = blockIdx.x * 32;
    int by = blockIdx.y * 32;
    int tx = threadIdx.x & 31;
    int ty = threadIdx.x >> 5;
    #pragma unroll
    for (int i = 0; i < 4; i++) {
        int k = by + ty + i*8;
        tile[ty + i*8][tx] = W[(size_t)k * DD + bx + tx];
    }
    __syncthreads();
    #pragma unroll
    for (int i = 0; i < 4; i++) {
        int n = bx + ty + i*8;
        int k = by + tx;
        float v = tile[tx][ty + i*8];
        __nv_bfloat16 h = __float2bfloat16(v);
        __nv_bfloat16 l = __float2bfloat16(v - __bfloat162float(h));
        th[(size_t)n * DD + k] = h;
        tl[(size_t)n * DD + k] = l;
    }
}

// ================= V[b][t][col] -> Vt[b*DD+col][t] transpose + hi/lo split =================
__global__ __launch_bounds__(256) void vtsplit_kernel(const float* __restrict__ V,
                                                      __nv_bfloat16* __restrict__ th,
                                                      __nv_bfloat16* __restrict__ tl) {
    __shared__ float tile[32][33];
    int b  = blockIdx.z;
    int t0 = blockIdx.x * 32;
    int d0 = blockIdx.y * 32;
    int tx = threadIdx.x & 31;
    int ty = threadIdx.x >> 5;
    #pragma unroll
    for (int i = 0; i < 4; i++) {
        int tt = t0 + ty + i*8;
        tile[ty + i*8][tx] = V[((size_t)(b*TT + tt)) * DD + d0 + tx];
    }
    __syncthreads();
    #pragma unroll
    for (int i = 0; i < 4; i++) {
        int d = d0 + ty + i*8;
        int tt = t0 + tx;
        float v = tile[tx][ty + i*8];
        __nv_bfloat16 h = __float2bfloat16(v);
        __nv_bfloat16 l = __float2bfloat16(v - __bfloat162float(h));
        th[((size_t)(b*DD + d)) * TT + tt] = h;
        tl[((size_t)(b*DD + d)) * TT + tt] = l;
    }
}

// ================= mma.sync bf16x3 GEMM (projections) =================
#define PAD_K 40
#define ARR_ELEMS (128*PAD_K)
#define STAGE_ELEMS (4*ARR_ELEMS)
#define GEMM_SMEM_BYTES (2*STAGE_ELEMS*2)

__device__ __forceinline__ void gemm_load_stage(uint32_t sm_u32, int stage,
        const __nv_bfloat16* __restrict__ Ah, const __nv_bfloat16* __restrict__ Al,
        const __nv_bfloat16* __restrict__ Bh, const __nv_bfloat16* __restrict__ Bl,
        int m0, int n0, int k0, int t) {
    uint32_t sbase = sm_u32 + (uint32_t)stage * (STAGE_ELEMS*2);
    #pragma unroll
    for (int o = 0; o < 2; o++) {
        int linear = t + o*256;
        int r  = linear >> 2;
        int c8 = linear & 3;
        uint32_t soff = (uint32_t)(r*(PAD_K*2) + c8*16);
        size_t goffA = (size_t)(m0 + r) * GK + k0 + c8*8;
        size_t goffB = (size_t)(n0 + r) * GK + k0 + c8*8;
        CP_ASYNC16(sbase +              soff, Ah + goffA);
        CP_ASYNC16(sbase + 1*ARR_ELEMS*2 + soff, Al + goffA);
        CP_ASYNC16(sbase + 2*ARR_ELEMS*2 + soff, Bh + goffB);
        CP_ASYNC16(sbase + 3*ARR_ELEMS*2 + soff, Bl + goffB);
    }
}

__global__ __launch_bounds__(256) void mma_gemm(const __nv_bfloat16* __restrict__ Ah,
                                                const __nv_bfloat16* __restrict__ Al,
                                                const __nv_bfloat16* __restrict__ Bh,
                                                const __nv_bfloat16* __restrict__ Bl,
                                                float* __restrict__ C,
                                                const float* __restrict__ bias) {
    extern __shared__ __nv_bfloat16 smb[];
    uint32_t sm_u32 = smem_to_u32(smb);
    int t = threadIdx.x;
    int wid = t >> 5, lane = t & 31;
    int wm = wid & 1;
    int wn = wid >> 1;
    int g  = lane >> 2;
    int tq = lane & 3;

    int m0 = blockIdx.y * 128, n0 = blockIdx.x * 128;

    float acc[4][4][4];
    #pragma unroll
    for (int mi = 0; mi < 4; mi++)
        #pragma unroll
        for (int ni = 0; ni < 4; ni++)
            #pragma unroll
            for (int r = 0; r < 4; r++) acc[mi][ni][r] = 0.f;

    gemm_load_stage(sm_u32, 0, Ah, Al, Bh, Bl, m0, n0, 0, t);
    CP_COMMIT();

    const int NIT = GK / 32;
    for (int it = 0; it < NIT; it++) {
        CP_WAIT0();
        __syncthreads();
        if (it + 1 < NIT) {
            gemm_load_stage(sm_u32, (it+1) & 1, Ah, Al, Bh, Bl, m0, n0, (it+1)*32, t);
            CP_COMMIT();
        }
        const __nv_bfloat16* S   = smb + (it & 1) * STAGE_ELEMS;
        const __nv_bfloat16* sAh = S;
        const __nv_bfloat16* sAl = S + ARR_ELEMS;
        const __nv_bfloat16* sBh = S + 2*ARR_ELEMS;
        const __nv_bfloat16* sBl = S + 3*ARR_ELEMS;

        #pragma unroll
        for (int kk = 0; kk < 32; kk += 16) {
            uint32_t ah[4][4], al[4][4];
            #pragma unroll
            for (int mi = 0; mi < 4; mi++) {
                int base = (wm*64 + mi*16 + g) * PAD_K + kk + tq*2;
                ah[mi][0] = *(const uint32_t*)(sAh + base);
                ah[mi][1] = *(const uint32_t*)(sAh + base + 8*PAD_K);
                ah[mi][2] = *(const uint32_t*)(sAh + base + 8);
                ah[mi][3] = *(const uint32_t*)(sAh + base + 8*PAD_K + 8);
                al[mi][0] = *(const uint32_t*)(sAl + base);
                al[mi][1] = *(const uint32_t*)(sAl + base + 8*PAD_K);
                al[mi][2] = *(const uint32_t*)(sAl + base + 8);
                al[mi][3] = *(const uint32_t*)(sAl + base + 8*PAD_K + 8);
            }
            #pragma unroll
            for (int ni = 0; ni < 4; ni++) {
                int bb = (wn*32 + ni*8 + g) * PAD_K + kk + tq*2;
                uint32_t bh0 = *(const uint32_t*)(sBh + bb);
                uint32_t bh1 = *(const uint32_t*)(sBh + bb + 8);
                uint32_t bl0 = *(const uint32_t*)(sBl + bb);
                uint32_t bl1 = *(const uint32_t*)(sBl + bb + 8);
                #pragma unroll
                for (int mi = 0; mi < 4; mi++) {
                    MMA16816(acc[mi][ni], ah[mi][0], ah[mi][1], ah[mi][2], ah[mi][3], bh0, bh1);
                    MMA16816(acc[mi][ni], al[mi][0], al[mi][1], al[mi][2], al[mi][3], bh0, bh1);
                    MMA16816(acc[mi][ni], ah[mi][0], ah[mi][1], ah[mi][2], ah[mi][3], bl0, bl1);
                }
            }
        }
    }

    #pragma unroll
    for (int mi = 0; mi < 4; mi++) {
        int row = m0 + wm*64 + mi*16 + g;
        #pragma unroll
        for (int ni = 0; ni < 4; ni++) {
            int col = n0 + wn*32 + ni*8 + tq*2;
            float b0 = 0.f, b1 = 0.f;
            if (bias) { b0 = bias[col]; b1 = bias[col+1]; }
            float2 v0 = { acc[mi][ni][0] + b0, acc[mi][ni][1] + b1 };
            float2 v1 = { acc[mi][ni][2] + b0, acc[mi][ni][3] + b1 };
            *(float2*)(C + (size_t)row * GN + col)       = v0;
            *(float2*)(C + (size_t)(row+8) * GN + col)   = v1;
        }
    }
}

// ================= l2-normalize + gate; emits bf16 hi/lo =================
__global__ __launch_bounds__(256) void norm_gate_kernel(const float* __restrict__ raw,
                                                        const float* __restrict__ g,
                                                        __nv_bfloat16* __restrict__ oh,
                                                        __nv_bfloat16* __restrict__ ol,
                                                        float* __restrict__ gate) {
    int task = blockIdx.x * 8 + (threadIdx.x >> 5);
    int lane = threadIdx.x & 31;
    int token = task >> 4;
    int h = task & 15;
    size_t base = (size_t)token * DD + h * HD;
    float2 v = ((const float2*)(raw + base))[lane];
    float sq = v.x*v.x + v.y*v.y;
    #pragma unroll
    for (int o = 16; o > 0; o >>= 1) sq += __shfl_xor_sync(0xffffffffu, sq, o);
    float nrm = sqrtf(sq);
    float inv = 1.0f / fmaxf(nrm, 1e-12f);
    float nx = v.x * inv, ny = v.y * inv;
    uint32_t hp = packbf(nx, ny);
    float lx = nx - __uint_as_float(hp << 16);
    float ly = ny - __uint_as_float(hp & 0xffff0000u);
    uint32_t lp = packbf(lx, ly);
    ((uint32_t*)(oh + base))[lane] = hp;
    ((uint32_t*)(ol + base))[lane] = lp;
    float2 gv = ((const float2*)g)[lane];
    float gp = nx*gv.x + ny*gv.y;
    #pragma unroll
    for (int o = 16; o > 0; o >>= 1) gp += __shfl_xor_sync(0xffffffffu, gp, o);
    if (lane == 0) {
        int b = token / TT, t = token % TT;
        gate[((size_t)(b*HH + h)) * TT + t] = gp;
    }
}

// ================= attention via mma.sync bf16x3 =================
// block: 128 t-rows (8 warps x m16), s-chunks of 64, double-buffered K/V.
// smem per stage: Kh,Kl,Vth,Vtl each 64 rows x 72 bf16 (144B) = 9216 B -> 36864/stage.
#define SC 64
#define ATTN_STG 36864
#define ATTN_SMEM (2*ATTN_STG + 512)

__device__ __forceinline__ void attn_load_stage(uint32_t sb, char* smc, int stage,
        int b, int h, int bh, int s0, int t,
        const __nv_bfloat16* __restrict__ Kh, const __nv_bfloat16* __restrict__ Kl,
        const __nv_bfloat16* __restrict__ Vh, const __nv_bfloat16* __restrict__ Vl,
        const float* __restrict__ gk) {
    uint32_t base = sb + (uint32_t)stage * ATTN_STG;
    int row_lo = t >> 3;     // 0..31
    int c = t & 7;
    #pragma unroll
    for (int i = 0; i < 8; i++) {
        int arr = i >> 1;
        int row = ((i & 1) << 5) + row_lo;   // 0..63
        uint32_t dst = base + (uint32_t)(arr*9216 + row*144 + c*16);
        const __nv_bfloat16* src;
        if (arr == 0)      src = Kh + ((size_t)(b*TT + s0 + row))*DD + h*64 + c*8;
        else if (arr == 1) src = Kl + ((size_t)(b*TT + s0 + row))*DD + h*64 + c*8;
        else if (arr == 2) src = Vh + ((size_t)(b*DD + h*64 + row))*TT + s0 + c*8;
        else               src = Vl + ((size_t)(b*DD + h*64 + row))*TT + s0 + c*8;
        CP_ASYNC16(dst, src);
    }
    if (t < 16) {
        uint32_t dst = sb + 2*ATTN_STG + (uint32_t)stage*256 + t*16;
        CP_ASYNC16(dst, gk + (size_t)bh*TT + s0 + t*4);
    }
}

__global__ __launch_bounds__(256) void attn_mma_kernel(
        const __nv_bfloat16* __restrict__ Qh, const __nv_bfloat16* __restrict__ Ql,
        const __nv_bfloat16* __restrict__ Kh, const __nv_bfloat16* __restrict__ Kl,
        const __nv_bfloat16* __restrict__ Vh, const __nv_bfloat16* __restrict__ Vl,
        const float* __restrict__ gateq, const float* __restrict__ gatek,
        float* __restrict__ outp) {
    extern __shared__ char smc[];
    uint32_t sb = smem_to_u32(smc);
    int t = threadIdx.x;
    int w = t >> 5, lane = t & 31;
    int g = lane >> 2, tq = lane & 3;
    int bh = blockIdx.y;
    int b = bh >> 4, h = bh & 15;
    int t0 = blockIdx.x * 128;
    int trow = t0 + w*16 + g;

    // Q fragments (register-resident for the whole block)
    uint32_t aqh[4][4], aql[4][4];
    {
        size_t r0 = ((size_t)(b*TT + trow))*DD + h*64;
        size_t r8 = r0 + 8*(size_t)DD;
        #pragma unroll
        for (int kq = 0; kq < 4; kq++) {
            int c = kq*16 + tq*2;
            aqh[kq][0] = *(const uint32_t*)(Qh + r0 + c);
            aqh[kq][1] = *(const uint32_t*)(Qh + r8 + c);
            aqh[kq][2] = *(const uint32_t*)(Qh + r0 + c + 8);
            aqh[kq][3] = *(const uint32_t*)(Qh + r8 + c + 8);
            aql[kq][0] = *(const uint32_t*)(Ql + r0 + c);
            aql[kq][1] = *(const uint32_t*)(Ql + r8 + c);
            aql[kq][2] = *(const uint32_t*)(Ql + r0 + c + 8);
            aql[kq][3] = *(const uint32_t*)(Ql + r8 + c + 8);
        }
    }
    float gq0 = gateq[(size_t)bh*TT + trow];
    float gq1 = gateq[(size_t)bh*TT + trow + 8];

    float cacc[8][4];
    #pragma unroll
    for (int di = 0; di < 8; di++)
        #pragma unroll
        for (int r = 0; r < 4; r++) cacc[di][r] = 0.f;

    attn_load_stage(sb, smc, 0, b, h, bh, 0, t, Kh, Kl, Vh, Vl, gatek);
    CP_COMMIT();

    const int NCH = TT / SC;   // 32
    for (int ic = 0; ic < NCH; ic++) {
        CP_WAIT0();
        __syncthreads();
        if (ic + 1 < NCH) {
            attn_load_stage(sb, smc, (ic+1) & 1, b, h, bh, (ic+1)*SC, t, Kh, Kl, Vh, Vl, gatek);
            CP_COMMIT();
        }
        char* stg = smc + (ic & 1) * ATTN_STG;
        const char* skh = stg;
        const char* skl = stg + 9216;
        const char* svh = stg + 18432;
        const char* svl = stg + 27648;
        const float* gks = (const float*)(smc + 2*ATTN_STG + (ic & 1)*256);

        // ---- GEMM1: S[16t x 64s] = Q . K^T (bf16x3) ----
        float sacc[8][4];
        #pragma unroll
        for (int si = 0; si < 8; si++)
            #pragma unroll
            for (int r = 0; r < 4; r++) sacc[si][r] = 0.f;

        #pragma unroll
        for (int si = 0; si < 8; si++) {
            #pragma unroll
            for (int kk = 0; kk < 4; kk++) {
                uint32_t off = (uint32_t)((si*8 + g)*144 + (kk*16 + tq*2)*2);
                uint32_t b0h = *(const uint32_t*)(skh + off);
                uint32_t b1h = *(const uint32_t*)(skh + off + 16);
                uint32_t b0l = *(const uint32_t*)(skl + off);
                uint32_t b1l = *(const uint32_t*)(skl + off + 16);
                MMA16816(sacc[si], aqh[kk][0], aqh[kk][1], aqh[kk][2], aqh[kk][3], b0h, b1h);
                MMA16816(sacc[si], aql[kk][0], aql[kk][1], aql[kk][2], aql[kk][3], b0h, b1h);
                MMA16816(sacc[si], aqh[kk][0], aqh[kk][1], aqh[kk][2], aqh[kk][3], b0l, b1l);
            }
        }

        // ---- modulation in registers, pack to A-fragments (hi + residual lo) ----
        uint32_t mh[4][4], ml[4][4];
        #pragma unroll
        for (int j = 0; j < 4; j++) {
            #pragma unroll
            for (int half = 0; half < 2; half++) {
                int si = 2*j + half;
                float gk0 = gks[si*8 + tq*2];
                float gk1 = gks[si*8 + tq*2 + 1];
                float z00 = (sacc[si][0] - THRESH_C) * SHARP_C;
                float z01 = (sacc[si][1] - THRESH_C) * SHARP_C;
                float z10 = (sacc[si][2] - THRESH_C) * SHARP_C;
                float z11 = (sacc[si][3] - THRESH_C) * SHARP_C;
                float m00 = __fdividef(1.f, 1.f + __expf(-z00)) * gq0 * gk0;
                float m01 = __fdividef(1.f, 1.f + __expf(-z01)) * gq0 * gk1;
                float m10 = __fdividef(1.f, 1.f + __expf(-z10)) * gq1 * gk0;
                float m11 = __fdividef(1.f, 1.f + __expf(-z11)) * gq1 * gk1;
                uint32_t h0 = packbf(m00, m01);
                uint32_t h1 = packbf(m10, m11);
                float l00 = m00 - __uint_as_float(h0 << 16);
                float l01 = m01 - __uint_as_float(h0 & 0xffff0000u);
                float l10 = m10 - __uint_as_float(h1 << 16);
                float l11 = m11 - __uint_as_float(h1 & 0xffff0000u);
                mh[j][half*2 + 0] = h0;   // row g
                mh[j][half*2 + 1] = h1;   // row g+8
                ml[j][half*2 + 0] = packbf(l00, l01);
                ml[j][half*2 + 1] = packbf(l10, l11);
            }
        }

        // ---- GEMM2: C[16t x 64d] += M[16t x 64s] . V[64s x 64d] (bf16x3) ----
        #pragma unroll
        for (int j = 0; j < 4; j++) {
            #pragma unroll
            for (int di = 0; di < 8; di++) {
                uint32_t off = (uint32_t)((di*8 + g)*144 + (j*16 + tq*2)*2);
                uint32_t b0h = *(const uint32_t*)(svh + off);
                uint32_t b1h = *(const uint32_t*)(svh + off + 16);
                uint32_t b0l = *(const uint32_t*)(svl + off);
                uint32_t b1l = *(const uint32_t*)(svl + off + 16);
                MMA16816(cacc[di], mh[j][0], mh[j][1], mh[j][2], mh[j][3], b0h, b1h);
                MMA16816(cacc[di], ml[j][0], ml[j][1], ml[j][2], ml[j][3], b0h, b1h);
                MMA16816(cacc[di], mh[j][0], mh[j][1], mh[j][2], mh[j][3], b0l, b1l);
            }
        }
    }

    // epilogue: write collapse fp32, head-concat layout
    size_t orow = ((size_t)(b*TT + trow))*DD + h*64;
    #pragma unroll
    for (int di = 0; di < 8; di++) {
        int col = di*8 + tq*2;
        float2 v0 = { cacc[di][0], cacc[di][1] };
        float2 v1 = { cacc[di][2], cacc[di][3] };
        *(float2*)(g_coll + orow + col)          = v0;
        *(float2*)(g_coll + orow + 8*(size_t)DD + col) = v1;
    }
    (void)outp;
}

// ================= launch =================
extern "C" void kernel_launch(void* const* d_in, const int* in_sizes, int n_in,
                              void* d_out, int out_size) {
    const float* x    = (const float*)d_in[0];
    const float* Wq   = (const float*)d_in[1];
    const float* Wk   = (const float*)d_in[2];
    const float* Wv   = (const float*)d_in[3];
    const float* gq   = (const float*)d_in[4];
    const float* gk   = (const float*)d_in[5];
    const float* Wo   = (const float*)d_in[6];
    const float* bo   = (const float*)d_in[7];
    const float* ln_w = (const float*)d_in[8];
    const float* ln_b = (const float*)d_in[9];
    float* out = (float*)d_out;

    float *p_xn, *p_qraw, *p_kraw, *p_v, *p_gq, *p_gk, *p_coll;
    cudaGetSymbolAddress((void**)&p_xn,   g_xn);
    cudaGetSymbolAddress((void**)&p_qraw, g_qraw);
    cudaGetSymbolAddress((void**)&p_kraw, g_kraw);
    cudaGetSymbolAddress((void**)&p_v,    g_v);
    cudaGetSymbolAddress((void**)&p_gq,   g_gateq);
    cudaGetSymbolAddress((void**)&p_gk,   g_gatek);
    cudaGetSymbolAddress((void**)&p_coll, g_coll);

    __nv_bfloat16 *p_xh,*p_xl,*p_xnh,*p_xnl,*p_ch,*p_cl;
    __nv_bfloat16 *p_wqh,*p_wql,*p_wkh,*p_wkl,*p_wvh,*p_wvl,*p_woh,*p_wol;
    __nv_bfloat16 *p_qbh,*p_qbl,*p_kbh,*p_kbl,*p_vth,*p_vtl;
    cudaGetSymbolAddress((void**)&p_xh,  g_xh);
    cudaGetSymbolAddress((void**)&p_xl,  g_xl);
    cudaGetSymbolAddress((void**)&p_xnh, g_xnh);
    cudaGetSymbolAddress((void**)&p_xnl, g_xnl);
    cudaGetSymbolAddress((void**)&p_ch,  g_ch);
    cudaGetSymbolAddress((void**)&p_cl,  g_cl);
    cudaGetSymbolAddress((void**)&p_wqh, g_wqh);
    cudaGetSymbolAddress((void**)&p_wql, g_wql);
    cudaGetSymbolAddress((void**)&p_wkh, g_wkh);
    cudaGetSymbolAddress((void**)&p_wkl, g_wkl);
    cudaGetSymbolAddress((void**)&p_wvh, g_wvh);
    cudaGetSymbolAddress((void**)&p_wvl, g_wvl);
    cudaGetSymbolAddress((void**)&p_woh, g_woh);
    cudaGetSymbolAddress((void**)&p_wol, g_wol);
    cudaGetSymbolAddress((void**)&p_qbh, g_qbh);
    cudaGetSymbolAddress((void**)&p_qbl, g_qbl);
    cudaGetSymbolAddress((void**)&p_kbh, g_kbh);
    cudaGetSymbolAddress((void**)&p_kbl, g_kbl);
    cudaGetSymbolAddress((void**)&p_vth, g_vth);
    cudaGetSymbolAddress((void**)&p_vtl, g_vtl);

    cudaFuncSetAttribute(mma_gemm, cudaFuncAttributeMaxDynamicSharedMemorySize, GEMM_SMEM_BYTES);
    cudaFuncSetAttribute(attn_mma_kernel, cudaFuncAttributeMaxDynamicSharedMemorySize, ATTN_SMEM);

    // 1. LayerNorm
    ln_kernel<<<NTOK, 256>>>(x, ln_w, ln_b);

    // 2. bf16 splits
    int split_blocks = (NTOK * DD / 4) / 256;
    split_kernel<<<split_blocks, 256>>>(x,    p_xh,  p_xl);
    split_kernel<<<split_blocks, 256>>>(p_xn, p_xnh, p_xnl);
    dim3 tgrid(DD/32, DD/32);
    tsplit_kernel<<<tgrid, 256>>>(Wq, p_wqh, p_wql);
    tsplit_kernel<<<tgrid, 256>>>(Wk, p_wkh, p_wkl);
    tsplit_kernel<<<tgrid, 256>>>(Wv, p_wvh, p_wvl);
    tsplit_kernel<<<tgrid, 256>>>(Wo, p_woh, p_wol);

    // 3. QKV projections
    dim3 ggrid(GN/128, GM/128);
    mma_gemm<<<ggrid, 256, GEMM_SMEM_BYTES>>>(p_xnh, p_xnl, p_wqh, p_wql, p_qraw, nullptr);
    mma_gemm<<<ggrid, 256, GEMM_SMEM_BYTES>>>(p_xnh, p_xnl, p_wkh, p_wkl, p_kraw, nullptr);
    mma_gemm<<<ggrid, 256, GEMM_SMEM_BYTES>>>(p_xh,  p_xl,  p_wvh, p_wvl, p_v,    nullptr);

    // 4. l2 normalize q,k (-> bf16 hi/lo) + gates; V transpose+split
    norm_gate_kernel<<<(NTOK*HH)/8, 256>>>(p_qraw, gq, p_qbh, p_qbl, p_gq);
    norm_gate_kernel<<<(NTOK*HH)/8, 256>>>(p_kraw, gk, p_kbh, p_kbl, p_gk);
    vtsplit_kernel<<<dim3(TT/32, DD/32, BB), 256>>>(p_v, p_vth, p_vtl);

    // 5. attention via mma.sync
    attn_mma_kernel<<<dim3(TT/128, BB*HH), 256, ATTN_SMEM>>>(
        p_qbh, p_qbl, p_kbh, p_kbl, p_vth, p_vtl, p_gq, p_gk, p_coll);

    // 6. output projection
    split_kernel<<<split_blocks, 256>>>(p_coll, p_ch, p_cl);
    mma_gemm<<<ggrid, 256, GEMM_SMEM_BYTES>>>(p_ch, p_cl, p_woh, p_wol, out, bo);
}

// round 6
// speedup vs baseline: 2.8756x; 1.1376x over previous
#include <cuda_runtime.h>
#include <cuda_bf16.h>
#include <cstdint>
#include <math.h>

#define BB 2
#define TT 2048
#define DD 1024
#define HH 16
#define HD 64
#define NTOK (BB*TT)

#define GM 4096
#define GN 1024
#define GK 1024

#define THRESH_C 0.29514f
#define SHARP_C  15.0f

// ================= low-level helpers =================
#define CP_ASYNC16(dst_u32, src_ptr) \
    asm volatile("cp.async.cg.shared.global [%0], [%1], 16;" \
        :: "r"(dst_u32), "l"(src_ptr) : "memory")
#define CP_COMMIT() asm volatile("cp.async.commit_group;" ::: "memory")
#define CP_WAIT0()  asm volatile("cp.async.wait_group 0;" ::: "memory")

__device__ __forceinline__ uint32_t smem_to_u32(const void* smem_ptr) {
    uint32_t addr;
    asm("{ .reg .u64 tmp; cvta.to.shared.u64 tmp, %1; cvt.u32.u64 %0, tmp; }"
        : "=r"(addr) : "l"(smem_ptr));
    return addr;
}

#define MMA16816(d, a0, a1, a2, a3, b0, b1) \
    asm volatile("mma.sync.aligned.m16n8k16.row.col.f32.bf16.bf16.f32 " \
        "{%0,%1,%2,%3}, {%4,%5,%6,%7}, {%8,%9}, {%0,%1,%2,%3};" \
        : "+f"((d)[0]), "+f"((d)[1]), "+f"((d)[2]), "+f"((d)[3]) \
        : "r"(a0), "r"(a1), "r"(a2), "r"(a3), "r"(b0), "r"(b1))

#define LDMX4(r0, r1, r2, r3, addr) \
    asm volatile("ldmatrix.sync.aligned.m8n8.x4.shared.b16 {%0,%1,%2,%3}, [%4];" \
        : "=r"(r0), "=r"(r1), "=r"(r2), "=r"(r3) : "r"(addr))

// pack two fp32 -> bf16x2 (flo -> low half, fhi -> high half)
__device__ __forceinline__ uint32_t packbf(float flo, float fhi) {
    uint32_t r;
    asm("cvt.rn.bf16x2.f32 %0, %1, %2;" : "=r"(r) : "f"(fhi), "f"(flo));
    return r;
}

// ================= scratch =================
__device__ float g_qraw[NTOK*DD];
__device__ float g_kraw[NTOK*DD];
__device__ float g_v[NTOK*DD];
__device__ float g_gateq[BB*HH*TT];
__device__ float g_gatek[BB*HH*TT];

__device__ __nv_bfloat16 g_xh[NTOK*DD],  g_xl[NTOK*DD];
__device__ __nv_bfloat16 g_xnh[NTOK*DD], g_xnl[NTOK*DD];
__device__ __nv_bfloat16 g_ch[NTOK*DD],  g_cl[NTOK*DD];
__device__ __nv_bfloat16 g_wqh[DD*DD], g_wql[DD*DD];
__device__ __nv_bfloat16 g_wkh[DD*DD], g_wkl[DD*DD];
__device__ __nv_bfloat16 g_wvh[DD*DD], g_wvl[DD*DD];
__device__ __nv_bfloat16 g_woh[DD*DD], g_wol[DD*DD];
__device__ __nv_bfloat16 g_qbh[NTOK*DD], g_qbl[NTOK*DD];
__device__ __nv_bfloat16 g_kbh[NTOK*DD], g_kbl[NTOK*DD];
// Vt premultiplied by gate_k: [b*DD + d][t], bf16 hi/lo
__device__ __nv_bfloat16 g_vth[BB*DD*TT], g_vtl[BB*DD*TT];

// ================= LayerNorm fused with bf16 hi/lo splits =================
// emits: xnh/xnl (normalized) and xh/xl (raw x) — no fp32 intermediates.
__global__ __launch_bounds__(256) void ln_kernel(const float* __restrict__ x,
                                                 const float* __restrict__ w,
                                                 const float* __restrict__ b) {
    int row = blockIdx.x;
    int tid = threadIdx.x;
    const float4* xr = (const float4*)(x + (size_t)row * DD);
    float4 v = xr[tid];
    float s  = v.x + v.y + v.z + v.w;
    float sq = v.x*v.x + v.y*v.y + v.z*v.z + v.w*v.w;
    #pragma unroll
    for (int o = 16; o > 0; o >>= 1) {
        s  += __shfl_xor_sync(0xffffffffu, s,  o);
        sq += __shfl_xor_sync(0xffffffffu, sq, o);
    }
    __shared__ float ss[8], ssq[8];
    int wid = tid >> 5, lid = tid & 31;
    if (lid == 0) { ss[wid] = s; ssq[wid] = sq; }
    __syncthreads();
    float ts = 0.f, tsq = 0.f;
    #pragma unroll
    for (int i = 0; i < 8; i++) { ts += ss[i]; tsq += ssq[i]; }
    float mu  = ts * (1.0f/DD);
    float var = tsq * (1.0f/DD) - mu*mu;
    float inv = rsqrtf(var + 1e-5f);
    float4 wv = ((const float4*)w)[tid];
    float4 bv = ((const float4*)b)[tid];
    float4 o;
    o.x = (v.x - mu) * inv * wv.x + bv.x;
    o.y = (v.y - mu) * inv * wv.y + bv.y;
    o.z = (v.z - mu) * inv * wv.z + bv.z;
    o.w = (v.w - mu) * inv * wv.w + bv.w;

    int i4 = row * (DD/4) + tid;   // uint2 index (4 bf16 = 8 B)
    // split raw x
    {
        uint32_t h0 = packbf(v.x, v.y);
        uint32_t h1 = packbf(v.z, v.w);
        float lx = v.x - __uint_as_float(h0 << 16);
        float ly = v.y - __uint_as_float(h0 & 0xffff0000u);
        float lz = v.z - __uint_as_float(h1 << 16);
        float lw = v.w - __uint_as_float(h1 & 0xffff0000u);
        uint2 hw = { h0, h1 };
        uint2 lw2 = { packbf(lx, ly), packbf(lz, lw) };
        ((uint2*)g_xh)[i4] = hw;
        ((uint2*)g_xl)[i4] = lw2;
    }
    // split normalized x
    {
        uint32_t h0 = packbf(o.x, o.y);
        uint32_t h1 = packbf(o.z, o.w);
        float lx = o.x - __uint_as_float(h0 << 16);
        float ly = o.y - __uint_as_float(h0 & 0xffff0000u);
        float lz = o.z - __uint_as_float(h1 << 16);
        float lw = o.w - __uint_as_float(h1 & 0xffff0000u);
        uint2 hw = { h0, h1 };
        uint2 lw2 = { packbf(lx, ly), packbf(lz, lw) };
        ((uint2*)g_xnh)[i4] = hw;
        ((uint2*)g_xnl)[i4] = lw2;
    }
}

// ================= W[K,N] -> Wt[N,K] transpose + hi/lo split =================
__global__ __launch_bounds__(256) void tsplit_kernel(const float* __restrict__ W,
                                                     __nv_bfloat16* __restrict__ th,
                                                     __nv_bfloat16* __restrict__ tl) {
    __shared__ float tile[32][33];
    int bx = blockIdx.x * 32;
    int by = blockIdx.y * 32;
    int tx = threadIdx.x & 31;
    int ty = threadIdx.x >> 5;
    #pragma unroll
    for (int i = 0; i < 4; i++) {
        int k = by + ty + i*8;
        tile[ty + i*8][tx] = W[(size_t)k * DD + bx + tx];
    }
    __syncthreads();
    #pragma unroll
    for (int i = 0; i < 4; i++) {
        int n = bx + ty + i*8;
        int k = by + tx;
        float v = tile[tx][ty + i*8];
        __nv_bfloat16 h = __float2bfloat16(v);
        __nv_bfloat16 l = __float2bfloat16(v - __bfloat162float(h));
        th[(size_t)n * DD + k] = h;
        tl[(size_t)n * DD + k] = l;
    }
}

// ========== V[b][t][d] -> Vt[b*DD+d][t] transpose, gate_k premultiplied ==========
__global__ __launch_bounds__(256) void vtsplit_kernel(const float* __restrict__ V,
                                                      const float* __restrict__ gatek,
                                                      __nv_bfloat16* __restrict__ th,
                                                      __nv_bfloat16* __restrict__ tl) {
    __shared__ float tile[32][33];
    int b  = blockIdx.z;
    int t0 = blockIdx.x * 32;
    int d0 = blockIdx.y * 32;
    int tx = threadIdx.x & 31;
    int ty = threadIdx.x >> 5;
    #pragma unroll
    for (int i = 0; i < 4; i++) {
        int tt = t0 + ty + i*8;
        tile[ty + i*8][tx] = V[((size_t)(b*TT + tt)) * DD + d0 + tx];
    }
    __syncthreads();
    int h = d0 >> 6;   // head (d-tile never spans heads: 32 | 64)
    float gk = gatek[((size_t)(b*HH + h)) * TT + t0 + tx];
    #pragma unroll
    for (int i = 0; i < 4; i++) {
        int d = d0 + ty + i*8;
        int tt = t0 + tx;
        float v = tile[tx][ty + i*8] * gk;
        __nv_bfloat16 hh = __float2bfloat16(v);
        __nv_bfloat16 ll = __float2bfloat16(v - __bfloat162float(hh));
        th[((size_t)(b*DD + d)) * TT + tt] = hh;
        tl[((size_t)(b*DD + d)) * TT + tt] = ll;
    }
}

// ================= mma.sync bf16x3 GEMM (projections) =================
#define PAD_K 40
#define ARR_ELEMS (128*PAD_K)
#define STAGE_ELEMS (4*ARR_ELEMS)
#define GEMM_SMEM_BYTES (2*STAGE_ELEMS*2)

__device__ __forceinline__ void gemm_load_stage(uint32_t sm_u32, int stage,
        const __nv_bfloat16* __restrict__ Ah, const __nv_bfloat16* __restrict__ Al,
        const __nv_bfloat16* __restrict__ Bh, const __nv_bfloat16* __restrict__ Bl,
        int m0, int n0, int k0, int t) {
    uint32_t sbase = sm_u32 + (uint32_t)stage * (STAGE_ELEMS*2);
    #pragma unroll
    for (int o = 0; o < 2; o++) {
        int linear = t + o*256;
        int r  = linear >> 2;
        int c8 = linear & 3;
        uint32_t soff = (uint32_t)(r*(PAD_K*2) + c8*16);
        size_t goffA = (size_t)(m0 + r) * GK + k0 + c8*8;
        size_t goffB = (size_t)(n0 + r) * GK + k0 + c8*8;
        CP_ASYNC16(sbase +              soff, Ah + goffA);
        CP_ASYNC16(sbase + 1*ARR_ELEMS*2 + soff, Al + goffA);
        CP_ASYNC16(sbase + 2*ARR_ELEMS*2 + soff, Bh + goffB);
        CP_ASYNC16(sbase + 3*ARR_ELEMS*2 + soff, Bl + goffB);
    }
}

__global__ __launch_bounds__(256) void mma_gemm(const __nv_bfloat16* __restrict__ Ah,
                                                const __nv_bfloat16* __restrict__ Al,
                                                const __nv_bfloat16* __restrict__ Bh,
                                                const __nv_bfloat16* __restrict__ Bl,
                                                float* __restrict__ C,
                                                const float* __restrict__ bias) {
    extern __shared__ __nv_bfloat16 smb[];
    uint32_t sm_u32 = smem_to_u32(smb);
    int t = threadIdx.x;
    int wid = t >> 5, lane = t & 31;
    int wm = wid & 1;
    int wn = wid >> 1;
    int g  = lane >> 2;
    int tq = lane & 3;

    int m0 = blockIdx.y * 128, n0 = blockIdx.x * 128;

    float acc[4][4][4];
    #pragma unroll
    for (int mi = 0; mi < 4; mi++)
        #pragma unroll
        for (int ni = 0; ni < 4; ni++)
            #pragma unroll
            for (int r = 0; r < 4; r++) acc[mi][ni][r] = 0.f;

    // per-lane ldmatrix address components
    int a_rsel = lane & 15;            // row within 16-row A tile
    int a_ksel = (lane >> 4) * 8;      // k offset for matrices 2,3
    int b_row  = lane & 7;
    int b_msel = (lane >> 4);          // n-octet select within pair
    int b_ksel = ((lane >> 3) & 1) * 8;

    gemm_load_stage(sm_u32, 0, Ah, Al, Bh, Bl, m0, n0, 0, t);
    CP_COMMIT();

    const int NIT = GK / 32;
    for (int it = 0; it < NIT; it++) {
        CP_WAIT0();
        __syncthreads();
        if (it + 1 < NIT) {
            gemm_load_stage(sm_u32, (it+1) & 1, Ah, Al, Bh, Bl, m0, n0, (it+1)*32, t);
            CP_COMMIT();
        }
        uint32_t S   = sm_u32 + (uint32_t)(it & 1) * (STAGE_ELEMS*2);
        uint32_t uAh = S;
        uint32_t uAl = S + 1*ARR_ELEMS*2;
        uint32_t uBh = S + 2*ARR_ELEMS*2;
        uint32_t uBl = S + 3*ARR_ELEMS*2;

        #pragma unroll
        for (int kk = 0; kk < 32; kk += 16) {
            uint32_t ah[4][4], al[4][4];
            #pragma unroll
            for (int mi = 0; mi < 4; mi++) {
                uint32_t off = (uint32_t)(((wm*64 + mi*16 + a_rsel) * PAD_K + kk + a_ksel) * 2);
                LDMX4(ah[mi][0], ah[mi][1], ah[mi][2], ah[mi][3], uAh + off);
                LDMX4(al[mi][0], al[mi][1], al[mi][2], al[mi][3], uAl + off);
            }
            uint32_t bh[4][2], bl[4][2];
            #pragma unroll
            for (int np = 0; np < 2; np++) {
                uint32_t off = (uint32_t)(((wn*32 + (np*2 + b_msel)*8 + b_row) * PAD_K + kk + b_ksel) * 2);
                uint32_t r0, r1, r2, r3;
                LDMX4(r0, r1, r2, r3, uBh + off);
                bh[np*2][0]=r0; bh[np*2][1]=r1; bh[np*2+1][0]=r2; bh[np*2+1][1]=r3;
                LDMX4(r0, r1, r2, r3, uBl + off);
                bl[np*2][0]=r0; bl[np*2][1]=r1; bl[np*2+1][0]=r2; bl[np*2+1][1]=r3;
            }
            #pragma unroll
            for (int ni = 0; ni < 4; ni++) {
                #pragma unroll
                for (int mi = 0; mi < 4; mi++) {
                    MMA16816(acc[mi][ni], ah[mi][0], ah[mi][1], ah[mi][2], ah[mi][3], bh[ni][0], bh[ni][1]);
                    MMA16816(acc[mi][ni], al[mi][0], al[mi][1], al[mi][2], al[mi][3], bh[ni][0], bh[ni][1]);
                    MMA16816(acc[mi][ni], ah[mi][0], ah[mi][1], ah[mi][2], ah[mi][3], bl[ni][0], bl[ni][1]);
                }
            }
        }
    }

    #pragma unroll
    for (int mi = 0; mi < 4; mi++) {
        int row = m0 + wm*64 + mi*16 + g;
        #pragma unroll
        for (int ni = 0; ni < 4; ni++) {
            int col = n0 + wn*32 + ni*8 + tq*2;
            float b0 = 0.f, b1 = 0.f;
            if (bias) { b0 = bias[col]; b1 = bias[col+1]; }
            float2 v0 = { acc[mi][ni][0] + b0, acc[mi][ni][1] + b1 };
            float2 v1 = { acc[mi][ni][2] + b0, acc[mi][ni][3] + b1 };
            *(float2*)(C + (size_t)row * GN + col)       = v0;
            *(float2*)(C + (size_t)(row+8) * GN + col)   = v1;
        }
    }
}

// ================= l2-normalize + gate; emits bf16 hi/lo =================
__global__ __launch_bounds__(256) void norm_gate_kernel(const float* __restrict__ raw,
                                                        const float* __restrict__ g,
                                                        __nv_bfloat16* __restrict__ oh,
                                                        __nv_bfloat16* __restrict__ ol,
                                                        float* __restrict__ gate) {
    int task = blockIdx.x * 8 + (threadIdx.x >> 5);
    int lane = threadIdx.x & 31;
    int token = task >> 4;
    int h = task & 15;
    size_t base = (size_t)token * DD + h * HD;
    float2 v = ((const float2*)(raw + base))[lane];
    float sq = v.x*v.x + v.y*v.y;
    #pragma unroll
    for (int o = 16; o > 0; o >>= 1) sq += __shfl_xor_sync(0xffffffffu, sq, o);
    float nrm = sqrtf(sq);
    float inv = 1.0f / fmaxf(nrm, 1e-12f);
    float nx = v.x * inv, ny = v.y * inv;
    uint32_t hp = packbf(nx, ny);
    float lx = nx - __uint_as_float(hp << 16);
    float ly = ny - __uint_as_float(hp & 0xffff0000u);
    uint32_t lp = packbf(lx, ly);
    ((uint32_t*)(oh + base))[lane] = hp;
    ((uint32_t*)(ol + base))[lane] = lp;
    float2 gv = ((const float2*)g)[lane];
    float gp = nx*gv.x + ny*gv.y;
    #pragma unroll
    for (int o = 16; o > 0; o >>= 1) gp += __shfl_xor_sync(0xffffffffu, gp, o);
    if (lane == 0) {
        int b = token / TT, t = token % TT;
        gate[((size_t)(b*HH + h)) * TT + t] = gp;
    }
}

// ================= attention via mma.sync bf16x3 + ldmatrix =================
#define SC 64
#define ATTN_STG 36864
#define ATTN_SMEM (2*ATTN_STG)

__device__ __forceinline__ void attn_load_stage(uint32_t sb, int stage,
        int b, int h, int s0, int t,
        const __nv_bfloat16* __restrict__ Kh, const __nv_bfloat16* __restrict__ Kl,
        const __nv_bfloat16* __restrict__ Vh, const __nv_bfloat16* __restrict__ Vl) {
    uint32_t base = sb + (uint32_t)stage * ATTN_STG;
    int row_lo = t >> 3;     // 0..31
    int c = t & 7;
    #pragma unroll
    for (int i = 0; i < 8; i++) {
        int arr = i >> 1;
        int row = ((i & 1) << 5) + row_lo;   // 0..63
        uint32_t dst = base + (uint32_t)(arr*9216 + row*144 + c*16);
        const __nv_bfloat16* src;
        if (arr == 0)      src = Kh + ((size_t)(b*TT + s0 + row))*DD + h*64 + c*8;
        else if (arr == 1) src = Kl + ((size_t)(b*TT + s0 + row))*DD + h*64 + c*8;
        else if (arr == 2) src = Vh + ((size_t)(b*DD + h*64 + row))*TT + s0 + c*8;
        else               src = Vl + ((size_t)(b*DD + h*64 + row))*TT + s0 + c*8;
        CP_ASYNC16(dst, src);
    }
}

__global__ __launch_bounds__(256) void attn_mma_kernel(
        const __nv_bfloat16* __restrict__ Qh, const __nv_bfloat16* __restrict__ Ql,
        const __nv_bfloat16* __restrict__ Kh, const __nv_bfloat16* __restrict__ Kl,
        const __nv_bfloat16* __restrict__ Vh, const __nv_bfloat16* __restrict__ Vl,
        const float* __restrict__ gateq) {
    extern __shared__ char smc[];
    uint32_t sb = smem_to_u32(smc);
    int t = threadIdx.x;
    int w = t >> 5, lane = t & 31;
    int g = lane >> 2, tq = lane & 3;
    int bh = blockIdx.y;
    int b = bh >> 4, h = bh & 15;
    int t0 = blockIdx.x * 128;
    int trow = t0 + w*16 + g;

    // ldmatrix B-operand lane address components (n-row + k-offset select)
    int b_row  = lane & 7;
    int b_msel = (lane >> 4);            // n-octet within pair
    int b_ksel = ((lane >> 3) & 1) * 8;  // k offset

    // Q fragments (register-resident)
    uint32_t aqh[4][4], aql[4][4];
    {
        size_t r0 = ((size_t)(b*TT + trow))*DD + h*64;
        size_t r8 = r0 + 8*(size_t)DD;
        #pragma unroll
        for (int kq = 0; kq < 4; kq++) {
            int c = kq*16 + tq*2;
            aqh[kq][0] = *(const uint32_t*)(Qh + r0 + c);
            aqh[kq][1] = *(const uint32_t*)(Qh + r8 + c);
            aqh[kq][2] = *(const uint32_t*)(Qh + r0 + c + 8);
            aqh[kq][3] = *(const uint32_t*)(Qh + r8 + c + 8);
            aql[kq][0] = *(const uint32_t*)(Ql + r0 + c);
            aql[kq][1] = *(const uint32_t*)(Ql + r8 + c);
            aql[kq][2] = *(const uint32_t*)(Ql + r0 + c + 8);
            aql[kq][3] = *(const uint32_t*)(Ql + r8 + c + 8);
        }
    }
    float gq0 = gateq[(size_t)bh*TT + trow];
    float gq1 = gateq[(size_t)bh*TT + trow + 8];

    float cacc[8][4];
    #pragma unroll
    for (int di = 0; di < 8; di++)
        #pragma unroll
        for (int r = 0; r < 4; r++) cacc[di][r] = 0.f;

    attn_load_stage(sb, 0, b, h, 0, t, Kh, Kl, Vh, Vl);
    CP_COMMIT();

    const int NCH = TT / SC;   // 32
    for (int ic = 0; ic < NCH; ic++) {
        CP_WAIT0();
        __syncthreads();
        if (ic + 1 < NCH) {
            attn_load_stage(sb, (ic+1) & 1, b, h, (ic+1)*SC, t, Kh, Kl, Vh, Vl);
            CP_COMMIT();
        }
        uint32_t stg = sb + (uint32_t)(ic & 1) * ATTN_STG;
        uint32_t uKh = stg;
        uint32_t uKl = stg +  9216;
        uint32_t uVh = stg + 18432;
        uint32_t uVl = stg + 27648;

        // ---- GEMM1: S[16t x 64s] = Q . K^T ----
        float sacc[8][4];
        #pragma unroll
        for (int si = 0; si < 8; si++)
            #pragma unroll
            for (int r = 0; r < 4; r++) sacc[si][r] = 0.f;

        #pragma unroll
        for (int sp = 0; sp < 4; sp++) {       // si pair {2sp, 2sp+1}
            #pragma unroll
            for (int kk = 0; kk < 4; kk++) {
                uint32_t off = (uint32_t)(((sp*2 + b_msel)*8 + b_row)*144 + (kk*16 + b_ksel)*2);
                uint32_t h0, h1, h2, h3, l0, l1, l2, l3;
                LDMX4(h0, h1, h2, h3, uKh + off);
                LDMX4(l0, l1, l2, l3, uKl + off);
                MMA16816(sacc[2*sp],   aqh[kk][0], aqh[kk][1], aqh[kk][2], aqh[kk][3], h0, h1);
                MMA16816(sacc[2*sp],   aql[kk][0], aql[kk][1], aql[kk][2], aql[kk][3], h0, h1);
                MMA16816(sacc[2*sp],   aqh[kk][0], aqh[kk][1], aqh[kk][2], aqh[kk][3], l0, l1);
                MMA16816(sacc[2*sp+1], aqh[kk][0], aqh[kk][1], aqh[kk][2], aqh[kk][3], h2, h3);
                MMA16816(sacc[2*sp+1], aql[kk][0], aql[kk][1], aql[kk][2], aql[kk][3], h2, h3);
                MMA16816(sacc[2*sp+1], aqh[kk][0], aqh[kk][1], aqh[kk][2], aqh[kk][3], l2, l3);
            }
        }

        // ---- modulation: sigmoid only (gates folded elsewhere) ----
        uint32_t mh[4][4], ml[4][4];
        #pragma unroll
        for (int j = 0; j < 4; j++) {
            #pragma unroll
            for (int half = 0; half < 2; half++) {
                int si = 2*j + half;
                float z00 = (sacc[si][0] - THRESH_C) * SHARP_C;
                float z01 = (sacc[si][1] - THRESH_C) * SHARP_C;
                float z10 = (sacc[si][2] - THRESH_C) * SHARP_C;
                float z11 = (sacc[si][3] - THRESH_C) * SHARP_C;
                float m00 = __fdividef(1.f, 1.f + __expf(-z00));
                float m01 = __fdividef(1.f, 1.f + __expf(-z01));
                float m10 = __fdividef(1.f, 1.f + __expf(-z10));
                float m11 = __fdividef(1.f, 1.f + __expf(-z11));
                uint32_t h0 = packbf(m00, m01);
                uint32_t h1 = packbf(m10, m11);
                float l00 = m00 - __uint_as_float(h0 << 16);
                float l01 = m01 - __uint_as_float(h0 & 0xffff0000u);
                float l10 = m10 - __uint_as_float(h1 << 16);
                float l11 = m11 - __uint_as_float(h1 & 0xffff0000u);
                mh[j][half*2 + 0] = h0;
                mh[j][half*2 + 1] = h1;
                ml[j][half*2 + 0] = packbf(l00, l01);
                ml[j][half*2 + 1] = packbf(l10, l11);
            }
        }

        // ---- GEMM2: C[16t x 64d] += M . (gk*V) ----
        #pragma unroll
        for (int dp = 0; dp < 4; dp++) {       // di pair {2dp, 2dp+1}
            #pragma unroll
            for (int j = 0; j < 4; j++) {
                uint32_t off = (uint32_t)(((dp*2 + b_msel)*8 + b_row)*144 + (j*16 + b_ksel)*2);
                uint32_t h0, h1, h2, h3, l0, l1, l2, l3;
                LDMX4(h0, h1, h2, h3, uVh + off);
                LDMX4(l0, l1, l2, l3, uVl + off);
                MMA16816(cacc[2*dp],   mh[j][0], mh[j][1], mh[j][2], mh[j][3], h0, h1);
                MMA16816(cacc[2*dp],   ml[j][0], ml[j][1], ml[j][2], ml[j][3], h0, h1);
                MMA16816(cacc[2*dp],   mh[j][0], mh[j][1], mh[j][2], mh[j][3], l0, l1);
                MMA16816(cacc[2*dp+1], mh[j][0], mh[j][1], mh[j][2], mh[j][3], h2, h3);
                MMA16816(cacc[2*dp+1], ml[j][0], ml[j][1], ml[j][2], ml[j][3], h2, h3);
                MMA16816(cacc[2*dp+1], mh[j][0], mh[j][1], mh[j][2], mh[j][3], l2, l3);
            }
        }
    }

    // epilogue: apply gq, split to bf16 hi/lo collapse (head-concat layout)
    size_t obase = ((size_t)(b*TT + trow))*DD + h*64;
    #pragma unroll
    for (int di = 0; di < 8; di++) {
        int col = di*8 + tq*2;
        float c00 = cacc[di][0]*gq0, c01 = cacc[di][1]*gq0;
        float c10 = cacc[di][2]*gq1, c11 = cacc[di][3]*gq1;
        uint32_t h0 = packbf(c00, c01);
        uint32_t h1 = packbf(c10, c11);
        float l00 = c00 - __uint_as_float(h0 << 16);
        float l01 = c01 - __uint_as_float(h0 & 0xffff0000u);
        float l10 = c10 - __uint_as_float(h1 << 16);
        float l11 = c11 - __uint_as_float(h1 & 0xffff0000u);
        *(uint32_t*)(g_ch + obase + col) = h0;
        *(uint32_t*)(g_cl + obase + col) = packbf(l00, l01);
        *(uint32_t*)(g_ch + obase + 8*(size_t)DD + col) = h1;
        *(uint32_t*)(g_cl + obase + 8*(size_t)DD + col) = packbf(l10, l11);
    }
}

// ================= launch =================
extern "C" void kernel_launch(void* const* d_in, const int* in_sizes, int n_in,
                              void* d_out, int out_size) {
    const float* x    = (const float*)d_in[0];
    const float* Wq   = (const float*)d_in[1];
    const float* Wk   = (const float*)d_in[2];
    const float* Wv   = (const float*)d_in[3];
    const float* gq   = (const float*)d_in[4];
    const float* gk   = (const float*)d_in[5];
    const float* Wo   = (const float*)d_in[6];
    const float* bo   = (const float*)d_in[7];
    const float* ln_w = (const float*)d_in[8];
    const float* ln_b = (const float*)d_in[9];
    float* out = (float*)d_out;

    float *p_qraw, *p_kraw, *p_v, *p_gq, *p_gk;
    cudaGetSymbolAddress((void**)&p_qraw, g_qraw);
    cudaGetSymbolAddress((void**)&p_kraw, g_kraw);
    cudaGetSymbolAddress((void**)&p_v,    g_v);
    cudaGetSymbolAddress((void**)&p_gq,   g_gateq);
    cudaGetSymbolAddress((void**)&p_gk,   g_gatek);

    __nv_bfloat16 *p_xh,*p_xl,*p_xnh,*p_xnl,*p_ch,*p_cl;
    __nv_bfloat16 *p_wqh,*p_wql,*p_wkh,*p_wkl,*p_wvh,*p_wvl,*p_woh,*p_wol;
    __nv_bfloat16 *p_qbh,*p_qbl,*p_kbh,*p_kbl,*p_vth,*p_vtl;
    cudaGetSymbolAddress((void**)&p_xh,  g_xh);
    cudaGetSymbolAddress((void**)&p_xl,  g_xl);
    cudaGetSymbolAddress((void**)&p_xnh, g_xnh);
    cudaGetSymbolAddress((void**)&p_xnl, g_xnl);
    cudaGetSymbolAddress((void**)&p_ch,  g_ch);
    cudaGetSymbolAddress((void**)&p_cl,  g_cl);
    cudaGetSymbolAddress((void**)&p_wqh, g_wqh);
    cudaGetSymbolAddress((void**)&p_wql, g_wql);
    cudaGetSymbolAddress((void**)&p_wkh, g_wkh);
    cudaGetSymbolAddress((void**)&p_wkl, g_wkl);
    cudaGetSymbolAddress((void**)&p_wvh, g_wvh);
    cudaGetSymbolAddress((void**)&p_wvl, g_wvl);
    cudaGetSymbolAddress((void**)&p_woh, g_woh);
    cudaGetSymbolAddress((void**)&p_wol, g_wol);
    cudaGetSymbolAddress((void**)&p_qbh, g_qbh);
    cudaGetSymbolAddress((void**)&p_qbl, g_qbl);
    cudaGetSymbolAddress((void**)&p_kbh, g_kbh);
    cudaGetSymbolAddress((void**)&p_kbl, g_kbl);
    cudaGetSymbolAddress((void**)&p_vth, g_vth);
    cudaGetSymbolAddress((void**)&p_vtl, g_vtl);

    cudaFuncSetAttribute(mma_gemm, cudaFuncAttributeMaxDynamicSharedMemorySize, GEMM_SMEM_BYTES);
    cudaFuncSetAttribute(attn_mma_kernel, cudaFuncAttributeMaxDynamicSharedMemorySize, ATTN_SMEM);

    // 1. LayerNorm + all x/xn bf16 splits (fused)
    ln_kernel<<<NTOK, 256>>>(x, ln_w, ln_b);

    // 2. weight transpose+split
    dim3 tgrid(DD/32, DD/32);
    tsplit_kernel<<<tgrid, 256>>>(Wq, p_wqh, p_wql);
    tsplit_kernel<<<tgrid, 256>>>(Wk, p_wkh, p_wkl);
    tsplit_kernel<<<tgrid, 256>>>(Wv, p_wvh, p_wvl);
    tsplit_kernel<<<tgrid, 256>>>(Wo, p_woh, p_wol);

    // 3. QKV projections
    dim3 ggrid(GN/128, GM/128);
    mma_gemm<<<ggrid, 256, GEMM_SMEM_BYTES>>>(p_xnh, p_xnl, p_wqh, p_wql, p_qraw, nullptr);
    mma_gemm<<<ggrid, 256, GEMM_SMEM_BYTES>>>(p_xnh, p_xnl, p_wkh, p_wkl, p_kraw, nullptr);
    mma_gemm<<<ggrid, 256, GEMM_SMEM_BYTES>>>(p_xh,  p_xl,  p_wvh, p_wvl, p_v,    nullptr);

    // 4. l2 normalize q,k + gates; V transpose+split with gate_k folded in
    norm_gate_kernel<<<(NTOK*HH)/8, 256>>>(p_qraw, gq, p_qbh, p_qbl, p_gq);
    norm_gate_kernel<<<(NTOK*HH)/8, 256>>>(p_kraw, gk, p_kbh, p_kbl, p_gk);
    vtsplit_kernel<<<dim3(TT/32, DD/32, BB), 256>>>(p_v, p_gk, p_vth, p_vtl);

    // 5. attention (emits collapse bf16 hi/lo with gq applied)
    attn_mma_kernel<<<dim3(TT/128, BB*HH), 256, ATTN_SMEM>>>(
        p_qbh, p_qbl, p_kbh, p_kbl, p_vth, p_vtl, p_gq);

    // 6. output projection
    mma_gemm<<<ggrid, 256, GEMM_SMEM_BYTES>>>(p_ch, p_cl, p_woh, p_wol, out, bo);
}

// round 7
// speedup vs baseline: 2.8841x; 1.0030x over previous
#include <cuda_runtime.h>
#include <cuda_bf16.h>
#include <cstdint>
#include <math.h>

#define BB 2
#define TT 2048
#define DD 1024
#define HH 16
#define HD 64
#define NTOK (BB*TT)

#define GM 4096
#define GN 1024
#define GK 1024

#define THRESH_C 0.29514f
#define SHARP_C  15.0f

// ================= low-level helpers =================
#define CP_ASYNC16(dst_u32, src_ptr) \
    asm volatile("cp.async.cg.shared.global [%0], [%1], 16;" \
        :: "r"(dst_u32), "l"(src_ptr) : "memory")
#define CP_COMMIT() asm volatile("cp.async.commit_group;" ::: "memory")
#define CP_WAIT0()  asm volatile("cp.async.wait_group 0;" ::: "memory")

__device__ __forceinline__ uint32_t smem_to_u32(const void* smem_ptr) {
    uint32_t addr;
    asm("{ .reg .u64 tmp; cvta.to.shared.u64 tmp, %1; cvt.u32.u64 %0, tmp; }"
        : "=r"(addr) : "l"(smem_ptr));
    return addr;
}

#define MMA16816(d, a0, a1, a2, a3, b0, b1) \
    asm volatile("mma.sync.aligned.m16n8k16.row.col.f32.bf16.bf16.f32 " \
        "{%0,%1,%2,%3}, {%4,%5,%6,%7}, {%8,%9}, {%0,%1,%2,%3};" \
        : "+f"((d)[0]), "+f"((d)[1]), "+f"((d)[2]), "+f"((d)[3]) \
        : "r"(a0), "r"(a1), "r"(a2), "r"(a3), "r"(b0), "r"(b1))

#define LDMX4(r0, r1, r2, r3, addr) \
    asm volatile("ldmatrix.sync.aligned.m8n8.x4.shared.b16 {%0,%1,%2,%3}, [%4];" \
        : "=r"(r0), "=r"(r1), "=r"(r2), "=r"(r3) : "r"(addr))

// pack two fp32 -> bf16x2 (flo -> low half, fhi -> high half)
__device__ __forceinline__ uint32_t packbf(float flo, float fhi) {
    uint32_t r;
    asm("cvt.rn.bf16x2.f32 %0, %1, %2;" : "=r"(r) : "f"(fhi), "f"(flo));
    return r;
}

// ================= scratch =================
__device__ float g_qraw[NTOK*DD];
__device__ float g_kraw[NTOK*DD];
__device__ float g_v[NTOK*DD];
__device__ float g_gateq[BB*HH*TT];
__device__ float g_gatek[BB*HH*TT];

__device__ __nv_bfloat16 g_xh[NTOK*DD],  g_xl[NTOK*DD];
__device__ __nv_bfloat16 g_xnh[NTOK*DD], g_xnl[NTOK*DD];
__device__ __nv_bfloat16 g_ch[NTOK*DD],  g_cl[NTOK*DD];
__device__ __nv_bfloat16 g_wqh[DD*DD], g_wql[DD*DD];
__device__ __nv_bfloat16 g_wkh[DD*DD], g_wkl[DD*DD];
__device__ __nv_bfloat16 g_wvh[DD*DD], g_wvl[DD*DD];
__device__ __nv_bfloat16 g_woh[DD*DD], g_wol[DD*DD];
__device__ __nv_bfloat16 g_qbh[NTOK*DD], g_qbl[NTOK*DD];
__device__ __nv_bfloat16 g_kbh[NTOK*DD], g_kbl[NTOK*DD];
__device__ __nv_bfloat16 g_vth[BB*DD*TT], g_vtl[BB*DD*TT];

// ================= LayerNorm fused with bf16 hi/lo splits =================
__global__ __launch_bounds__(256) void ln_kernel(const float* __restrict__ x,
                                                 const float* __restrict__ w,
                                                 const float* __restrict__ b) {
    int row = blockIdx.x;
    int tid = threadIdx.x;
    const float4* xr = (const float4*)(x + (size_t)row * DD);
    float4 v = xr[tid];
    float s  = v.x + v.y + v.z + v.w;
    float sq = v.x*v.x + v.y*v.y + v.z*v.z + v.w*v.w;
    #pragma unroll
    for (int o = 16; o > 0; o >>= 1) {
        s  += __shfl_xor_sync(0xffffffffu, s,  o);
        sq += __shfl_xor_sync(0xffffffffu, sq, o);
    }
    __shared__ float ss[8], ssq[8];
    int wid = tid >> 5, lid = tid & 31;
    if (lid == 0) { ss[wid] = s; ssq[wid] = sq; }
    __syncthreads();
    float ts = 0.f, tsq = 0.f;
    #pragma unroll
    for (int i = 0; i < 8; i++) { ts += ss[i]; tsq += ssq[i]; }
    float mu  = ts * (1.0f/DD);
    float var = tsq * (1.0f/DD) - mu*mu;
    float inv = rsqrtf(var + 1e-5f);
    float4 wv = ((const float4*)w)[tid];
    float4 bv = ((const float4*)b)[tid];
    float4 o;
    o.x = (v.x - mu) * inv * wv.x + bv.x;
    o.y = (v.y - mu) * inv * wv.y + bv.y;
    o.z = (v.z - mu) * inv * wv.z + bv.z;
    o.w = (v.w - mu) * inv * wv.w + bv.w;

    int i4 = row * (DD/4) + tid;
    {
        uint32_t h0 = packbf(v.x, v.y);
        uint32_t h1 = packbf(v.z, v.w);
        float lx = v.x - __uint_as_float(h0 << 16);
        float ly = v.y - __uint_as_float(h0 & 0xffff0000u);
        float lz = v.z - __uint_as_float(h1 << 16);
        float lw = v.w - __uint_as_float(h1 & 0xffff0000u);
        uint2 hw = { h0, h1 };
        uint2 lw2 = { packbf(lx, ly), packbf(lz, lw) };
        ((uint2*)g_xh)[i4] = hw;
        ((uint2*)g_xl)[i4] = lw2;
    }
    {
        uint32_t h0 = packbf(o.x, o.y);
        uint32_t h1 = packbf(o.z, o.w);
        float lx = o.x - __uint_as_float(h0 << 16);
        float ly = o.y - __uint_as_float(h0 & 0xffff0000u);
        float lz = o.z - __uint_as_float(h1 << 16);
        float lw = o.w - __uint_as_float(h1 & 0xffff0000u);
        uint2 hw = { h0, h1 };
        uint2 lw2 = { packbf(lx, ly), packbf(lz, lw) };
        ((uint2*)g_xnh)[i4] = hw;
        ((uint2*)g_xnl)[i4] = lw2;
    }
}

// ===== all 4 weights: W[K,N] -> Wt[N,K] transpose + hi/lo split (z-indexed) =====
__global__ __launch_bounds__(256) void tsplit4_kernel(const float* __restrict__ W0,
                                                      const float* __restrict__ W1,
                                                      const float* __restrict__ W2,
                                                      const float* __restrict__ W3) {
    __shared__ float tile[32][33];
    const float* W;
    __nv_bfloat16 *th, *tl;
    switch (blockIdx.z) {
        case 0: W = W0; th = g_wqh; tl = g_wql; break;
        case 1: W = W1; th = g_wkh; tl = g_wkl; break;
        case 2: W = W2; th = g_wvh; tl = g_wvl; break;
        default: W = W3; th = g_woh; tl = g_wol; break;
    }
    int bx = blockIdx.x * 32;
    int by = blockIdx.y * 32;
    int tx = threadIdx.x & 31;
    int ty = threadIdx.x >> 5;
    #pragma unroll
    for (int i = 0; i < 4; i++) {
        int k = by + ty + i*8;
        tile[ty + i*8][tx] = W[(size_t)k * DD + bx + tx];
    }
    __syncthreads();
    #pragma unroll
    for (int i = 0; i < 4; i++) {
        int n = bx + ty + i*8;
        int k = by + tx;
        float v = tile[tx][ty + i*8];
        __nv_bfloat16 h = __float2bfloat16(v);
        __nv_bfloat16 l = __float2bfloat16(v - __bfloat162float(h));
        th[(size_t)n * DD + k] = h;
        tl[(size_t)n * DD + k] = l;
    }
}

// ========== V[b][t][d] -> Vt[b*DD+d][t] transpose, gate_k premultiplied ==========
__global__ __launch_bounds__(256) void vtsplit_kernel(const float* __restrict__ V,
                                                      const float* __restrict__ gatek,
                                                      __nv_bfloat16* __restrict__ th,
                                                      __nv_bfloat16* __restrict__ tl) {
    __shared__ float tile[32][33];
    int b  = blockIdx.z;
    int t0 = blockIdx.x * 32;
    int d0 = blockIdx.y * 32;
    int tx = threadIdx.x & 31;
    int ty = threadIdx.x >> 5;
    #pragma unroll
    for (int i = 0; i < 4; i++) {
        int tt = t0 + ty + i*8;
        tile[ty + i*8][tx] = V[((size_t)(b*TT + tt)) * DD + d0 + tx];
    }
    __syncthreads();
    int h = d0 >> 6;
    float gk = gatek[((size_t)(b*HH + h)) * TT + t0 + tx];
    #pragma unroll
    for (int i = 0; i < 4; i++) {
        int d = d0 + ty + i*8;
        int tt = t0 + tx;
        float v = tile[tx][ty + i*8] * gk;
        __nv_bfloat16 hh = __float2bfloat16(v);
        __nv_bfloat16 ll = __float2bfloat16(v - __bfloat162float(hh));
        th[((size_t)(b*DD + d)) * TT + tt] = hh;
        tl[((size_t)(b*DD + d)) * TT + tt] = ll;
    }
}

// ================= mma.sync bf16x3 GEMM (projections) =================
#define PAD_K 40
#define ARR_ELEMS (128*PAD_K)
#define STAGE_ELEMS (4*ARR_ELEMS)
#define GEMM_SMEM_BYTES (2*STAGE_ELEMS*2)

__device__ __forceinline__ void gemm_load_stage(uint32_t sm_u32, int stage,
        const __nv_bfloat16* __restrict__ Ah, const __nv_bfloat16* __restrict__ Al,
        const __nv_bfloat16* __restrict__ Bh, const __nv_bfloat16* __restrict__ Bl,
        int m0, int n0, int k0, int t) {
    uint32_t sbase = sm_u32 + (uint32_t)stage * (STAGE_ELEMS*2);
    #pragma unroll
    for (int o = 0; o < 2; o++) {
        int linear = t + o*256;
        int r  = linear >> 2;
        int c8 = linear & 3;
        uint32_t soff = (uint32_t)(r*(PAD_K*2) + c8*16);
        size_t goffA = (size_t)(m0 + r) * GK + k0 + c8*8;
        size_t goffB = (size_t)(n0 + r) * GK + k0 + c8*8;
        CP_ASYNC16(sbase +              soff, Ah + goffA);
        CP_ASYNC16(sbase + 1*ARR_ELEMS*2 + soff, Al + goffA);
        CP_ASYNC16(sbase + 2*ARR_ELEMS*2 + soff, Bh + goffB);
        CP_ASYNC16(sbase + 3*ARR_ELEMS*2 + soff, Bl + goffB);
    }
}

__global__ __launch_bounds__(256) void mma_gemm(const __nv_bfloat16* __restrict__ Ah,
                                                const __nv_bfloat16* __restrict__ Al,
                                                const __nv_bfloat16* __restrict__ Bh,
                                                const __nv_bfloat16* __restrict__ Bl,
                                                float* __restrict__ C,
                                                const float* __restrict__ bias) {
    extern __shared__ __nv_bfloat16 smb[];
    uint32_t sm_u32 = smem_to_u32(smb);
    int t = threadIdx.x;
    int wid = t >> 5, lane = t & 31;
    int wm = wid & 1;
    int wn = wid >> 1;
    int g  = lane >> 2;
    int tq = lane & 3;

    int m0 = blockIdx.y * 128, n0 = blockIdx.x * 128;

    float acc[4][4][4];
    #pragma unroll
    for (int mi = 0; mi < 4; mi++)
        #pragma unroll
        for (int ni = 0; ni < 4; ni++)
            #pragma unroll
            for (int r = 0; r < 4; r++) acc[mi][ni][r] = 0.f;

    int a_rsel = lane & 15;
    int a_ksel = (lane >> 4) * 8;
    int b_row  = lane & 7;
    int b_msel = (lane >> 4);
    int b_ksel = ((lane >> 3) & 1) * 8;

    gemm_load_stage(sm_u32, 0, Ah, Al, Bh, Bl, m0, n0, 0, t);
    CP_COMMIT();

    const int NIT = GK / 32;
    for (int it = 0; it < NIT; it++) {
        CP_WAIT0();
        __syncthreads();
        if (it + 1 < NIT) {
            gemm_load_stage(sm_u32, (it+1) & 1, Ah, Al, Bh, Bl, m0, n0, (it+1)*32, t);
            CP_COMMIT();
        }
        uint32_t S   = sm_u32 + (uint32_t)(it & 1) * (STAGE_ELEMS*2);
        uint32_t uAh = S;
        uint32_t uAl = S + 1*ARR_ELEMS*2;
        uint32_t uBh = S + 2*ARR_ELEMS*2;
        uint32_t uBl = S + 3*ARR_ELEMS*2;

        #pragma unroll
        for (int kk = 0; kk < 32; kk += 16) {
            uint32_t ah[4][4], al[4][4];
            #pragma unroll
            for (int mi = 0; mi < 4; mi++) {
                uint32_t off = (uint32_t)(((wm*64 + mi*16 + a_rsel) * PAD_K + kk + a_ksel) * 2);
                LDMX4(ah[mi][0], ah[mi][1], ah[mi][2], ah[mi][3], uAh + off);
                LDMX4(al[mi][0], al[mi][1], al[mi][2], al[mi][3], uAl + off);
            }
            uint32_t bh[4][2], bl[4][2];
            #pragma unroll
            for (int np = 0; np < 2; np++) {
                uint32_t off = (uint32_t)(((wn*32 + (np*2 + b_msel)*8 + b_row) * PAD_K + kk + b_ksel) * 2);
                uint32_t r0, r1, r2, r3;
                LDMX4(r0, r1, r2, r3, uBh + off);
                bh[np*2][0]=r0; bh[np*2][1]=r1; bh[np*2+1][0]=r2; bh[np*2+1][1]=r3;
                LDMX4(r0, r1, r2, r3, uBl + off);
                bl[np*2][0]=r0; bl[np*2][1]=r1; bl[np*2+1][0]=r2; bl[np*2+1][1]=r3;
            }
            // term-outer ordering: 16 independent accs between same-acc updates
            #pragma unroll
            for (int ni = 0; ni < 4; ni++)
                #pragma unroll
                for (int mi = 0; mi < 4; mi++)
                    MMA16816(acc[mi][ni], ah[mi][0], ah[mi][1], ah[mi][2], ah[mi][3], bh[ni][0], bh[ni][1]);
            #pragma unroll
            for (int ni = 0; ni < 4; ni++)
                #pragma unroll
                for (int mi = 0; mi < 4; mi++)
                    MMA16816(acc[mi][ni], al[mi][0], al[mi][1], al[mi][2], al[mi][3], bh[ni][0], bh[ni][1]);
            #pragma unroll
            for (int ni = 0; ni < 4; ni++)
                #pragma unroll
                for (int mi = 0; mi < 4; mi++)
                    MMA16816(acc[mi][ni], ah[mi][0], ah[mi][1], ah[mi][2], ah[mi][3], bl[ni][0], bl[ni][1]);
        }
    }

    #pragma unroll
    for (int mi = 0; mi < 4; mi++) {
        int row = m0 + wm*64 + mi*16 + g;
        #pragma unroll
        for (int ni = 0; ni < 4; ni++) {
            int col = n0 + wn*32 + ni*8 + tq*2;
            float b0 = 0.f, b1 = 0.f;
            if (bias) { b0 = bias[col]; b1 = bias[col+1]; }
            float2 v0 = { acc[mi][ni][0] + b0, acc[mi][ni][1] + b1 };
            float2 v1 = { acc[mi][ni][2] + b0, acc[mi][ni][3] + b1 };
            *(float2*)(C + (size_t)row * GN + col)       = v0;
            *(float2*)(C + (size_t)(row+8) * GN + col)   = v1;
        }
    }
}

// ================= l2-normalize + gate; emits bf16 hi/lo =================
__global__ __launch_bounds__(256) void norm_gate_kernel(const float* __restrict__ raw,
                                                        const float* __restrict__ g,
                                                        __nv_bfloat16* __restrict__ oh,
                                                        __nv_bfloat16* __restrict__ ol,
                                                        float* __restrict__ gate) {
    int task = blockIdx.x * 8 + (threadIdx.x >> 5);
    int lane = threadIdx.x & 31;
    int token = task >> 4;
    int h = task & 15;
    size_t base = (size_t)token * DD + h * HD;
    float2 v = ((const float2*)(raw + base))[lane];
    float sq = v.x*v.x + v.y*v.y;
    #pragma unroll
    for (int o = 16; o > 0; o >>= 1) sq += __shfl_xor_sync(0xffffffffu, sq, o);
    float nrm = sqrtf(sq);
    float inv = 1.0f / fmaxf(nrm, 1e-12f);
    float nx = v.x * inv, ny = v.y * inv;
    uint32_t hp = packbf(nx, ny);
    float lx = nx - __uint_as_float(hp << 16);
    float ly = ny - __uint_as_float(hp & 0xffff0000u);
    uint32_t lp = packbf(lx, ly);
    ((uint32_t*)(oh + base))[lane] = hp;
    ((uint32_t*)(ol + base))[lane] = lp;
    float2 gv = ((const float2*)g)[lane];
    float gp = nx*gv.x + ny*gv.y;
    #pragma unroll
    for (int o = 16; o > 0; o >>= 1) gp += __shfl_xor_sync(0xffffffffu, gp, o);
    if (lane == 0) {
        int b = token / TT, t = token % TT;
        gate[((size_t)(b*HH + h)) * TT + t] = gp;
    }
}

// ================= attention via mma.sync bf16x3 + ldmatrix =================
#define SC 64
#define ATTN_STG 36864
#define ATTN_SMEM (2*ATTN_STG)

__device__ __forceinline__ void attn_load_stage(uint32_t sb, int stage,
        int b, int h, int s0, int t,
        const __nv_bfloat16* __restrict__ Kh, const __nv_bfloat16* __restrict__ Kl,
        const __nv_bfloat16* __restrict__ Vh, const __nv_bfloat16* __restrict__ Vl) {
    uint32_t base = sb + (uint32_t)stage * ATTN_STG;
    int row_lo = t >> 3;
    int c = t & 7;
    #pragma unroll
    for (int i = 0; i < 8; i++) {
        int arr = i >> 1;
        int row = ((i & 1) << 5) + row_lo;
        uint32_t dst = base + (uint32_t)(arr*9216 + row*144 + c*16);
        const __nv_bfloat16* src;
        if (arr == 0)      src = Kh + ((size_t)(b*TT + s0 + row))*DD + h*64 + c*8;
        else if (arr == 1) src = Kl + ((size_t)(b*TT + s0 + row))*DD + h*64 + c*8;
        else if (arr == 2) src = Vh + ((size_t)(b*DD + h*64 + row))*TT + s0 + c*8;
        else               src = Vl + ((size_t)(b*DD + h*64 + row))*TT + s0 + c*8;
        CP_ASYNC16(dst, src);
    }
}

__global__ __launch_bounds__(256) void attn_mma_kernel(
        const __nv_bfloat16* __restrict__ Qh, const __nv_bfloat16* __restrict__ Ql,
        const __nv_bfloat16* __restrict__ Kh, const __nv_bfloat16* __restrict__ Kl,
        const __nv_bfloat16* __restrict__ Vh, const __nv_bfloat16* __restrict__ Vl,
        const float* __restrict__ gateq) {
    extern __shared__ char smc[];
    uint32_t sb = smem_to_u32(smc);
    int t = threadIdx.x;
    int w = t >> 5, lane = t & 31;
    int g = lane >> 2, tq = lane & 3;
    int bh = blockIdx.y;
    int b = bh >> 4, h = bh & 15;
    int t0 = blockIdx.x * 128;
    int trow = t0 + w*16 + g;

    int b_row  = lane & 7;
    int b_msel = (lane >> 4);
    int b_ksel = ((lane >> 3) & 1) * 8;

    uint32_t aqh[4][4], aql[4][4];
    {
        size_t r0 = ((size_t)(b*TT + trow))*DD + h*64;
        size_t r8 = r0 + 8*(size_t)DD;
        #pragma unroll
        for (int kq = 0; kq < 4; kq++) {
            int c = kq*16 + tq*2;
            aqh[kq][0] = *(const uint32_t*)(Qh + r0 + c);
            aqh[kq][1] = *(const uint32_t*)(Qh + r8 + c);
            aqh[kq][2] = *(const uint32_t*)(Qh + r0 + c + 8);
            aqh[kq][3] = *(const uint32_t*)(Qh + r8 + c + 8);
            aql[kq][0] = *(const uint32_t*)(Ql + r0 + c);
            aql[kq][1] = *(const uint32_t*)(Ql + r8 + c);
            aql[kq][2] = *(const uint32_t*)(Ql + r0 + c + 8);
            aql[kq][3] = *(const uint32_t*)(Ql + r8 + c + 8);
        }
    }
    float gq0 = gateq[(size_t)bh*TT + trow];
    float gq1 = gateq[(size_t)bh*TT + trow + 8];

    float cacc[8][4];
    #pragma unroll
    for (int di = 0; di < 8; di++)
        #pragma unroll
        for (int r = 0; r < 4; r++) cacc[di][r] = 0.f;

    attn_load_stage(sb, 0, b, h, 0, t, Kh, Kl, Vh, Vl);
    CP_COMMIT();

    const int NCH = TT / SC;
    for (int ic = 0; ic < NCH; ic++) {
        CP_WAIT0();
        __syncthreads();
        if (ic + 1 < NCH) {
            attn_load_stage(sb, (ic+1) & 1, b, h, (ic+1)*SC, t, Kh, Kl, Vh, Vl);
            CP_COMMIT();
        }
        uint32_t stg = sb + (uint32_t)(ic & 1) * ATTN_STG;
        uint32_t uKh = stg;
        uint32_t uKl = stg +  9216;
        uint32_t uVh = stg + 18432;
        uint32_t uVl = stg + 27648;

        // ---- GEMM1: S[16t x 64s] = Q . K^T ; kk outer, term-ordered over 8 accs ----
        float sacc[8][4];
        #pragma unroll
        for (int si = 0; si < 8; si++)
            #pragma unroll
            for (int r = 0; r < 4; r++) sacc[si][r] = 0.f;

        #pragma unroll
        for (int kk = 0; kk < 4; kk++) {
            uint32_t kfh[4][4], kfl[4][4];
            #pragma unroll
            for (int sp = 0; sp < 4; sp++) {
                uint32_t off = (uint32_t)(((sp*2 + b_msel)*8 + b_row)*144 + (kk*16 + b_ksel)*2);
                LDMX4(kfh[sp][0], kfh[sp][1], kfh[sp][2], kfh[sp][3], uKh + off);
                LDMX4(kfl[sp][0], kfl[sp][1], kfl[sp][2], kfl[sp][3], uKl + off);
            }
            #pragma unroll
            for (int sp = 0; sp < 4; sp++) {
                MMA16816(sacc[2*sp],   aqh[kk][0], aqh[kk][1], aqh[kk][2], aqh[kk][3], kfh[sp][0], kfh[sp][1]);
                MMA16816(sacc[2*sp+1], aqh[kk][0], aqh[kk][1], aqh[kk][2], aqh[kk][3], kfh[sp][2], kfh[sp][3]);
            }
            #pragma unroll
            for (int sp = 0; sp < 4; sp++) {
                MMA16816(sacc[2*sp],   aql[kk][0], aql[kk][1], aql[kk][2], aql[kk][3], kfh[sp][0], kfh[sp][1]);
                MMA16816(sacc[2*sp+1], aql[kk][0], aql[kk][1], aql[kk][2], aql[kk][3], kfh[sp][2], kfh[sp][3]);
            }
            #pragma unroll
            for (int sp = 0; sp < 4; sp++) {
                MMA16816(sacc[2*sp],   aqh[kk][0], aqh[kk][1], aqh[kk][2], aqh[kk][3], kfl[sp][0], kfl[sp][1]);
                MMA16816(sacc[2*sp+1], aqh[kk][0], aqh[kk][1], aqh[kk][2], aqh[kk][3], kfl[sp][2], kfl[sp][3]);
            }
        }

        // ---- modulation: sigmoid only ----
        uint32_t mh[4][4], ml[4][4];
        #pragma unroll
        for (int j = 0; j < 4; j++) {
            #pragma unroll
            for (int half = 0; half < 2; half++) {
                int si = 2*j + half;
                float z00 = (sacc[si][0] - THRESH_C) * SHARP_C;
                float z01 = (sacc[si][1] - THRESH_C) * SHARP_C;
                float z10 = (sacc[si][2] - THRESH_C) * SHARP_C;
                float z11 = (sacc[si][3] - THRESH_C) * SHARP_C;
                float m00 = __fdividef(1.f, 1.f + __expf(-z00));
                float m01 = __fdividef(1.f, 1.f + __expf(-z01));
                float m10 = __fdividef(1.f, 1.f + __expf(-z10));
                float m11 = __fdividef(1.f, 1.f + __expf(-z11));
                uint32_t h0 = packbf(m00, m01);
                uint32_t h1 = packbf(m10, m11);
                float l00 = m00 - __uint_as_float(h0 << 16);
                float l01 = m01 - __uint_as_float(h0 & 0xffff0000u);
                float l10 = m10 - __uint_as_float(h1 << 16);
                float l11 = m11 - __uint_as_float(h1 & 0xffff0000u);
                mh[j][half*2 + 0] = h0;
                mh[j][half*2 + 1] = h1;
                ml[j][half*2 + 0] = packbf(l00, l01);
                ml[j][half*2 + 1] = packbf(l10, l11);
            }
        }

        // ---- GEMM2: C += M . (gk*V) ; j outer, term-ordered over 8 accs ----
        #pragma unroll
        for (int j = 0; j < 4; j++) {
            uint32_t vfh[4][4], vfl[4][4];
            #pragma unroll
            for (int dp = 0; dp < 4; dp++) {
                uint32_t off = (uint32_t)(((dp*2 + b_msel)*8 + b_row)*144 + (j*16 + b_ksel)*2);
                LDMX4(vfh[dp][0], vfh[dp][1], vfh[dp][2], vfh[dp][3], uVh + off);
                LDMX4(vfl[dp][0], vfl[dp][1], vfl[dp][2], vfl[dp][3], uVl + off);
            }
            #pragma unroll
            for (int dp = 0; dp < 4; dp++) {
                MMA16816(cacc[2*dp],   mh[j][0], mh[j][1], mh[j][2], mh[j][3], vfh[dp][0], vfh[dp][1]);
                MMA16816(cacc[2*dp+1], mh[j][0], mh[j][1], mh[j][2], mh[j][3], vfh[dp][2], vfh[dp][3]);
            }
            #pragma unroll
            for (int dp = 0; dp < 4; dp++) {
                MMA16816(cacc[2*dp],   ml[j][0], ml[j][1], ml[j][2], ml[j][3], vfh[dp][0], vfh[dp][1]);
                MMA16816(cacc[2*dp+1], ml[j][0], ml[j][1], ml[j][2], ml[j][3], vfh[dp][2], vfh[dp][3]);
            }
            #pragma unroll
            for (int dp = 0; dp < 4; dp++) {
                MMA16816(cacc[2*dp],   mh[j][0], mh[j][1], mh[j][2], mh[j][3], vfl[dp][0], vfl[dp][1]);
                MMA16816(cacc[2*dp+1], mh[j][0], mh[j][1], mh[j][2], mh[j][3], vfl[dp][2], vfl[dp][3]);
            }
        }
    }

    // epilogue
    size_t obase = ((size_t)(b*TT + trow))*DD + h*64;
    #pragma unroll
    for (int di = 0; di < 8; di++) {
        int col = di*8 + tq*2;
        float c00 = cacc[di][0]*gq0, c01 = cacc[di][1]*gq0;
        float c10 = cacc[di][2]*gq1, c11 = cacc[di][3]*gq1;
        uint32_t h0 = packbf(c00, c01);
        uint32_t h1 = packbf(c10, c11);
        float l00 = c00 - __uint_as_float(h0 << 16);
        float l01 = c01 - __uint_as_float(h0 & 0xffff0000u);
        float l10 = c10 - __uint_as_float(h1 << 16);
        float l11 = c11 - __uint_as_float(h1 & 0xffff0000u);
        *(uint32_t*)(g_ch + obase + col) = h0;
        *(uint32_t*)(g_cl + obase + col) = packbf(l00, l01);
        *(uint32_t*)(g_ch + obase + 8*(size_t)DD + col) = h1;
        *(uint32_t*)(g_cl + obase + 8*(size_t)DD + col) = packbf(l10, l11);
    }
}

// ================= launch =================
extern "C" void kernel_launch(void* const* d_in, const int* in_sizes, int n_in,
                              void* d_out, int out_size) {
    const float* x    = (const float*)d_in[0];
    const float* Wq   = (const float*)d_in[1];
    const float* Wk   = (const float*)d_in[2];
    const float* Wv   = (const float*)d_in[3];
    const float* gq   = (const float*)d_in[4];
    const float* gk   = (const float*)d_in[5];
    const float* Wo   = (const float*)d_in[6];
    const float* bo   = (const float*)d_in[7];
    const float* ln_w = (const float*)d_in[8];
    const float* ln_b = (const float*)d_in[9];
    float* out = (float*)d_out;

    float *p_qraw, *p_kraw, *p_v, *p_gq, *p_gk;
    cudaGetSymbolAddress((void**)&p_qraw, g_qraw);
    cudaGetSymbolAddress((void**)&p_kraw, g_kraw);
    cudaGetSymbolAddress((void**)&p_v,    g_v);
    cudaGetSymbolAddress((void**)&p_gq,   g_gateq);
    cudaGetSymbolAddress((void**)&p_gk,   g_gatek);

    __nv_bfloat16 *p_xh,*p_xl,*p_xnh,*p_xnl,*p_ch,*p_cl;
    __nv_bfloat16 *p_wqh,*p_wql,*p_wkh,*p_wkl,*p_wvh,*p_wvl,*p_woh,*p_wol;
    __nv_bfloat16 *p_qbh,*p_qbl,*p_kbh,*p_kbl,*p_vth,*p_vtl;
    cudaGetSymbolAddress((void**)&p_xh,  g_xh);
    cudaGetSymbolAddress((void**)&p_xl,  g_xl);
    cudaGetSymbolAddress((void**)&p_xnh, g_xnh);
    cudaGetSymbolAddress((void**)&p_xnl, g_xnl);
    cudaGetSymbolAddress((void**)&p_ch,  g_ch);
    cudaGetSymbolAddress((void**)&p_cl,  g_cl);
    cudaGetSymbolAddress((void**)&p_wqh, g_wqh);
    cudaGetSymbolAddress((void**)&p_wql, g_wql);
    cudaGetSymbolAddress((void**)&p_wkh, g_wkh);
    cudaGetSymbolAddress((void**)&p_wkl, g_wkl);
    cudaGetSymbolAddress((void**)&p_wvh, g_wvh);
    cudaGetSymbolAddress((void**)&p_wvl, g_wvl);
    cudaGetSymbolAddress((void**)&p_woh, g_woh);
    cudaGetSymbolAddress((void**)&p_wol, g_wol);
    cudaGetSymbolAddress((void**)&p_qbh, g_qbh);
    cudaGetSymbolAddress((void**)&p_qbl, g_qbl);
    cudaGetSymbolAddress((void**)&p_kbh, g_kbh);
    cudaGetSymbolAddress((void**)&p_kbl, g_kbl);
    cudaGetSymbolAddress((void**)&p_vth, g_vth);
    cudaGetSymbolAddress((void**)&p_vtl, g_vtl);

    cudaFuncSetAttribute(mma_gemm, cudaFuncAttributeMaxDynamicSharedMemorySize, GEMM_SMEM_BYTES);
    cudaFuncSetAttribute(attn_mma_kernel, cudaFuncAttributeMaxDynamicSharedMemorySize, ATTN_SMEM);

    // 1. LayerNorm + splits
    ln_kernel<<<NTOK, 256>>>(x, ln_w, ln_b);

    // 2. weight transpose+split (fused, z-indexed)
    tsplit4_kernel<<<dim3(DD/32, DD/32, 4), 256>>>(Wq, Wk, Wv, Wo);

    // 3. QKV projections
    dim3 ggrid(GN/128, GM/128);
    mma_gemm<<<ggrid, 256, GEMM_SMEM_BYTES>>>(p_xnh, p_xnl, p_wqh, p_wql, p_qraw, nullptr);
    mma_gemm<<<ggrid, 256, GEMM_SMEM_BYTES>>>(p_xnh, p_xnl, p_wkh, p_wkl, p_kraw, nullptr);
    mma_gemm<<<ggrid, 256, GEMM_SMEM_BYTES>>>(p_xh,  p_xl,  p_wvh, p_wvl, p_v,    nullptr);

    // 4. normalize + gates; V transpose+split
    norm_gate_kernel<<<(NTOK*HH)/8, 256>>>(p_qraw, gq, p_qbh, p_qbl, p_gq);
    norm_gate_kernel<<<(NTOK*HH)/8, 256>>>(p_kraw, gk, p_kbh, p_kbl, p_gk);
    vtsplit_kernel<<<dim3(TT/32, DD/32, BB), 256>>>(p_v, p_gk, p_vth, p_vtl);

    // 5. attention
    attn_mma_kernel<<<dim3(TT/128, BB*HH), 256, ATTN_SMEM>>>(
        p_qbh, p_qbl, p_kbh, p_kbl, p_vth, p_vtl, p_gq);

    // 6. output projection
    mma_gemm<<<ggrid, 256, GEMM_SMEM_BYTES>>>(p_ch, p_cl, p_woh, p_wol, out, bo);
}

// round 8
// speedup vs baseline: 3.8615x; 1.3389x over previous
#include <cuda_runtime.h>
#include <cuda_fp16.h>
#include <cstdint>
#include <math.h>

#define BB 2
#define TT 2048
#define DD 1024
#define HH 16
#define HD 64
#define NTOK (BB*TT)

#define GM 4096
#define GN 1024
#define GK 1024

#define THRESH_C 0.29514f
#define SHARP_C  15.0f

// ================= low-level helpers =================
#define CP_ASYNC16(dst_u32, src_ptr) \
    asm volatile("cp.async.cg.shared.global [%0], [%1], 16;" \
        :: "r"(dst_u32), "l"(src_ptr) : "memory")
#define CP_COMMIT() asm volatile("cp.async.commit_group;" ::: "memory")
#define CP_WAIT0()  asm volatile("cp.async.wait_group 0;" ::: "memory")

__device__ __forceinline__ uint32_t smem_to_u32(const void* smem_ptr) {
    uint32_t addr;
    asm("{ .reg .u64 tmp; cvta.to.shared.u64 tmp, %1; cvt.u32.u64 %0, tmp; }"
        : "=r"(addr) : "l"(smem_ptr));
    return addr;
}

// fp16 mma m16n8k16 (sm_80+ baseline)
#define MMA16816(d, a0, a1, a2, a3, b0, b1) \
    asm volatile("mma.sync.aligned.m16n8k16.row.col.f32.f16.f16.f32 " \
        "{%0,%1,%2,%3}, {%4,%5,%6,%7}, {%8,%9}, {%0,%1,%2,%3};" \
        : "+f"((d)[0]), "+f"((d)[1]), "+f"((d)[2]), "+f"((d)[3]) \
        : "r"(a0), "r"(a1), "r"(a2), "r"(a3), "r"(b0), "r"(b1))

#define LDMX4(r0, r1, r2, r3, addr) \
    asm volatile("ldmatrix.sync.aligned.m8n8.x4.shared.b16 {%0,%1,%2,%3}, [%4];" \
        : "=r"(r0), "=r"(r1), "=r"(r2), "=r"(r3) : "r"(addr))

// split two fp32 into fp16 hi + fp16 residual lo, packed as half2 words
__device__ __forceinline__ void split2(float x, float y, uint32_t& hw, uint32_t& lw) {
    __half hx = __float2half_rn(x), hy = __float2half_rn(y);
    __half lx = __float2half_rn(x - __half2float(hx));
    __half ly = __float2half_rn(y - __half2float(hy));
    __half2 hp = __halves2half2(hx, hy);
    __half2 lp = __halves2half2(lx, ly);
    hw = *(uint32_t*)&hp;
    lw = *(uint32_t*)&lp;
}

// ================= scratch =================
__device__ float g_qraw[NTOK*DD];
__device__ float g_kraw[NTOK*DD];
__device__ float g_v[NTOK*DD];
__device__ float g_gateq[BB*HH*TT];
__device__ float g_gatek[BB*HH*TT];

__device__ __half g_xh[NTOK*DD],  g_xl[NTOK*DD];     // raw x hi/lo (A of V-proj)
__device__ __half g_xnh[NTOK*DD], g_xnl[NTOK*DD];    // layernormed x hi/lo
__device__ __half g_ch[NTOK*DD],  g_cl[NTOK*DD];     // collapse hi/lo (A of out-proj)
__device__ __half g_wqh[DD*DD], g_wkh[DD*DD], g_wvh[DD*DD], g_woh[DD*DD];  // B fp16
__device__ __half g_qbh[NTOK*DD], g_qbl[NTOK*DD];    // normalized q hi/lo (A side)
__device__ __half g_kbh[NTOK*DD];                     // normalized k (B side, fp16)
__device__ __half g_vth[BB*DD*TT];                    // gk*V transposed (B side)

// ================= LayerNorm fused with fp16 hi/lo splits =================
__global__ __launch_bounds__(256) void ln_kernel(const float* __restrict__ x,
                                                 const float* __restrict__ w,
                                                 const float* __restrict__ b) {
    int row = blockIdx.x;
    int tid = threadIdx.x;
    const float4* xr = (const float4*)(x + (size_t)row * DD);
    float4 v = xr[tid];
    float s  = v.x + v.y + v.z + v.w;
    float sq = v.x*v.x + v.y*v.y + v.z*v.z + v.w*v.w;
    #pragma unroll
    for (int o = 16; o > 0; o >>= 1) {
        s  += __shfl_xor_sync(0xffffffffu, s,  o);
        sq += __shfl_xor_sync(0xffffffffu, sq, o);
    }
    __shared__ float ss[8], ssq[8];
    int wid = tid >> 5, lid = tid & 31;
    if (lid == 0) { ss[wid] = s; ssq[wid] = sq; }
    __syncthreads();
    float ts = 0.f, tsq = 0.f;
    #pragma unroll
    for (int i = 0; i < 8; i++) { ts += ss[i]; tsq += ssq[i]; }
    float mu  = ts * (1.0f/DD);
    float var = tsq * (1.0f/DD) - mu*mu;
    float inv = rsqrtf(var + 1e-5f);
    float4 wv = ((const float4*)w)[tid];
    float4 bv = ((const float4*)b)[tid];
    float4 o;
    o.x = (v.x - mu) * inv * wv.x + bv.x;
    o.y = (v.y - mu) * inv * wv.y + bv.y;
    o.z = (v.z - mu) * inv * wv.z + bv.z;
    o.w = (v.w - mu) * inv * wv.w + bv.w;

    int i4 = row * (DD/4) + tid;
    {
        uint2 hw, lw;
        split2(v.x, v.y, hw.x, lw.x);
        split2(v.z, v.w, hw.y, lw.y);
        ((uint2*)g_xh)[i4] = hw;
        ((uint2*)g_xl)[i4] = lw;
    }
    {
        uint2 hw, lw;
        split2(o.x, o.y, hw.x, lw.x);
        split2(o.z, o.w, hw.y, lw.y);
        ((uint2*)g_xnh)[i4] = hw;
        ((uint2*)g_xnl)[i4] = lw;
    }
}

// ===== all 4 weights: W[K,N] -> Wt[N,K] transpose, fp16 (z-indexed) =====
__global__ __launch_bounds__(256) void tsplit4_kernel(const float* __restrict__ W0,
                                                      const float* __restrict__ W1,
                                                      const float* __restrict__ W2,
                                                      const float* __restrict__ W3) {
    __shared__ float tile[32][33];
    const float* W;
    __half* th;
    switch (blockIdx.z) {
        case 0: W = W0; th = g_wqh; break;
        case 1: W = W1; th = g_wkh; break;
        case 2: W = W2; th = g_wvh; break;
        default: W = W3; th = g_woh; break;
    }
    int bx = blockIdx.x * 32;
    int by = blockIdx.y * 32;
    int tx = threadIdx.x & 31;
    int ty = threadIdx.x >> 5;
    #pragma unroll
    for (int i = 0; i < 4; i++) {
        int k = by + ty + i*8;
        tile[ty + i*8][tx] = W[(size_t)k * DD + bx + tx];
    }
    __syncthreads();
    #pragma unroll
    for (int i = 0; i < 4; i++) {
        int n = bx + ty + i*8;
        int k = by + tx;
        th[(size_t)n * DD + k] = __float2half_rn(tile[tx][ty + i*8]);
    }
}

// ========== V[b][t][d] -> Vt[b*DD+d][t] transpose, gate_k premultiplied, fp16 ==========
__global__ __launch_bounds__(256) void vtsplit_kernel(const float* __restrict__ V,
                                                      const float* __restrict__ gatek,
                                                      __half* __restrict__ th) {
    __shared__ float tile[32][33];
    int b  = blockIdx.z;
    int t0 = blockIdx.x * 32;
    int d0 = blockIdx.y * 32;
    int tx = threadIdx.x & 31;
    int ty = threadIdx.x >> 5;
    #pragma unroll
    for (int i = 0; i < 4; i++) {
        int tt = t0 + ty + i*8;
        tile[ty + i*8][tx] = V[((size_t)(b*TT + tt)) * DD + d0 + tx];
    }
    __syncthreads();
    int h = d0 >> 6;
    float gk = gatek[((size_t)(b*HH + h)) * TT + t0 + tx];
    #pragma unroll
    for (int i = 0; i < 4; i++) {
        int d = d0 + ty + i*8;
        int tt = t0 + tx;
        th[((size_t)(b*DD + d)) * TT + tt] = __float2half_rn(tile[tx][ty + i*8] * gk);
    }
}

// ================= mma.sync fp16x2 GEMM (projections): Ah,Al split, Bh fp16 =================
#define PAD_K 40
#define ARR_ELEMS (128*PAD_K)
#define STAGE_BYTES (3*ARR_ELEMS*2)          // Ah, Al, Bh = 30720 B
#define GEMM_SMEM_BYTES (2*STAGE_BYTES)      // 61440 B

__device__ __forceinline__ void gemm_load_stage(uint32_t sm_u32, int stage,
        const __half* __restrict__ Ah, const __half* __restrict__ Al,
        const __half* __restrict__ Bh,
        int m0, int n0, int k0, int t) {
    uint32_t sbase = sm_u32 + (uint32_t)stage * STAGE_BYTES;
    #pragma unroll
    for (int o = 0; o < 2; o++) {
        int linear = t + o*256;
        int r  = linear >> 2;
        int c8 = linear & 3;
        uint32_t soff = (uint32_t)(r*(PAD_K*2) + c8*16);
        size_t goffA = (size_t)(m0 + r) * GK + k0 + c8*8;
        size_t goffB = (size_t)(n0 + r) * GK + k0 + c8*8;
        CP_ASYNC16(sbase +                 soff, Ah + goffA);
        CP_ASYNC16(sbase + 1*ARR_ELEMS*2 + soff, Al + goffA);
        CP_ASYNC16(sbase + 2*ARR_ELEMS*2 + soff, Bh + goffB);
    }
}

__global__ __launch_bounds__(256) void mma_gemm(const __half* __restrict__ Ah,
                                                const __half* __restrict__ Al,
                                                const __half* __restrict__ Bh,
                                                float* __restrict__ C,
                                                const float* __restrict__ bias) {
    extern __shared__ __half smb[];
    uint32_t sm_u32 = smem_to_u32(smb);
    int t = threadIdx.x;
    int wid = t >> 5, lane = t & 31;
    int wm = wid & 1;
    int wn = wid >> 1;
    int g  = lane >> 2;
    int tq = lane & 3;

    int m0 = blockIdx.y * 128, n0 = blockIdx.x * 128;

    float acc[4][4][4];
    #pragma unroll
    for (int mi = 0; mi < 4; mi++)
        #pragma unroll
        for (int ni = 0; ni < 4; ni++)
            #pragma unroll
            for (int r = 0; r < 4; r++) acc[mi][ni][r] = 0.f;

    int a_rsel = lane & 15;
    int a_ksel = (lane >> 4) * 8;
    int b_row  = lane & 7;
    int b_msel = (lane >> 4);
    int b_ksel = ((lane >> 3) & 1) * 8;

    gemm_load_stage(sm_u32, 0, Ah, Al, Bh, m0, n0, 0, t);
    CP_COMMIT();

    const int NIT = GK / 32;
    for (int it = 0; it < NIT; it++) {
        CP_WAIT0();
        __syncthreads();
        if (it + 1 < NIT) {
            gemm_load_stage(sm_u32, (it+1) & 1, Ah, Al, Bh, m0, n0, (it+1)*32, t);
            CP_COMMIT();
        }
        uint32_t S   = sm_u32 + (uint32_t)(it & 1) * STAGE_BYTES;
        uint32_t uAh = S;
        uint32_t uAl = S + 1*ARR_ELEMS*2;
        uint32_t uBh = S + 2*ARR_ELEMS*2;

        #pragma unroll
        for (int kk = 0; kk < 32; kk += 16) {
            uint32_t ah[4][4], al[4][4];
            #pragma unroll
            for (int mi = 0; mi < 4; mi++) {
                uint32_t off = (uint32_t)(((wm*64 + mi*16 + a_rsel) * PAD_K + kk + a_ksel) * 2);
                LDMX4(ah[mi][0], ah[mi][1], ah[mi][2], ah[mi][3], uAh + off);
                LDMX4(al[mi][0], al[mi][1], al[mi][2], al[mi][3], uAl + off);
            }
            uint32_t bh[4][2];
            #pragma unroll
            for (int np = 0; np < 2; np++) {
                uint32_t off = (uint32_t)(((wn*32 + (np*2 + b_msel)*8 + b_row) * PAD_K + kk + b_ksel) * 2);
                uint32_t r0, r1, r2, r3;
                LDMX4(r0, r1, r2, r3, uBh + off);
                bh[np*2][0]=r0; bh[np*2][1]=r1; bh[np*2+1][0]=r2; bh[np*2+1][1]=r3;
            }
            #pragma unroll
            for (int ni = 0; ni < 4; ni++)
                #pragma unroll
                for (int mi = 0; mi < 4; mi++)
                    MMA16816(acc[mi][ni], ah[mi][0], ah[mi][1], ah[mi][2], ah[mi][3], bh[ni][0], bh[ni][1]);
            #pragma unroll
            for (int ni = 0; ni < 4; ni++)
                #pragma unroll
                for (int mi = 0; mi < 4; mi++)
                    MMA16816(acc[mi][ni], al[mi][0], al[mi][1], al[mi][2], al[mi][3], bh[ni][0], bh[ni][1]);
        }
    }

    #pragma unroll
    for (int mi = 0; mi < 4; mi++) {
        int row = m0 + wm*64 + mi*16 + g;
        #pragma unroll
        for (int ni = 0; ni < 4; ni++) {
            int col = n0 + wn*32 + ni*8 + tq*2;
            float b0 = 0.f, b1 = 0.f;
            if (bias) { b0 = bias[col]; b1 = bias[col+1]; }
            float2 v0 = { acc[mi][ni][0] + b0, acc[mi][ni][1] + b1 };
            float2 v1 = { acc[mi][ni][2] + b0, acc[mi][ni][3] + b1 };
            *(float2*)(C + (size_t)row * GN + col)       = v0;
            *(float2*)(C + (size_t)(row+8) * GN + col)   = v1;
        }
    }
}

// ================= l2-normalize + gate; emits fp16 (hi[/lo]) =================
__global__ __launch_bounds__(256) void norm_gate_kernel(const float* __restrict__ raw,
                                                        const float* __restrict__ g,
                                                        __half* __restrict__ oh,
                                                        __half* __restrict__ ol,   // may be null
                                                        float* __restrict__ gate) {
    int task = blockIdx.x * 8 + (threadIdx.x >> 5);
    int lane = threadIdx.x & 31;
    int token = task >> 4;
    int h = task & 15;
    size_t base = (size_t)token * DD + h * HD;
    float2 v = ((const float2*)(raw + base))[lane];
    float sq = v.x*v.x + v.y*v.y;
    #pragma unroll
    for (int o = 16; o > 0; o >>= 1) sq += __shfl_xor_sync(0xffffffffu, sq, o);
    float nrm = sqrtf(sq);
    float inv = 1.0f / fmaxf(nrm, 1e-12f);
    float nx = v.x * inv, ny = v.y * inv;
    uint32_t hw, lw;
    split2(nx, ny, hw, lw);
    ((uint32_t*)(oh + base))[lane] = hw;
    if (ol) ((uint32_t*)(ol + base))[lane] = lw;
    float2 gv = ((const float2*)g)[lane];
    float gp = nx*gv.x + ny*gv.y;
    #pragma unroll
    for (int o = 16; o > 0; o >>= 1) gp += __shfl_xor_sync(0xffffffffu, gp, o);
    if (lane == 0) {
        int b = token / TT, t = token % TT;
        gate[((size_t)(b*HH + h)) * TT + t] = gp;
    }
}

// ================= attention via mma.sync fp16x2 + ldmatrix =================
#define SC 64
#define ATTN_STG 18432              // Kh (9216) + Vh (9216)
#define ATTN_SMEM (2*ATTN_STG)

__device__ __forceinline__ void attn_load_stage(uint32_t sb, int stage,
        int b, int h, int s0, int t,
        const __half* __restrict__ Kh, const __half* __restrict__ Vh) {
    uint32_t base = sb + (uint32_t)stage * ATTN_STG;
    int row_lo = t >> 3;
    int c = t & 7;
    #pragma unroll
    for (int i = 0; i < 4; i++) {
        int arr = i >> 1;
        int row = ((i & 1) << 5) + row_lo;
        uint32_t dst = base + (uint32_t)(arr*9216 + row*144 + c*16);
        const __half* src = (arr == 0)
            ? Kh + ((size_t)(b*TT + s0 + row))*DD + h*64 + c*8
            : Vh + ((size_t)(b*DD + h*64 + row))*TT + s0 + c*8;
        CP_ASYNC16(dst, src);
    }
}

__global__ __launch_bounds__(256) void attn_mma_kernel(
        const __half* __restrict__ Qh, const __half* __restrict__ Ql,
        const __half* __restrict__ Kh, const __half* __restrict__ Vh,
        const float* __restrict__ gateq) {
    extern __shared__ char smc[];
    uint32_t sb = smem_to_u32(smc);
    int t = threadIdx.x;
    int w = t >> 5, lane = t & 31;
    int g = lane >> 2, tq = lane & 3;
    int bh = blockIdx.y;
    int b = bh >> 4, h = bh & 15;
    int t0 = blockIdx.x * 128;
    int trow = t0 + w*16 + g;

    int b_row  = lane & 7;
    int b_msel = (lane >> 4);
    int b_ksel = ((lane >> 3) & 1) * 8;

    uint32_t aqh[4][4], aql[4][4];
    {
        size_t r0 = ((size_t)(b*TT + trow))*DD + h*64;
        size_t r8 = r0 + 8*(size_t)DD;
        #pragma unroll
        for (int kq = 0; kq < 4; kq++) {
            int c = kq*16 + tq*2;
            aqh[kq][0] = *(const uint32_t*)(Qh + r0 + c);
            aqh[kq][1] = *(const uint32_t*)(Qh + r8 + c);
            aqh[kq][2] = *(const uint32_t*)(Qh + r0 + c + 8);
            aqh[kq][3] = *(const uint32_t*)(Qh + r8 + c + 8);
            aql[kq][0] = *(const uint32_t*)(Ql + r0 + c);
            aql[kq][1] = *(const uint32_t*)(Ql + r8 + c);
            aql[kq][2] = *(const uint32_t*)(Ql + r0 + c + 8);
            aql[kq][3] = *(const uint32_t*)(Ql + r8 + c + 8);
        }
    }
    float gq0 = gateq[(size_t)bh*TT + trow];
    float gq1 = gateq[(size_t)bh*TT + trow + 8];

    float cacc[8][4];
    #pragma unroll
    for (int di = 0; di < 8; di++)
        #pragma unroll
        for (int r = 0; r < 4; r++) cacc[di][r] = 0.f;

    attn_load_stage(sb, 0, b, h, 0, t, Kh, Vh);
    CP_COMMIT();

    const int NCH = TT / SC;
    for (int ic = 0; ic < NCH; ic++) {
        CP_WAIT0();
        __syncthreads();
        if (ic + 1 < NCH) {
            attn_load_stage(sb, (ic+1) & 1, b, h, (ic+1)*SC, t, Kh, Vh);
            CP_COMMIT();
        }
        uint32_t stg = sb + (uint32_t)(ic & 1) * ATTN_STG;
        uint32_t uKh = stg;
        uint32_t uVh = stg + 9216;

        // ---- GEMM1: S = Q . K^T (Ah+Al terms) ----
        float sacc[8][4];
        #pragma unroll
        for (int si = 0; si < 8; si++)
            #pragma unroll
            for (int r = 0; r < 4; r++) sacc[si][r] = 0.f;

        #pragma unroll
        for (int kk = 0; kk < 4; kk++) {
            uint32_t kfh[4][4];
            #pragma unroll
            for (int sp = 0; sp < 4; sp++) {
                uint32_t off = (uint32_t)(((sp*2 + b_msel)*8 + b_row)*144 + (kk*16 + b_ksel)*2);
                LDMX4(kfh[sp][0], kfh[sp][1], kfh[sp][2], kfh[sp][3], uKh + off);
            }
            #pragma unroll
            for (int sp = 0; sp < 4; sp++) {
                MMA16816(sacc[2*sp],   aqh[kk][0], aqh[kk][1], aqh[kk][2], aqh[kk][3], kfh[sp][0], kfh[sp][1]);
                MMA16816(sacc[2*sp+1], aqh[kk][0], aqh[kk][1], aqh[kk][2], aqh[kk][3], kfh[sp][2], kfh[sp][3]);
            }
            #pragma unroll
            for (int sp = 0; sp < 4; sp++) {
                MMA16816(sacc[2*sp],   aql[kk][0], aql[kk][1], aql[kk][2], aql[kk][3], kfh[sp][0], kfh[sp][1]);
                MMA16816(sacc[2*sp+1], aql[kk][0], aql[kk][1], aql[kk][2], aql[kk][3], kfh[sp][2], kfh[sp][3]);
            }
        }

        // ---- modulation: sigmoid, fp16 hi/lo pack ----
        uint32_t mh[4][4], ml[4][4];
        #pragma unroll
        for (int j = 0; j < 4; j++) {
            #pragma unroll
            for (int half = 0; half < 2; half++) {
                int si = 2*j + half;
                float z00 = (sacc[si][0] - THRESH_C) * SHARP_C;
                float z01 = (sacc[si][1] - THRESH_C) * SHARP_C;
                float z10 = (sacc[si][2] - THRESH_C) * SHARP_C;
                float z11 = (sacc[si][3] - THRESH_C) * SHARP_C;
                float m00 = __fdividef(1.f, 1.f + __expf(-z00));
                float m01 = __fdividef(1.f, 1.f + __expf(-z01));
                float m10 = __fdividef(1.f, 1.f + __expf(-z10));
                float m11 = __fdividef(1.f, 1.f + __expf(-z11));
                uint32_t h0, l0, h1, l1;
                split2(m00, m01, h0, l0);
                split2(m10, m11, h1, l1);
                mh[j][half*2 + 0] = h0;
                mh[j][half*2 + 1] = h1;
                ml[j][half*2 + 0] = l0;
                ml[j][half*2 + 1] = l1;
            }
        }

        // ---- GEMM2: C += M . (gk*V) (Mh+Ml terms) ----
        #pragma unroll
        for (int j = 0; j < 4; j++) {
            uint32_t vfh[4][4];
            #pragma unroll
            for (int dp = 0; dp < 4; dp++) {
                uint32_t off = (uint32_t)(((dp*2 + b_msel)*8 + b_row)*144 + (j*16 + b_ksel)*2);
                LDMX4(vfh[dp][0], vfh[dp][1], vfh[dp][2], vfh[dp][3], uVh + off);
            }
            #pragma unroll
            for (int dp = 0; dp < 4; dp++) {
                MMA16816(cacc[2*dp],   mh[j][0], mh[j][1], mh[j][2], mh[j][3], vfh[dp][0], vfh[dp][1]);
                MMA16816(cacc[2*dp+1], mh[j][0], mh[j][1], mh[j][2], mh[j][3], vfh[dp][2], vfh[dp][3]);
            }
            #pragma unroll
            for (int dp = 0; dp < 4; dp++) {
                MMA16816(cacc[2*dp],   ml[j][0], ml[j][1], ml[j][2], ml[j][3], vfh[dp][0], vfh[dp][1]);
                MMA16816(cacc[2*dp+1], ml[j][0], ml[j][1], ml[j][2], ml[j][3], vfh[dp][2], vfh[dp][3]);
            }
        }
    }

    // epilogue: apply gq, split to fp16 hi/lo collapse
    size_t obase = ((size_t)(b*TT + trow))*DD + h*64;
    #pragma unroll
    for (int di = 0; di < 8; di++) {
        int col = di*8 + tq*2;
        float c00 = cacc[di][0]*gq0, c01 = cacc[di][1]*gq0;
        float c10 = cacc[di][2]*gq1, c11 = cacc[di][3]*gq1;
        uint32_t h0, l0, h1, l1;
        split2(c00, c01, h0, l0);
        split2(c10, c11, h1, l1);
        *(uint32_t*)(g_ch + obase + col) = h0;
        *(uint32_t*)(g_cl + obase + col) = l0;
        *(uint32_t*)(g_ch + obase + 8*(size_t)DD + col) = h1;
        *(uint32_t*)(g_cl + obase + 8*(size_t)DD + col) = l1;
    }
}

// ================= launch =================
extern "C" void kernel_launch(void* const* d_in, const int* in_sizes, int n_in,
                              void* d_out, int out_size) {
    const float* x    = (const float*)d_in[0];
    const float* Wq   = (const float*)d_in[1];
    const float* Wk   = (const float*)d_in[2];
    const float* Wv   = (const float*)d_in[3];
    const float* gq   = (const float*)d_in[4];
    const float* gk   = (const float*)d_in[5];
    const float* Wo   = (const float*)d_in[6];
    const float* bo   = (const float*)d_in[7];
    const float* ln_w = (const float*)d_in[8];
    const float* ln_b = (const float*)d_in[9];
    float* out = (float*)d_out;

    float *p_qraw, *p_kraw, *p_v, *p_gq, *p_gk;
    cudaGetSymbolAddress((void**)&p_qraw, g_qraw);
    cudaGetSymbolAddress((void**)&p_kraw, g_kraw);
    cudaGetSymbolAddress((void**)&p_v,    g_v);
    cudaGetSymbolAddress((void**)&p_gq,   g_gateq);
    cudaGetSymbolAddress((void**)&p_gk,   g_gatek);

    __half *p_xh,*p_xl,*p_xnh,*p_xnl,*p_ch,*p_cl;
    __half *p_wqh,*p_wkh,*p_wvh,*p_woh;
    __half *p_qbh,*p_qbl,*p_kbh,*p_vth;
    cudaGetSymbolAddress((void**)&p_xh,  g_xh);
    cudaGetSymbolAddress((void**)&p_xl,  g_xl);
    cudaGetSymbolAddress((void**)&p_xnh, g_xnh);
    cudaGetSymbolAddress((void**)&p_xnl, g_xnl);
    cudaGetSymbolAddress((void**)&p_ch,  g_ch);
    cudaGetSymbolAddress((void**)&p_cl,  g_cl);
    cudaGetSymbolAddress((void**)&p_wqh, g_wqh);
    cudaGetSymbolAddress((void**)&p_wkh, g_wkh);
    cudaGetSymbolAddress((void**)&p_wvh, g_wvh);
    cudaGetSymbolAddress((void**)&p_woh, g_woh);
    cudaGetSymbolAddress((void**)&p_qbh, g_qbh);
    cudaGetSymbolAddress((void**)&p_qbl, g_qbl);
    cudaGetSymbolAddress((void**)&p_kbh, g_kbh);
    cudaGetSymbolAddress((void**)&p_vth, g_vth);

    cudaFuncSetAttribute(mma_gemm, cudaFuncAttributeMaxDynamicSharedMemorySize, GEMM_SMEM_BYTES);
    cudaFuncSetAttribute(attn_mma_kernel, cudaFuncAttributeMaxDynamicSharedMemorySize, ATTN_SMEM);

    // 1. LayerNorm + splits
    ln_kernel<<<NTOK, 256>>>(x, ln_w, ln_b);

    // 2. weight transpose (fp16), z-indexed
    tsplit4_kernel<<<dim3(DD/32, DD/32, 4), 256>>>(Wq, Wk, Wv, Wo);

    // 3. QKV projections (A hi/lo x B fp16)
    dim3 ggrid(GN/128, GM/128);
    mma_gemm<<<ggrid, 256, GEMM_SMEM_BYTES>>>(p_xnh, p_xnl, p_wqh, p_qraw, nullptr);
    mma_gemm<<<ggrid, 256, GEMM_SMEM_BYTES>>>(p_xnh, p_xnl, p_wkh, p_kraw, nullptr);
    mma_gemm<<<ggrid, 256, GEMM_SMEM_BYTES>>>(p_xh,  p_xl,  p_wvh, p_v,    nullptr);

    // 4. normalize + gates; V transpose
    norm_gate_kernel<<<(NTOK*HH)/8, 256>>>(p_qraw, gq, p_qbh, p_qbl, p_gq);
    norm_gate_kernel<<<(NTOK*HH)/8, 256>>>(p_kraw, gk, p_kbh, nullptr, p_gk);
    vtsplit_kernel<<<dim3(TT/32, DD/32, BB), 256>>>(p_v, p_gk, p_vth);

    // 5. attention
    attn_mma_kernel<<<dim3(TT/128, BB*HH), 256, ATTN_SMEM>>>(
        p_qbh, p_qbl, p_kbh, p_vth, p_gq);

    // 6. output projection
    mma_gemm<<<ggrid, 256, GEMM_SMEM_BYTES>>>(p_ch, p_cl, p_woh, out, bo);
}

// round 9
// speedup vs baseline: 4.4685x; 1.1572x over previous
#include <cuda_runtime.h>
#include <cuda_fp16.h>
#include <cstdint>
#include <math.h>

#define BB 2
#define TT 2048
#define DD 1024
#define HH 16
#define HD 64
#define NTOK (BB*TT)

#define GM 4096
#define GN 1024
#define GK 1024

#define THRESH_C 0.29514f
#define SHARP_C  15.0f

// ================= low-level helpers =================
#define CP_ASYNC16(dst_u32, src_ptr) \
    asm volatile("cp.async.cg.shared.global [%0], [%1], 16;" \
        :: "r"(dst_u32), "l"(src_ptr) : "memory")
#define CP_COMMIT() asm volatile("cp.async.commit_group;" ::: "memory")
#define CP_WAIT1()  asm volatile("cp.async.wait_group 1;" ::: "memory")
#define CP_WAIT2()  asm volatile("cp.async.wait_group 2;" ::: "memory")

__device__ __forceinline__ uint32_t smem_to_u32(const void* smem_ptr) {
    uint32_t addr;
    asm("{ .reg .u64 tmp; cvta.to.shared.u64 tmp, %1; cvt.u32.u64 %0, tmp; }"
        : "=r"(addr) : "l"(smem_ptr));
    return addr;
}

#define MMA16816(d, a0, a1, a2, a3, b0, b1) \
    asm volatile("mma.sync.aligned.m16n8k16.row.col.f32.f16.f16.f32 " \
        "{%0,%1,%2,%3}, {%4,%5,%6,%7}, {%8,%9}, {%0,%1,%2,%3};" \
        : "+f"((d)[0]), "+f"((d)[1]), "+f"((d)[2]), "+f"((d)[3]) \
        : "r"(a0), "r"(a1), "r"(a2), "r"(a3), "r"(b0), "r"(b1))

#define LDMX4(r0, r1, r2, r3, addr) \
    asm volatile("ldmatrix.sync.aligned.m8n8.x4.shared.b16 {%0,%1,%2,%3}, [%4];" \
        : "=r"(r0), "=r"(r1), "=r"(r2), "=r"(r3) : "r"(addr))

// split two fp32 into fp16 hi + fp16 residual lo, packed as half2 words
__device__ __forceinline__ void split2(float x, float y, uint32_t& hw, uint32_t& lw) {
    __half hx = __float2half_rn(x), hy = __float2half_rn(y);
    __half lx = __float2half_rn(x - __half2float(hx));
    __half ly = __float2half_rn(y - __half2float(hy));
    __half2 hp = __halves2half2(hx, hy);
    __half2 lp = __halves2half2(lx, ly);
    hw = *(uint32_t*)&hp;
    lw = *(uint32_t*)&lp;
}
__device__ __forceinline__ uint32_t packh2(float x, float y) {
    __half2 hp = __floats2half2_rn(x, y);
    return *(uint32_t*)&hp;
}

// ================= scratch =================
__device__ float g_qraw[NTOK*DD];
__device__ float g_kraw[NTOK*DD];
__device__ float g_v[NTOK*DD];
__device__ float g_gateq[BB*HH*TT];
__device__ float g_gatek[BB*HH*TT];

__device__ __half g_xh[NTOK*DD];                     // raw x fp16 (A of V-proj, 1-term)
__device__ __half g_xnh[NTOK*DD], g_xnl[NTOK*DD];    // layernormed x hi/lo
__device__ __half g_ch[NTOK*DD],  g_cl[NTOK*DD];     // collapse hi/lo (A of out-proj)
__device__ __half g_wqh[DD*DD], g_wkh[DD*DD], g_wvh[DD*DD], g_woh[DD*DD];  // B fp16
__device__ __half g_qbh[NTOK*DD], g_qbl[NTOK*DD];    // normalized q hi/lo (A side)
__device__ __half g_kbh[NTOK*DD];                     // normalized k (B side, fp16)
__device__ __half g_vth[BB*DD*TT];                    // gk*V transposed (B side)

// ================= LayerNorm fused with fp16 splits =================
__global__ __launch_bounds__(256) void ln_kernel(const float* __restrict__ x,
                                                 const float* __restrict__ w,
                                                 const float* __restrict__ b) {
    int row = blockIdx.x;
    int tid = threadIdx.x;
    const float4* xr = (const float4*)(x + (size_t)row * DD);
    float4 v = xr[tid];
    float s  = v.x + v.y + v.z + v.w;
    float sq = v.x*v.x + v.y*v.y + v.z*v.z + v.w*v.w;
    #pragma unroll
    for (int o = 16; o > 0; o >>= 1) {
        s  += __shfl_xor_sync(0xffffffffu, s,  o);
        sq += __shfl_xor_sync(0xffffffffu, sq, o);
    }
    __shared__ float ss[8], ssq[8];
    int wid = tid >> 5, lid = tid & 31;
    if (lid == 0) { ss[wid] = s; ssq[wid] = sq; }
    __syncthreads();
    float ts = 0.f, tsq = 0.f;
    #pragma unroll
    for (int i = 0; i < 8; i++) { ts += ss[i]; tsq += ssq[i]; }
    float mu  = ts * (1.0f/DD);
    float var = tsq * (1.0f/DD) - mu*mu;
    float inv = rsqrtf(var + 1e-5f);
    float4 wv = ((const float4*)w)[tid];
    float4 bv = ((const float4*)b)[tid];
    float4 o;
    o.x = (v.x - mu) * inv * wv.x + bv.x;
    o.y = (v.y - mu) * inv * wv.y + bv.y;
    o.z = (v.z - mu) * inv * wv.z + bv.z;
    o.w = (v.w - mu) * inv * wv.w + bv.w;

    int i4 = row * (DD/4) + tid;
    {
        uint2 hw = { packh2(v.x, v.y), packh2(v.z, v.w) };
        ((uint2*)g_xh)[i4] = hw;
    }
    {
        uint2 hw, lw;
        split2(o.x, o.y, hw.x, lw.x);
        split2(o.z, o.w, hw.y, lw.y);
        ((uint2*)g_xnh)[i4] = hw;
        ((uint2*)g_xnl)[i4] = lw;
    }
}

// ===== all 4 weights: W[K,N] -> Wt[N,K] transpose, fp16 (z-indexed) =====
__global__ __launch_bounds__(256) void tsplit4_kernel(const float* __restrict__ W0,
                                                      const float* __restrict__ W1,
                                                      const float* __restrict__ W2,
                                                      const float* __restrict__ W3) {
    __shared__ float tile[32][33];
    const float* W;
    __half* th;
    switch (blockIdx.z) {
        case 0: W = W0; th = g_wqh; break;
        case 1: W = W1; th = g_wkh; break;
        case 2: W = W2; th = g_wvh; break;
        default: W = W3; th = g_woh; break;
    }
    int bx = blockIdx.x * 32;
    int by = blockIdx.y * 32;
    int tx = threadIdx.x & 31;
    int ty = threadIdx.x >> 5;
    #pragma unroll
    for (int i = 0; i < 4; i++) {
        int k = by + ty + i*8;
        tile[ty + i*8][tx] = W[(size_t)k * DD + bx + tx];
    }
    __syncthreads();
    #pragma unroll
    for (int i = 0; i < 4; i++) {
        int n = bx + ty + i*8;
        int k = by + tx;
        th[(size_t)n * DD + k] = __float2half_rn(tile[tx][ty + i*8]);
    }
}

// ========== V[b][t][d] -> Vt[b*DD+d][t] transpose, gate_k premultiplied, fp16 ==========
__global__ __launch_bounds__(256) void vtsplit_kernel(const float* __restrict__ V,
                                                      const float* __restrict__ gatek,
                                                      __half* __restrict__ th) {
    __shared__ float tile[32][33];
    int b  = blockIdx.z;
    int t0 = blockIdx.x * 32;
    int d0 = blockIdx.y * 32;
    int tx = threadIdx.x & 31;
    int ty = threadIdx.x >> 5;
    #pragma unroll
    for (int i = 0; i < 4; i++) {
        int tt = t0 + ty + i*8;
        tile[ty + i*8][tx] = V[((size_t)(b*TT + tt)) * DD + d0 + tx];
    }
    __syncthreads();
    int h = d0 >> 6;
    float gk = gatek[((size_t)(b*HH + h)) * TT + t0 + tx];
    #pragma unroll
    for (int i = 0; i < 4; i++) {
        int d = d0 + ty + i*8;
        int tt = t0 + tx;
        th[((size_t)(b*DD + d)) * TT + tt] = __float2half_rn(tile[tx][ty + i*8] * gk);
    }
}

// ================= mma.sync GEMM, 3-stage cp.async pipeline =================
// A hi (+ optional lo) fp16, B fp16.  Tile 128x128, BK=32.
#define PAD_K 40
#define ARR_ELEMS (128*PAD_K)
#define STAGE_BYTES (3*ARR_ELEMS*2)          // Ah, Al, Bh slots = 30720 B
#define GEMM_SMEM_BYTES (3*STAGE_BYTES)      // 92160 B

__device__ __forceinline__ void gemm_load_stage(uint32_t sm_u32, int stage,
        const __half* __restrict__ Ah, const __half* __restrict__ Al,
        const __half* __restrict__ Bh,
        int m0, int n0, int k0, int t) {
    uint32_t sbase = sm_u32 + (uint32_t)stage * STAGE_BYTES;
    #pragma unroll
    for (int o = 0; o < 2; o++) {
        int linear = t + o*256;
        int r  = linear >> 2;
        int c8 = linear & 3;
        uint32_t soff = (uint32_t)(r*(PAD_K*2) + c8*16);
        size_t goffA = (size_t)(m0 + r) * GK + k0 + c8*8;
        size_t goffB = (size_t)(n0 + r) * GK + k0 + c8*8;
        CP_ASYNC16(sbase +                 soff, Ah + goffA);
        if (Al) CP_ASYNC16(sbase + 1*ARR_ELEMS*2 + soff, Al + goffA);
        CP_ASYNC16(sbase + 2*ARR_ELEMS*2 + soff, Bh + goffB);
    }
}

__global__ __launch_bounds__(256) void mma_gemm(const __half* __restrict__ Ah,
                                                const __half* __restrict__ Al,
                                                const __half* __restrict__ Bh,
                                                float* __restrict__ C,
                                                const float* __restrict__ bias) {
    extern __shared__ __half smb[];
    uint32_t sm_u32 = smem_to_u32(smb);
    int t = threadIdx.x;
    int wid = t >> 5, lane = t & 31;
    int wm = wid & 1;
    int wn = wid >> 1;
    int g  = lane >> 2;
    int tq = lane & 3;

    int m0 = blockIdx.y * 128, n0 = blockIdx.x * 128;

    float acc[4][4][4];
    #pragma unroll
    for (int mi = 0; mi < 4; mi++)
        #pragma unroll
        for (int ni = 0; ni < 4; ni++)
            #pragma unroll
            for (int r = 0; r < 4; r++) acc[mi][ni][r] = 0.f;

    int a_rsel = lane & 15;
    int a_ksel = (lane >> 4) * 8;
    int b_row  = lane & 7;
    int b_msel = (lane >> 4);
    int b_ksel = ((lane >> 3) & 1) * 8;

    const int NIT = GK / 32;
    gemm_load_stage(sm_u32, 0, Ah, Al, Bh, m0, n0, 0, t);
    CP_COMMIT();
    gemm_load_stage(sm_u32, 1, Ah, Al, Bh, m0, n0, 32, t);
    CP_COMMIT();

    int stage = 0;
    for (int it = 0; it < NIT; it++) {
        CP_WAIT1();
        __syncthreads();
        if (it + 2 < NIT) {
            int ns = stage + 2; if (ns >= 3) ns -= 3;
            gemm_load_stage(sm_u32, ns, Ah, Al, Bh, m0, n0, (it+2)*32, t);
        }
        CP_COMMIT();   // always commit (empty groups at tail keep ordering)

        uint32_t S   = sm_u32 + (uint32_t)stage * STAGE_BYTES;
        uint32_t uAh = S;
        uint32_t uAl = S + 1*ARR_ELEMS*2;
        uint32_t uBh = S + 2*ARR_ELEMS*2;

        #pragma unroll
        for (int kk = 0; kk < 32; kk += 16) {
            uint32_t ah[4][4], al[4][4];
            #pragma unroll
            for (int mi = 0; mi < 4; mi++) {
                uint32_t off = (uint32_t)(((wm*64 + mi*16 + a_rsel) * PAD_K + kk + a_ksel) * 2);
                LDMX4(ah[mi][0], ah[mi][1], ah[mi][2], ah[mi][3], uAh + off);
                if (Al) LDMX4(al[mi][0], al[mi][1], al[mi][2], al[mi][3], uAl + off);
            }
            uint32_t bh[4][2];
            #pragma unroll
            for (int np = 0; np < 2; np++) {
                uint32_t off = (uint32_t)(((wn*32 + (np*2 + b_msel)*8 + b_row) * PAD_K + kk + b_ksel) * 2);
                uint32_t r0, r1, r2, r3;
                LDMX4(r0, r1, r2, r3, uBh + off);
                bh[np*2][0]=r0; bh[np*2][1]=r1; bh[np*2+1][0]=r2; bh[np*2+1][1]=r3;
            }
            #pragma unroll
            for (int ni = 0; ni < 4; ni++)
                #pragma unroll
                for (int mi = 0; mi < 4; mi++)
                    MMA16816(acc[mi][ni], ah[mi][0], ah[mi][1], ah[mi][2], ah[mi][3], bh[ni][0], bh[ni][1]);
            if (Al) {
                #pragma unroll
                for (int ni = 0; ni < 4; ni++)
                    #pragma unroll
                    for (int mi = 0; mi < 4; mi++)
                        MMA16816(acc[mi][ni], al[mi][0], al[mi][1], al[mi][2], al[mi][3], bh[ni][0], bh[ni][1]);
            }
        }
        if (++stage == 3) stage = 0;
    }

    #pragma unroll
    for (int mi = 0; mi < 4; mi++) {
        int row = m0 + wm*64 + mi*16 + g;
        #pragma unroll
        for (int ni = 0; ni < 4; ni++) {
            int col = n0 + wn*32 + ni*8 + tq*2;
            float b0 = 0.f, b1 = 0.f;
            if (bias) { b0 = bias[col]; b1 = bias[col+1]; }
            float2 v0 = { acc[mi][ni][0] + b0, acc[mi][ni][1] + b1 };
            float2 v1 = { acc[mi][ni][2] + b0, acc[mi][ni][3] + b1 };
            *(float2*)(C + (size_t)row * GN + col)       = v0;
            *(float2*)(C + (size_t)(row+8) * GN + col)   = v1;
        }
    }
}

// ================= l2-normalize + gate; emits fp16 (hi[/lo]) =================
__global__ __launch_bounds__(256) void norm_gate_kernel(const float* __restrict__ raw,
                                                        const float* __restrict__ g,
                                                        __half* __restrict__ oh,
                                                        __half* __restrict__ ol,
                                                        float* __restrict__ gate) {
    int task = blockIdx.x * 8 + (threadIdx.x >> 5);
    int lane = threadIdx.x & 31;
    int token = task >> 4;
    int h = task & 15;
    size_t base = (size_t)token * DD + h * HD;
    float2 v = ((const float2*)(raw + base))[lane];
    float sq = v.x*v.x + v.y*v.y;
    #pragma unroll
    for (int o = 16; o > 0; o >>= 1) sq += __shfl_xor_sync(0xffffffffu, sq, o);
    float nrm = sqrtf(sq);
    float inv = 1.0f / fmaxf(nrm, 1e-12f);
    float nx = v.x * inv, ny = v.y * inv;
    uint32_t hw, lw;
    split2(nx, ny, hw, lw);
    ((uint32_t*)(oh + base))[lane] = hw;
    if (ol) ((uint32_t*)(ol + base))[lane] = lw;
    float2 gv = ((const float2*)g)[lane];
    float gp = nx*gv.x + ny*gv.y;
    #pragma unroll
    for (int o = 16; o > 0; o >>= 1) gp += __shfl_xor_sync(0xffffffffu, gp, o);
    if (lane == 0) {
        int b = token / TT, t = token % TT;
        gate[((size_t)(b*HH + h)) * TT + t] = gp;
    }
}

// ================= attention: mma.sync fp16, 4-stage cp.async pipeline =================
#define SC 64
#define ATTN_STG 18432              // Kh (9216) + Vh (9216)
#define ATTN_SMEM (4*ATTN_STG)      // 73728

__device__ __forceinline__ void attn_load_stage(uint32_t sb, int stage,
        int b, int h, int s0, int t,
        const __half* __restrict__ Kh, const __half* __restrict__ Vh) {
    uint32_t base = sb + (uint32_t)stage * ATTN_STG;
    int row_lo = t >> 3;
    int c = t & 7;
    #pragma unroll
    for (int i = 0; i < 4; i++) {
        int arr = i >> 1;
        int row = ((i & 1) << 5) + row_lo;
        uint32_t dst = base + (uint32_t)(arr*9216 + row*144 + c*16);
        const __half* src = (arr == 0)
            ? Kh + ((size_t)(b*TT + s0 + row))*DD + h*64 + c*8
            : Vh + ((size_t)(b*DD + h*64 + row))*TT + s0 + c*8;
        CP_ASYNC16(dst, src);
    }
}

__global__ __launch_bounds__(256) void attn_mma_kernel(
        const __half* __restrict__ Qh, const __half* __restrict__ Ql,
        const __half* __restrict__ Kh, const __half* __restrict__ Vh,
        const float* __restrict__ gateq) {
    extern __shared__ char smc[];
    uint32_t sb = smem_to_u32(smc);
    int t = threadIdx.x;
    int w = t >> 5, lane = t & 31;
    int g = lane >> 2, tq = lane & 3;
    int bh = blockIdx.y;
    int b = bh >> 4, h = bh & 15;
    int t0 = blockIdx.x * 128;
    int trow = t0 + w*16 + g;

    int b_row  = lane & 7;
    int b_msel = (lane >> 4);
    int b_ksel = ((lane >> 3) & 1) * 8;

    uint32_t aqh[4][4], aql[4][4];
    {
        size_t r0 = ((size_t)(b*TT + trow))*DD + h*64;
        size_t r8 = r0 + 8*(size_t)DD;
        #pragma unroll
        for (int kq = 0; kq < 4; kq++) {
            int c = kq*16 + tq*2;
            aqh[kq][0] = *(const uint32_t*)(Qh + r0 + c);
            aqh[kq][1] = *(const uint32_t*)(Qh + r8 + c);
            aqh[kq][2] = *(const uint32_t*)(Qh + r0 + c + 8);
            aqh[kq][3] = *(const uint32_t*)(Qh + r8 + c + 8);
            aql[kq][0] = *(const uint32_t*)(Ql + r0 + c);
            aql[kq][1] = *(const uint32_t*)(Ql + r8 + c);
            aql[kq][2] = *(const uint32_t*)(Ql + r0 + c + 8);
            aql[kq][3] = *(const uint32_t*)(Ql + r8 + c + 8);
        }
    }
    float gq0 = gateq[(size_t)bh*TT + trow];
    float gq1 = gateq[(size_t)bh*TT + trow + 8];

    float cacc[8][4];
    #pragma unroll
    for (int di = 0; di < 8; di++)
        #pragma unroll
        for (int r = 0; r < 4; r++) cacc[di][r] = 0.f;

    const int NCH = TT / SC;
    attn_load_stage(sb, 0, b, h, 0,    t, Kh, Vh); CP_COMMIT();
    attn_load_stage(sb, 1, b, h, SC,   t, Kh, Vh); CP_COMMIT();
    attn_load_stage(sb, 2, b, h, 2*SC, t, Kh, Vh); CP_COMMIT();

    for (int ic = 0; ic < NCH; ic++) {
        CP_WAIT2();
        __syncthreads();
        if (ic + 3 < NCH)
            attn_load_stage(sb, (ic+3) & 3, b, h, (ic+3)*SC, t, Kh, Vh);
        CP_COMMIT();

        uint32_t stg = sb + (uint32_t)(ic & 3) * ATTN_STG;
        uint32_t uKh = stg;
        uint32_t uVh = stg + 9216;

        // ---- GEMM1: S = Q . K^T (Qh + Ql terms) ----
        float sacc[8][4];
        #pragma unroll
        for (int si = 0; si < 8; si++)
            #pragma unroll
            for (int r = 0; r < 4; r++) sacc[si][r] = 0.f;

        #pragma unroll
        for (int kk = 0; kk < 4; kk++) {
            uint32_t kfh[4][4];
            #pragma unroll
            for (int sp = 0; sp < 4; sp++) {
                uint32_t off = (uint32_t)(((sp*2 + b_msel)*8 + b_row)*144 + (kk*16 + b_ksel)*2);
                LDMX4(kfh[sp][0], kfh[sp][1], kfh[sp][2], kfh[sp][3], uKh + off);
            }
            #pragma unroll
            for (int sp = 0; sp < 4; sp++) {
                MMA16816(sacc[2*sp],   aqh[kk][0], aqh[kk][1], aqh[kk][2], aqh[kk][3], kfh[sp][0], kfh[sp][1]);
                MMA16816(sacc[2*sp+1], aqh[kk][0], aqh[kk][1], aqh[kk][2], aqh[kk][3], kfh[sp][2], kfh[sp][3]);
            }
            #pragma unroll
            for (int sp = 0; sp < 4; sp++) {
                MMA16816(sacc[2*sp],   aql[kk][0], aql[kk][1], aql[kk][2], aql[kk][3], kfh[sp][0], kfh[sp][1]);
                MMA16816(sacc[2*sp+1], aql[kk][0], aql[kk][1], aql[kk][2], aql[kk][3], kfh[sp][2], kfh[sp][3]);
            }
        }

        // ---- modulation: sigmoid, single fp16 pack ----
        uint32_t mh[4][4];
        #pragma unroll
        for (int j = 0; j < 4; j++) {
            #pragma unroll
            for (int half = 0; half < 2; half++) {
                int si = 2*j + half;
                float z00 = (sacc[si][0] - THRESH_C) * SHARP_C;
                float z01 = (sacc[si][1] - THRESH_C) * SHARP_C;
                float z10 = (sacc[si][2] - THRESH_C) * SHARP_C;
                float z11 = (sacc[si][3] - THRESH_C) * SHARP_C;
                float m00 = __fdividef(1.f, 1.f + __expf(-z00));
                float m01 = __fdividef(1.f, 1.f + __expf(-z01));
                float m10 = __fdividef(1.f, 1.f + __expf(-z10));
                float m11 = __fdividef(1.f, 1.f + __expf(-z11));
                mh[j][half*2 + 0] = packh2(m00, m01);
                mh[j][half*2 + 1] = packh2(m10, m11);
            }
        }

        // ---- GEMM2: C += M . (gk*V), single term ----
        #pragma unroll
        for (int j = 0; j < 4; j++) {
            uint32_t vfh[4][4];
            #pragma unroll
            for (int dp = 0; dp < 4; dp++) {
                uint32_t off = (uint32_t)(((dp*2 + b_msel)*8 + b_row)*144 + (j*16 + b_ksel)*2);
                LDMX4(vfh[dp][0], vfh[dp][1], vfh[dp][2], vfh[dp][3], uVh + off);
            }
            #pragma unroll
            for (int dp = 0; dp < 4; dp++) {
                MMA16816(cacc[2*dp],   mh[j][0], mh[j][1], mh[j][2], mh[j][3], vfh[dp][0], vfh[dp][1]);
                MMA16816(cacc[2*dp+1], mh[j][0], mh[j][1], mh[j][2], mh[j][3], vfh[dp][2], vfh[dp][3]);
            }
        }
    }

    // epilogue: apply gq, split to fp16 hi/lo collapse
    size_t obase = ((size_t)(b*TT + trow))*DD + h*64;
    #pragma unroll
    for (int di = 0; di < 8; di++) {
        int col = di*8 + tq*2;
        float c00 = cacc[di][0]*gq0, c01 = cacc[di][1]*gq0;
        float c10 = cacc[di][2]*gq1, c11 = cacc[di][3]*gq1;
        uint32_t h0, l0, h1, l1;
        split2(c00, c01, h0, l0);
        split2(c10, c11, h1, l1);
        *(uint32_t*)(g_ch + obase + col) = h0;
        *(uint32_t*)(g_cl + obase + col) = l0;
        *(uint32_t*)(g_ch + obase + 8*(size_t)DD + col) = h1;
        *(uint32_t*)(g_cl + obase + 8*(size_t)DD + col) = l1;
    }
}

// ================= launch =================
extern "C" void kernel_launch(void* const* d_in, const int* in_sizes, int n_in,
                              void* d_out, int out_size) {
    const float* x    = (const float*)d_in[0];
    const float* Wq   = (const float*)d_in[1];
    const float* Wk   = (const float*)d_in[2];
    const float* Wv   = (const float*)d_in[3];
    const float* gq   = (const float*)d_in[4];
    const float* gk   = (const float*)d_in[5];
    const float* Wo   = (const float*)d_in[6];
    const float* bo   = (const float*)d_in[7];
    const float* ln_w = (const float*)d_in[8];
    const float* ln_b = (const float*)d_in[9];
    float* out = (float*)d_out;

    float *p_qraw, *p_kraw, *p_v, *p_gq, *p_gk;
    cudaGetSymbolAddress((void**)&p_qraw, g_qraw);
    cudaGetSymbolAddress((void**)&p_kraw, g_kraw);
    cudaGetSymbolAddress((void**)&p_v,    g_v);
    cudaGetSymbolAddress((void**)&p_gq,   g_gateq);
    cudaGetSymbolAddress((void**)&p_gk,   g_gatek);

    __half *p_xh,*p_xnh,*p_xnl,*p_ch,*p_cl;
    __half *p_wqh,*p_wkh,*p_wvh,*p_woh;
    __half *p_qbh,*p_qbl,*p_kbh,*p_vth;
    cudaGetSymbolAddress((void**)&p_xh,  g_xh);
    cudaGetSymbolAddress((void**)&p_xnh, g_xnh);
    cudaGetSymbolAddress((void**)&p_xnl, g_xnl);
    cudaGetSymbolAddress((void**)&p_ch,  g_ch);
    cudaGetSymbolAddress((void**)&p_cl,  g_cl);
    cudaGetSymbolAddress((void**)&p_wqh, g_wqh);
    cudaGetSymbolAddress((void**)&p_wkh, g_wkh);
    cudaGetSymbolAddress((void**)&p_wvh, g_wvh);
    cudaGetSymbolAddress((void**)&p_woh, g_woh);
    cudaGetSymbolAddress((void**)&p_qbh, g_qbh);
    cudaGetSymbolAddress((void**)&p_qbl, g_qbl);
    cudaGetSymbolAddress((void**)&p_kbh, g_kbh);
    cudaGetSymbolAddress((void**)&p_vth, g_vth);

    cudaFuncSetAttribute(mma_gemm, cudaFuncAttributeMaxDynamicSharedMemorySize, GEMM_SMEM_BYTES);
    cudaFuncSetAttribute(attn_mma_kernel, cudaFuncAttributeMaxDynamicSharedMemorySize, ATTN_SMEM);

    // 1. LayerNorm + splits
    ln_kernel<<<NTOK, 256>>>(x, ln_w, ln_b);

    // 2. weight transpose (fp16), z-indexed
    tsplit4_kernel<<<dim3(DD/32, DD/32, 4), 256>>>(Wq, Wk, Wv, Wo);

    // 3. QKV projections (Q/K: 2-term A; V: 1-term A)
    dim3 ggrid(GN/128, GM/128);
    mma_gemm<<<ggrid, 256, GEMM_SMEM_BYTES>>>(p_xnh, p_xnl, p_wqh, p_qraw, nullptr);
    mma_gemm<<<ggrid, 256, GEMM_SMEM_BYTES>>>(p_xnh, p_xnl, p_wkh, p_kraw, nullptr);
    mma_gemm<<<ggrid, 256, GEMM_SMEM_BYTES>>>(p_xh,  nullptr, p_wvh, p_v,  nullptr);

    // 4. normalize + gates; V transpose
    norm_gate_kernel<<<(NTOK*HH)/8, 256>>>(p_qraw, gq, p_qbh, p_qbl, p_gq);
    norm_gate_kernel<<<(NTOK*HH)/8, 256>>>(p_kraw, gk, p_kbh, nullptr, p_gk);
    vtsplit_kernel<<<dim3(TT/32, DD/32, BB), 256>>>(p_v, p_gk, p_vth);

    // 5. attention
    attn_mma_kernel<<<dim3(TT/128, BB*HH), 256, ATTN_SMEM>>>(
        p_qbh, p_qbl, p_kbh, p_vth, p_gq);

    // 6. output projection (2-term A)
    mma_gemm<<<ggrid, 256, GEMM_SMEM_BYTES>>>(p_ch, p_cl, p_woh, out, bo);
}

// round 10
// speedup vs baseline: 5.0711x; 1.1349x over previous
#include <cuda_runtime.h>
#include <cuda_fp16.h>
#include <cstdint>
#include <math.h>

#define BB 2
#define TT 2048
#define DD 1024
#define HH 16
#define HD 64
#define NTOK (BB*TT)

#define GM 4096
#define GN 1024
#define GK 1024

#define THRESH_C 0.29514f
#define SHARP_C  15.0f

// ================= low-level helpers =================
#define CP_ASYNC16(dst_u32, src_ptr) \
    asm volatile("cp.async.cg.shared.global [%0], [%1], 16;" \
        :: "r"(dst_u32), "l"(src_ptr) : "memory")
#define CP_COMMIT() asm volatile("cp.async.commit_group;" ::: "memory")
#define CP_WAIT1()  asm volatile("cp.async.wait_group 1;" ::: "memory")
#define CP_WAIT2()  asm volatile("cp.async.wait_group 2;" ::: "memory")

__device__ __forceinline__ uint32_t smem_to_u32(const void* smem_ptr) {
    uint32_t addr;
    asm("{ .reg .u64 tmp; cvta.to.shared.u64 tmp, %1; cvt.u32.u64 %0, tmp; }"
        : "=r"(addr) : "l"(smem_ptr));
    return addr;
}

#define MMA16816(d, a0, a1, a2, a3, b0, b1) \
    asm volatile("mma.sync.aligned.m16n8k16.row.col.f32.f16.f16.f32 " \
        "{%0,%1,%2,%3}, {%4,%5,%6,%7}, {%8,%9}, {%0,%1,%2,%3};" \
        : "+f"((d)[0]), "+f"((d)[1]), "+f"((d)[2]), "+f"((d)[3]) \
        : "r"(a0), "r"(a1), "r"(a2), "r"(a3), "r"(b0), "r"(b1))

#define LDMX4(r0, r1, r2, r3, addr) \
    asm volatile("ldmatrix.sync.aligned.m8n8.x4.shared.b16 {%0,%1,%2,%3}, [%4];" \
        : "=r"(r0), "=r"(r1), "=r"(r2), "=r"(r3) : "r"(addr))

// split two fp32 into fp16 hi + fp16 residual lo, packed as half2 words
__device__ __forceinline__ void split2(float x, float y, uint32_t& hw, uint32_t& lw) {
    __half hx = __float2half_rn(x), hy = __float2half_rn(y);
    __half lx = __float2half_rn(x - __half2float(hx));
    __half ly = __float2half_rn(y - __half2float(hy));
    __half2 hp = __halves2half2(hx, hy);
    __half2 lp = __halves2half2(lx, ly);
    hw = *(uint32_t*)&hp;
    lw = *(uint32_t*)&lp;
}
__device__ __forceinline__ uint32_t packh2(float x, float y) {
    __half2 hp = __floats2half2_rn(x, y);
    return *(uint32_t*)&hp;
}

// ================= scratch =================
__device__ float g_qraw[NTOK*DD];
__device__ float g_kraw[NTOK*DD];
__device__ float g_v[NTOK*DD];
__device__ float g_gateq[BB*HH*TT];
__device__ float g_gatek[BB*HH*TT];

__device__ __half g_xh[NTOK*DD];                     // raw x fp16 (A of V-proj)
__device__ __half g_xnh[NTOK*DD];                    // layernormed x fp16 (A of Q/K-proj)
__device__ __half g_ch[NTOK*DD],  g_cl[NTOK*DD];     // collapse hi/lo (A of out-proj, 2-term)
__device__ __half g_wqh[DD*DD], g_wkh[DD*DD], g_wvh[DD*DD], g_woh[DD*DD];  // B fp16
__device__ __half g_qbh[NTOK*DD], g_qbl[NTOK*DD];    // normalized q hi/lo (GEMM1 A, 2-term)
__device__ __half g_kbh[NTOK*DD];                     // normalized k (B side, fp16)
__device__ __half g_vth[BB*DD*TT];                    // gk*V transposed (B side)

// ================= LayerNorm fused with fp16 conversions =================
__global__ __launch_bounds__(256) void ln_kernel(const float* __restrict__ x,
                                                 const float* __restrict__ w,
                                                 const float* __restrict__ b) {
    int row = blockIdx.x;
    int tid = threadIdx.x;
    const float4* xr = (const float4*)(x + (size_t)row * DD);
    float4 v = xr[tid];
    float s  = v.x + v.y + v.z + v.w;
    float sq = v.x*v.x + v.y*v.y + v.z*v.z + v.w*v.w;
    #pragma unroll
    for (int o = 16; o > 0; o >>= 1) {
        s  += __shfl_xor_sync(0xffffffffu, s,  o);
        sq += __shfl_xor_sync(0xffffffffu, sq, o);
    }
    __shared__ float ss[8], ssq[8];
    int wid = tid >> 5, lid = tid & 31;
    if (lid == 0) { ss[wid] = s; ssq[wid] = sq; }
    __syncthreads();
    float ts = 0.f, tsq = 0.f;
    #pragma unroll
    for (int i = 0; i < 8; i++) { ts += ss[i]; tsq += ssq[i]; }
    float mu  = ts * (1.0f/DD);
    float var = tsq * (1.0f/DD) - mu*mu;
    float inv = rsqrtf(var + 1e-5f);
    float4 wv = ((const float4*)w)[tid];
    float4 bv = ((const float4*)b)[tid];
    float4 o;
    o.x = (v.x - mu) * inv * wv.x + bv.x;
    o.y = (v.y - mu) * inv * wv.y + bv.y;
    o.z = (v.z - mu) * inv * wv.z + bv.z;
    o.w = (v.w - mu) * inv * wv.w + bv.w;

    int i4 = row * (DD/4) + tid;
    {
        uint2 hw = { packh2(v.x, v.y), packh2(v.z, v.w) };
        ((uint2*)g_xh)[i4] = hw;
    }
    {
        uint2 hw = { packh2(o.x, o.y), packh2(o.z, o.w) };
        ((uint2*)g_xnh)[i4] = hw;
    }
}

// ===== all 4 weights: W[K,N] -> Wt[N,K] transpose, fp16 (z-indexed) =====
__global__ __launch_bounds__(256) void tsplit4_kernel(const float* __restrict__ W0,
                                                      const float* __restrict__ W1,
                                                      const float* __restrict__ W2,
                                                      const float* __restrict__ W3) {
    __shared__ float tile[32][33];
    const float* W;
    __half* th;
    switch (blockIdx.z) {
        case 0: W = W0; th = g_wqh; break;
        case 1: W = W1; th = g_wkh; break;
        case 2: W = W2; th = g_wvh; break;
        default: W = W3; th = g_woh; break;
    }
    int bx = blockIdx.x * 32;
    int by = blockIdx.y * 32;
    int tx = threadIdx.x & 31;
    int ty = threadIdx.x >> 5;
    #pragma unroll
    for (int i = 0; i < 4; i++) {
        int k = by + ty + i*8;
        tile[ty + i*8][tx] = W[(size_t)k * DD + bx + tx];
    }
    __syncthreads();
    #pragma unroll
    for (int i = 0; i < 4; i++) {
        int n = bx + ty + i*8;
        int k = by + tx;
        th[(size_t)n * DD + k] = __float2half_rn(tile[tx][ty + i*8]);
    }
}

// ========== V[b][t][d] -> Vt[b*DD+d][t] transpose, gate_k premultiplied, fp16 ==========
__global__ __launch_bounds__(256) void vtsplit_kernel(const float* __restrict__ V,
                                                      const float* __restrict__ gatek,
                                                      __half* __restrict__ th) {
    __shared__ float tile[32][33];
    int b  = blockIdx.z;
    int t0 = blockIdx.x * 32;
    int d0 = blockIdx.y * 32;
    int tx = threadIdx.x & 31;
    int ty = threadIdx.x >> 5;
    #pragma unroll
    for (int i = 0; i < 4; i++) {
        int tt = t0 + ty + i*8;
        tile[ty + i*8][tx] = V[((size_t)(b*TT + tt)) * DD + d0 + tx];
    }
    __syncthreads();
    int h = d0 >> 6;
    float gk = gatek[((size_t)(b*HH + h)) * TT + t0 + tx];
    #pragma unroll
    for (int i = 0; i < 4; i++) {
        int d = d0 + ty + i*8;
        int tt = t0 + tx;
        th[((size_t)(b*DD + d)) * TT + tt] = __float2half_rn(tile[tx][ty + i*8] * gk);
    }
}

// ================= mma.sync GEMM, 3-stage cp.async pipeline =================
// A hi (+ optional lo) fp16, B fp16.  Tile 128x128, BK=32.
#define PAD_K 40
#define ARR_ELEMS (128*PAD_K)
#define STAGE_BYTES (3*ARR_ELEMS*2)          // Ah, Al, Bh slots = 30720 B
#define GEMM_SMEM_BYTES (3*STAGE_BYTES)      // 92160 B

__device__ __forceinline__ void gemm_load_stage(uint32_t sm_u32, int stage,
        const __half* __restrict__ Ah, const __half* __restrict__ Al,
        const __half* __restrict__ Bh,
        int m0, int n0, int k0, int t) {
    uint32_t sbase = sm_u32 + (uint32_t)stage * STAGE_BYTES;
    #pragma unroll
    for (int o = 0; o < 2; o++) {
        int linear = t + o*256;
        int r  = linear >> 2;
        int c8 = linear & 3;
        uint32_t soff = (uint32_t)(r*(PAD_K*2) + c8*16);
        size_t goffA = (size_t)(m0 + r) * GK + k0 + c8*8;
        size_t goffB = (size_t)(n0 + r) * GK + k0 + c8*8;
        CP_ASYNC16(sbase +                 soff, Ah + goffA);
        if (Al) CP_ASYNC16(sbase + 1*ARR_ELEMS*2 + soff, Al + goffA);
        CP_ASYNC16(sbase + 2*ARR_ELEMS*2 + soff, Bh + goffB);
    }
}

__global__ __launch_bounds__(256) void mma_gemm(const __half* __restrict__ Ah,
                                                const __half* __restrict__ Al,
                                                const __half* __restrict__ Bh,
                                                float* __restrict__ C,
                                                const float* __restrict__ bias) {
    extern __shared__ __half smb[];
    uint32_t sm_u32 = smem_to_u32(smb);
    int t = threadIdx.x;
    int wid = t >> 5, lane = t & 31;
    int wm = wid & 1;
    int wn = wid >> 1;
    int g  = lane >> 2;
    int tq = lane & 3;

    int m0 = blockIdx.y * 128, n0 = blockIdx.x * 128;

    float acc[4][4][4];
    #pragma unroll
    for (int mi = 0; mi < 4; mi++)
        #pragma unroll
        for (int ni = 0; ni < 4; ni++)
            #pragma unroll
            for (int r = 0; r < 4; r++) acc[mi][ni][r] = 0.f;

    int a_rsel = lane & 15;
    int a_ksel = (lane >> 4) * 8;
    int b_row  = lane & 7;
    int b_msel = (lane >> 4);
    int b_ksel = ((lane >> 3) & 1) * 8;

    const int NIT = GK / 32;
    gemm_load_stage(sm_u32, 0, Ah, Al, Bh, m0, n0, 0, t);
    CP_COMMIT();
    gemm_load_stage(sm_u32, 1, Ah, Al, Bh, m0, n0, 32, t);
    CP_COMMIT();

    int stage = 0;
    for (int it = 0; it < NIT; it++) {
        CP_WAIT1();
        __syncthreads();
        if (it + 2 < NIT) {
            int ns = stage + 2; if (ns >= 3) ns -= 3;
            gemm_load_stage(sm_u32, ns, Ah, Al, Bh, m0, n0, (it+2)*32, t);
        }
        CP_COMMIT();   // always commit (empty groups at tail keep ordering)

        uint32_t S   = sm_u32 + (uint32_t)stage * STAGE_BYTES;
        uint32_t uAh = S;
        uint32_t uAl = S + 1*ARR_ELEMS*2;
        uint32_t uBh = S + 2*ARR_ELEMS*2;

        #pragma unroll
        for (int kk = 0; kk < 32; kk += 16) {
            uint32_t ah[4][4], al[4][4];
            #pragma unroll
            for (int mi = 0; mi < 4; mi++) {
                uint32_t off = (uint32_t)(((wm*64 + mi*16 + a_rsel) * PAD_K + kk + a_ksel) * 2);
                LDMX4(ah[mi][0], ah[mi][1], ah[mi][2], ah[mi][3], uAh + off);
                if (Al) LDMX4(al[mi][0], al[mi][1], al[mi][2], al[mi][3], uAl + off);
            }
            uint32_t bh[4][2];
            #pragma unroll
            for (int np = 0; np < 2; np++) {
                uint32_t off = (uint32_t)(((wn*32 + (np*2 + b_msel)*8 + b_row) * PAD_K + kk + b_ksel) * 2);
                uint32_t r0, r1, r2, r3;
                LDMX4(r0, r1, r2, r3, uBh + off);
                bh[np*2][0]=r0; bh[np*2][1]=r1; bh[np*2+1][0]=r2; bh[np*2+1][1]=r3;
            }
            #pragma unroll
            for (int ni = 0; ni < 4; ni++)
                #pragma unroll
                for (int mi = 0; mi < 4; mi++)
                    MMA16816(acc[mi][ni], ah[mi][0], ah[mi][1], ah[mi][2], ah[mi][3], bh[ni][0], bh[ni][1]);
            if (Al) {
                #pragma unroll
                for (int ni = 0; ni < 4; ni++)
                    #pragma unroll
                    for (int mi = 0; mi < 4; mi++)
                        MMA16816(acc[mi][ni], al[mi][0], al[mi][1], al[mi][2], al[mi][3], bh[ni][0], bh[ni][1]);
            }
        }
        if (++stage == 3) stage = 0;
    }

    #pragma unroll
    for (int mi = 0; mi < 4; mi++) {
        int row = m0 + wm*64 + mi*16 + g;
        #pragma unroll
        for (int ni = 0; ni < 4; ni++) {
            int col = n0 + wn*32 + ni*8 + tq*2;
            float b0 = 0.f, b1 = 0.f;
            if (bias) { b0 = bias[col]; b1 = bias[col+1]; }
            float2 v0 = { acc[mi][ni][0] + b0, acc[mi][ni][1] + b1 };
            float2 v1 = { acc[mi][ni][2] + b0, acc[mi][ni][3] + b1 };
            *(float2*)(C + (size_t)row * GN + col)       = v0;
            *(float2*)(C + (size_t)(row+8) * GN + col)   = v1;
        }
    }
}

// ======== l2-normalize + gate for BOTH q and k (y-indexed); emits fp16 ========
__global__ __launch_bounds__(256) void norm_gate2_kernel(const float* __restrict__ qraw,
                                                         const float* __restrict__ kraw,
                                                         const float* __restrict__ gqv,
                                                         const float* __restrict__ gkv) {
    bool isq = (blockIdx.y == 0);
    const float* raw = isq ? qraw : kraw;
    const float* g   = isq ? gqv : gkv;
    __half* oh       = isq ? g_qbh : g_kbh;
    __half* ol       = isq ? g_qbl : (__half*)0;
    float* gate      = isq ? g_gateq : g_gatek;

    int task = blockIdx.x * 8 + (threadIdx.x >> 5);
    int lane = threadIdx.x & 31;
    int token = task >> 4;
    int h = task & 15;
    size_t base = (size_t)token * DD + h * HD;
    float2 v = ((const float2*)(raw + base))[lane];
    float sq = v.x*v.x + v.y*v.y;
    #pragma unroll
    for (int o = 16; o > 0; o >>= 1) sq += __shfl_xor_sync(0xffffffffu, sq, o);
    float nrm = sqrtf(sq);
    float inv = 1.0f / fmaxf(nrm, 1e-12f);
    float nx = v.x * inv, ny = v.y * inv;
    uint32_t hw, lw;
    split2(nx, ny, hw, lw);
    ((uint32_t*)(oh + base))[lane] = hw;
    if (ol) ((uint32_t*)(ol + base))[lane] = lw;
    float2 gv = ((const float2*)g)[lane];
    float gp = nx*gv.x + ny*gv.y;
    #pragma unroll
    for (int o = 16; o > 0; o >>= 1) gp += __shfl_xor_sync(0xffffffffu, gp, o);
    if (lane == 0) {
        int b = token / TT, t = token % TT;
        gate[((size_t)(b*HH + h)) * TT + t] = gp;
    }
}

// ================= attention: mma.sync fp16, 4-stage cp.async pipeline =================
#define SC 64
#define ATTN_STG 18432              // Kh (9216) + Vh (9216)
#define ATTN_SMEM (4*ATTN_STG)      // 73728

__device__ __forceinline__ void attn_load_stage(uint32_t sb, int stage,
        int b, int h, int s0, int t,
        const __half* __restrict__ Kh, const __half* __restrict__ Vh) {
    uint32_t base = sb + (uint32_t)stage * ATTN_STG;
    int row_lo = t >> 3;
    int c = t & 7;
    #pragma unroll
    for (int i = 0; i < 4; i++) {
        int arr = i >> 1;
        int row = ((i & 1) << 5) + row_lo;
        uint32_t dst = base + (uint32_t)(arr*9216 + row*144 + c*16);
        const __half* src = (arr == 0)
            ? Kh + ((size_t)(b*TT + s0 + row))*DD + h*64 + c*8
            : Vh + ((size_t)(b*DD + h*64 + row))*TT + s0 + c*8;
        CP_ASYNC16(dst, src);
    }
}

__global__ __launch_bounds__(256) void attn_mma_kernel(
        const __half* __restrict__ Qh, const __half* __restrict__ Ql,
        const __half* __restrict__ Kh, const __half* __restrict__ Vh,
        const float* __restrict__ gateq) {
    extern __shared__ char smc[];
    uint32_t sb = smem_to_u32(smc);
    int t = threadIdx.x;
    int w = t >> 5, lane = t & 31;
    int g = lane >> 2, tq = lane & 3;
    int bh = blockIdx.y;
    int b = bh >> 4, h = bh & 15;
    int t0 = blockIdx.x * 128;
    int trow = t0 + w*16 + g;

    int b_row  = lane & 7;
    int b_msel = (lane >> 4);
    int b_ksel = ((lane >> 3) & 1) * 8;

    uint32_t aqh[4][4], aql[4][4];
    {
        size_t r0 = ((size_t)(b*TT + trow))*DD + h*64;
        size_t r8 = r0 + 8*(size_t)DD;
        #pragma unroll
        for (int kq = 0; kq < 4; kq++) {
            int c = kq*16 + tq*2;
            aqh[kq][0] = *(const uint32_t*)(Qh + r0 + c);
            aqh[kq][1] = *(const uint32_t*)(Qh + r8 + c);
            aqh[kq][2] = *(const uint32_t*)(Qh + r0 + c + 8);
            aqh[kq][3] = *(const uint32_t*)(Qh + r8 + c + 8);
            aql[kq][0] = *(const uint32_t*)(Ql + r0 + c);
            aql[kq][1] = *(const uint32_t*)(Ql + r8 + c);
            aql[kq][2] = *(const uint32_t*)(Ql + r0 + c + 8);
            aql[kq][3] = *(const uint32_t*)(Ql + r8 + c + 8);
        }
    }
    float gq0 = gateq[(size_t)bh*TT + trow];
    float gq1 = gateq[(size_t)bh*TT + trow + 8];

    float cacc[8][4];
    #pragma unroll
    for (int di = 0; di < 8; di++)
        #pragma unroll
        for (int r = 0; r < 4; r++) cacc[di][r] = 0.f;

    const int NCH = TT / SC;
    attn_load_stage(sb, 0, b, h, 0,    t, Kh, Vh); CP_COMMIT();
    attn_load_stage(sb, 1, b, h, SC,   t, Kh, Vh); CP_COMMIT();
    attn_load_stage(sb, 2, b, h, 2*SC, t, Kh, Vh); CP_COMMIT();

    for (int ic = 0; ic < NCH; ic++) {
        CP_WAIT2();
        __syncthreads();
        if (ic + 3 < NCH)
            attn_load_stage(sb, (ic+3) & 3, b, h, (ic+3)*SC, t, Kh, Vh);
        CP_COMMIT();

        uint32_t stg = sb + (uint32_t)(ic & 3) * ATTN_STG;
        uint32_t uKh = stg;
        uint32_t uVh = stg + 9216;

        // ---- GEMM1: S = Q . K^T (Qh + Ql terms) ----
        float sacc[8][4];
        #pragma unroll
        for (int si = 0; si < 8; si++)
            #pragma unroll
            for (int r = 0; r < 4; r++) sacc[si][r] = 0.f;

        #pragma unroll
        for (int kk = 0; kk < 4; kk++) {
            uint32_t kfh[4][4];
            #pragma unroll
            for (int sp = 0; sp < 4; sp++) {
                uint32_t off = (uint32_t)(((sp*2 + b_msel)*8 + b_row)*144 + (kk*16 + b_ksel)*2);
                LDMX4(kfh[sp][0], kfh[sp][1], kfh[sp][2], kfh[sp][3], uKh + off);
            }
            #pragma unroll
            for (int sp = 0; sp < 4; sp++) {
                MMA16816(sacc[2*sp],   aqh[kk][0], aqh[kk][1], aqh[kk][2], aqh[kk][3], kfh[sp][0], kfh[sp][1]);
                MMA16816(sacc[2*sp+1], aqh[kk][0], aqh[kk][1], aqh[kk][2], aqh[kk][3], kfh[sp][2], kfh[sp][3]);
            }
            #pragma unroll
            for (int sp = 0; sp < 4; sp++) {
                MMA16816(sacc[2*sp],   aql[kk][0], aql[kk][1], aql[kk][2], aql[kk][3], kfh[sp][0], kfh[sp][1]);
                MMA16816(sacc[2*sp+1], aql[kk][0], aql[kk][1], aql[kk][2], aql[kk][3], kfh[sp][2], kfh[sp][3]);
            }
        }

        // ---- modulation: sigmoid, single fp16 pack ----
        uint32_t mh[4][4];
        #pragma unroll
        for (int j = 0; j < 4; j++) {
            #pragma unroll
            for (int half = 0; half < 2; half++) {
                int si = 2*j + half;
                float z00 = (sacc[si][0] - THRESH_C) * SHARP_C;
                float z01 = (sacc[si][1] - THRESH_C) * SHARP_C;
                float z10 = (sacc[si][2] - THRESH_C) * SHARP_C;
                float z11 = (sacc[si][3] - THRESH_C) * SHARP_C;
                float m00 = __fdividef(1.f, 1.f + __expf(-z00));
                float m01 = __fdividef(1.f, 1.f + __expf(-z01));
                float m10 = __fdividef(1.f, 1.f + __expf(-z10));
                float m11 = __fdividef(1.f, 1.f + __expf(-z11));
                mh[j][half*2 + 0] = packh2(m00, m01);
                mh[j][half*2 + 1] = packh2(m10, m11);
            }
        }

        // ---- GEMM2: C += M . (gk*V), single term ----
        #pragma unroll
        for (int j = 0; j < 4; j++) {
            uint32_t vfh[4][4];
            #pragma unroll
            for (int dp = 0; dp < 4; dp++) {
                uint32_t off = (uint32_t)(((dp*2 + b_msel)*8 + b_row)*144 + (j*16 + b_ksel)*2);
                LDMX4(vfh[dp][0], vfh[dp][1], vfh[dp][2], vfh[dp][3], uVh + off);
            }
            #pragma unroll
            for (int dp = 0; dp < 4; dp++) {
                MMA16816(cacc[2*dp],   mh[j][0], mh[j][1], mh[j][2], mh[j][3], vfh[dp][0], vfh[dp][1]);
                MMA16816(cacc[2*dp+1], mh[j][0], mh[j][1], mh[j][2], mh[j][3], vfh[dp][2], vfh[dp][3]);
            }
        }
    }

    // epilogue: apply gq, split to fp16 hi/lo collapse (out-proj stays 2-term)
    size_t obase = ((size_t)(b*TT + trow))*DD + h*64;
    #pragma unroll
    for (int di = 0; di < 8; di++) {
        int col = di*8 + tq*2;
        float c00 = cacc[di][0]*gq0, c01 = cacc[di][1]*gq0;
        float c10 = cacc[di][2]*gq1, c11 = cacc[di][3]*gq1;
        uint32_t h0, l0, h1, l1;
        split2(c00, c01, h0, l0);
        split2(c10, c11, h1, l1);
        *(uint32_t*)(g_ch + obase + col) = h0;
        *(uint32_t*)(g_cl + obase + col) = l0;
        *(uint32_t*)(g_ch + obase + 8*(size_t)DD + col) = h1;
        *(uint32_t*)(g_cl + obase + 8*(size_t)DD + col) = l1;
    }
}

// ================= launch =================
extern "C" void kernel_launch(void* const* d_in, const int* in_sizes, int n_in,
                              void* d_out, int out_size) {
    const float* x    = (const float*)d_in[0];
    const float* Wq   = (const float*)d_in[1];
    const float* Wk   = (const float*)d_in[2];
    const float* Wv   = (const float*)d_in[3];
    const float* gq   = (const float*)d_in[4];
    const float* gk   = (const float*)d_in[5];
    const float* Wo   = (const float*)d_in[6];
    const float* bo   = (const float*)d_in[7];
    const float* ln_w = (const float*)d_in[8];
    const float* ln_b = (const float*)d_in[9];
    float* out = (float*)d_out;

    float *p_qraw, *p_kraw, *p_v, *p_gq, *p_gk;
    cudaGetSymbolAddress((void**)&p_qraw, g_qraw);
    cudaGetSymbolAddress((void**)&p_kraw, g_kraw);
    cudaGetSymbolAddress((void**)&p_v,    g_v);
    cudaGetSymbolAddress((void**)&p_gq,   g_gateq);
    cudaGetSymbolAddress((void**)&p_gk,   g_gatek);

    __half *p_xh,*p_xnh,*p_ch,*p_cl;
    __half *p_wqh,*p_wkh,*p_wvh,*p_woh;
    __half *p_qbh,*p_qbl,*p_kbh,*p_vth;
    cudaGetSymbolAddress((void**)&p_xh,  g_xh);
    cudaGetSymbolAddress((void**)&p_xnh, g_xnh);
    cudaGetSymbolAddress((void**)&p_ch,  g_ch);
    cudaGetSymbolAddress((void**)&p_cl,  g_cl);
    cudaGetSymbolAddress((void**)&p_wqh, g_wqh);
    cudaGetSymbolAddress((void**)&p_wkh, g_wkh);
    cudaGetSymbolAddress((void**)&p_wvh, g_wvh);
    cudaGetSymbolAddress((void**)&p_woh, g_woh);
    cudaGetSymbolAddress((void**)&p_qbh, g_qbh);
    cudaGetSymbolAddress((void**)&p_qbl, g_qbl);
    cudaGetSymbolAddress((void**)&p_kbh, g_kbh);
    cudaGetSymbolAddress((void**)&p_vth, g_vth);

    cudaFuncSetAttribute(mma_gemm, cudaFuncAttributeMaxDynamicSharedMemorySize, GEMM_SMEM_BYTES);
    cudaFuncSetAttribute(attn_mma_kernel, cudaFuncAttributeMaxDynamicSharedMemorySize, ATTN_SMEM);

    // 1. LayerNorm + fp16 conversions
    ln_kernel<<<NTOK, 256>>>(x, ln_w, ln_b);

    // 2. weight transpose (fp16), z-indexed
    tsplit4_kernel<<<dim3(DD/32, DD/32, 4), 256>>>(Wq, Wk, Wv, Wo);

    // 3. QKV projections (all 1-term A)
    dim3 ggrid(GN/128, GM/128);
    mma_gemm<<<ggrid, 256, GEMM_SMEM_BYTES>>>(p_xnh, nullptr, p_wqh, p_qraw, nullptr);
    mma_gemm<<<ggrid, 256, GEMM_SMEM_BYTES>>>(p_xnh, nullptr, p_wkh, p_kraw, nullptr);
    mma_gemm<<<ggrid, 256, GEMM_SMEM_BYTES>>>(p_xh,  nullptr, p_wvh, p_v,    nullptr);

    // 4. normalize + gates (q & k fused); V transpose
    norm_gate2_kernel<<<dim3((NTOK*HH)/8, 2), 256>>>(p_qraw, p_kraw, gq, gk);
    vtsplit_kernel<<<dim3(TT/32, DD/32, BB), 256>>>(p_v, p_gk, p_vth);

    // 5. attention (GEMM1 2-term, GEMM2 1-term)
    attn_mma_kernel<<<dim3(TT/128, BB*HH), 256, ATTN_SMEM>>>(
        p_qbh, p_qbl, p_kbh, p_vth, p_gq);

    // 6. output projection (2-term A, guards output precision)
    mma_gemm<<<ggrid, 256, GEMM_SMEM_BYTES>>>(p_ch, p_cl, p_woh, out, bo);
}

// round 11
// speedup vs baseline: 6.4743x; 1.2767x over previous
#include <cuda_runtime.h>
#include <cuda_fp16.h>
#include <cstdint>
#include <math.h>

#define BB 2
#define TT 2048
#define DD 1024
#define HH 16
#define HD 64
#define NTOK (BB*TT)

#define GM 4096
#define GN 1024
#define GK 1024

#define THRESH_C 0.29514f
#define SHARP_C  15.0f

// ================= low-level helpers =================
#define CP_ASYNC16(dst_u32, src_ptr) \
    asm volatile("cp.async.cg.shared.global [%0], [%1], 16;" \
        :: "r"(dst_u32), "l"(src_ptr) : "memory")
#define CP_COMMIT() asm volatile("cp.async.commit_group;" ::: "memory")
#define CP_WAIT1()  asm volatile("cp.async.wait_group 1;" ::: "memory")
#define CP_WAIT2()  asm volatile("cp.async.wait_group 2;" ::: "memory")

__device__ __forceinline__ uint32_t smem_to_u32(const void* smem_ptr) {
    uint32_t addr;
    asm("{ .reg .u64 tmp; cvta.to.shared.u64 tmp, %1; cvt.u32.u64 %0, tmp; }"
        : "=r"(addr) : "l"(smem_ptr));
    return addr;
}

#define MMA16816(d, a0, a1, a2, a3, b0, b1) \
    asm volatile("mma.sync.aligned.m16n8k16.row.col.f32.f16.f16.f32 " \
        "{%0,%1,%2,%3}, {%4,%5,%6,%7}, {%8,%9}, {%0,%1,%2,%3};" \
        : "+f"((d)[0]), "+f"((d)[1]), "+f"((d)[2]), "+f"((d)[3]) \
        : "r"(a0), "r"(a1), "r"(a2), "r"(a3), "r"(b0), "r"(b1))

#define LDMX4(r0, r1, r2, r3, addr) \
    asm volatile("ldmatrix.sync.aligned.m8n8.x4.shared.b16 {%0,%1,%2,%3}, [%4];" \
        : "=r"(r0), "=r"(r1), "=r"(r2), "=r"(r3) : "r"(addr))

__device__ __forceinline__ uint32_t packh2(float x, float y) {
    __half2 hp = __floats2half2_rn(x, y);
    return *(uint32_t*)&hp;
}

// ================= scratch =================
__device__ float g_qraw[NTOK*DD];
__device__ float g_kraw[NTOK*DD];
__device__ float g_v[NTOK*DD];
__device__ float g_gateq[BB*HH*TT];
__device__ float g_gatek[BB*HH*TT];

__device__ __half g_xh[NTOK*DD];      // raw x fp16 (A of V-proj)
__device__ __half g_xnh[NTOK*DD];     // layernormed x fp16 (A of Q/K-proj)
__device__ __half g_ch[NTOK*DD];      // collapse fp16 (A of out-proj)
__device__ __half g_wqh[DD*DD], g_wkh[DD*DD], g_wvh[DD*DD], g_woh[DD*DD];  // B fp16
__device__ __half g_qbh[NTOK*DD];     // normalized q fp16 (GEMM1 A)
__device__ __half g_kbh[NTOK*DD];     // normalized k fp16 (B side)
__device__ __half g_vth[BB*DD*TT];    // gk*V transposed fp16 (B side)

// ================= LayerNorm fused with fp16 conversions =================
__global__ __launch_bounds__(256) void ln_kernel(const float* __restrict__ x,
                                                 const float* __restrict__ w,
                                                 const float* __restrict__ b) {
    int row = blockIdx.x;
    int tid = threadIdx.x;
    const float4* xr = (const float4*)(x + (size_t)row * DD);
    float4 v = xr[tid];
    float s  = v.x + v.y + v.z + v.w;
    float sq = v.x*v.x + v.y*v.y + v.z*v.z + v.w*v.w;
    #pragma unroll
    for (int o = 16; o > 0; o >>= 1) {
        s  += __shfl_xor_sync(0xffffffffu, s,  o);
        sq += __shfl_xor_sync(0xffffffffu, sq, o);
    }
    __shared__ float ss[8], ssq[8];
    int wid = tid >> 5, lid = tid & 31;
    if (lid == 0) { ss[wid] = s; ssq[wid] = sq; }
    __syncthreads();
    float ts = 0.f, tsq = 0.f;
    #pragma unroll
    for (int i = 0; i < 8; i++) { ts += ss[i]; tsq += ssq[i]; }
    float mu  = ts * (1.0f/DD);
    float var = tsq * (1.0f/DD) - mu*mu;
    float inv = rsqrtf(var + 1e-5f);
    float4 wv = ((const float4*)w)[tid];
    float4 bv = ((const float4*)b)[tid];
    float4 o;
    o.x = (v.x - mu) * inv * wv.x + bv.x;
    o.y = (v.y - mu) * inv * wv.y + bv.y;
    o.z = (v.z - mu) * inv * wv.z + bv.z;
    o.w = (v.w - mu) * inv * wv.w + bv.w;

    int i4 = row * (DD/4) + tid;
    {
        uint2 hw = { packh2(v.x, v.y), packh2(v.z, v.w) };
        ((uint2*)g_xh)[i4] = hw;
    }
    {
        uint2 hw = { packh2(o.x, o.y), packh2(o.z, o.w) };
        ((uint2*)g_xnh)[i4] = hw;
    }
}

// ===== all 4 weights: W[K,N] -> Wt[N,K] transpose, fp16 (z-indexed) =====
__global__ __launch_bounds__(256) void tsplit4_kernel(const float* __restrict__ W0,
                                                      const float* __restrict__ W1,
                                                      const float* __restrict__ W2,
                                                      const float* __restrict__ W3) {
    __shared__ float tile[32][33];
    const float* W;
    __half* th;
    switch (blockIdx.z) {
        case 0: W = W0; th = g_wqh; break;
        case 1: W = W1; th = g_wkh; break;
        case 2: W = W2; th = g_wvh; break;
        default: W = W3; th = g_woh; break;
    }
    int bx = blockIdx.x * 32;
    int by = blockIdx.y * 32;
    int tx = threadIdx.x & 31;
    int ty = threadIdx.x >> 5;
    #pragma unroll
    for (int i = 0; i < 4; i++) {
        int k = by + ty + i*8;
        tile[ty + i*8][tx] = W[(size_t)k * DD + bx + tx];
    }
    __syncthreads();
    #pragma unroll
    for (int i = 0; i < 4; i++) {
        int n = bx + ty + i*8;
        int k = by + tx;
        th[(size_t)n * DD + k] = __float2half_rn(tile[tx][ty + i*8]);
    }
}

// ========== V[b][t][d] -> Vt[b*DD+d][t] transpose, gate_k premultiplied, fp16 ==========
__global__ __launch_bounds__(256) void vtsplit_kernel(const float* __restrict__ V,
                                                      const float* __restrict__ gatek,
                                                      __half* __restrict__ th) {
    __shared__ float tile[32][33];
    int b  = blockIdx.z;
    int t0 = blockIdx.x * 32;
    int d0 = blockIdx.y * 32;
    int tx = threadIdx.x & 31;
    int ty = threadIdx.x >> 5;
    #pragma unroll
    for (int i = 0; i < 4; i++) {
        int tt = t0 + ty + i*8;
        tile[ty + i*8][tx] = V[((size_t)(b*TT + tt)) * DD + d0 + tx];
    }
    __syncthreads();
    int h = d0 >> 6;
    float gk = gatek[((size_t)(b*HH + h)) * TT + t0 + tx];
    #pragma unroll
    for (int i = 0; i < 4; i++) {
        int d = d0 + ty + i*8;
        int tt = t0 + tx;
        th[((size_t)(b*DD + d)) * TT + tt] = __float2half_rn(tile[tx][ty + i*8] * gk);
    }
}

// ================= mma.sync GEMM, BK=64, 3-stage cp.async pipeline =================
// A fp16, B fp16.  Tile 128x128, BK=64, padded stride 72 halves (144 B rows).
#define PAD_K 72
#define ARR_BYTES (128*PAD_K*2)              // 18432
#define STAGE_BYTES (2*ARR_BYTES)            // 36864 (A + B)
#define GEMM_SMEM_BYTES (3*STAGE_BYTES)      // 110592

__device__ __forceinline__ void gemm_load_stage(uint32_t sm_u32, int stage,
        const __half* __restrict__ Ah, const __half* __restrict__ Bh,
        int m0, int n0, int k0, int t) {
    uint32_t sbase = sm_u32 + (uint32_t)stage * STAGE_BYTES;
    #pragma unroll
    for (int o = 0; o < 4; o++) {
        int linear = t + o*256;          // 0..1023
        int r  = linear >> 3;            // 0..127
        int c8 = linear & 7;             // 16B chunk in 128B row
        uint32_t soff = (uint32_t)(r*(PAD_K*2) + c8*16);
        size_t goffA = (size_t)(m0 + r) * GK + k0 + c8*8;
        size_t goffB = (size_t)(n0 + r) * GK + k0 + c8*8;
        CP_ASYNC16(sbase +             soff, Ah + goffA);
        CP_ASYNC16(sbase + ARR_BYTES + soff, Bh + goffB);
    }
}

__global__ __launch_bounds__(256) void mma_gemm(const __half* __restrict__ Ah,
                                                const __half* __restrict__ Bh,
                                                float* __restrict__ C,
                                                const float* __restrict__ bias) {
    extern __shared__ __half smb[];
    uint32_t sm_u32 = smem_to_u32(smb);
    int t = threadIdx.x;
    int wid = t >> 5, lane = t & 31;
    int wm = wid & 1;
    int wn = wid >> 1;
    int g  = lane >> 2;
    int tq = lane & 3;

    int m0 = blockIdx.y * 128, n0 = blockIdx.x * 128;

    float acc[4][4][4];
    #pragma unroll
    for (int mi = 0; mi < 4; mi++)
        #pragma unroll
        for (int ni = 0; ni < 4; ni++)
            #pragma unroll
            for (int r = 0; r < 4; r++) acc[mi][ni][r] = 0.f;

    int a_rsel = lane & 15;
    int a_ksel = (lane >> 4) * 8;
    int b_row  = lane & 7;
    int b_msel = (lane >> 4);
    int b_ksel = ((lane >> 3) & 1) * 8;

    const int NIT = GK / 64;   // 16
    gemm_load_stage(sm_u32, 0, Ah, Bh, m0, n0, 0, t);
    CP_COMMIT();
    gemm_load_stage(sm_u32, 1, Ah, Bh, m0, n0, 64, t);
    CP_COMMIT();

    int stage = 0;
    for (int it = 0; it < NIT; it++) {
        CP_WAIT1();
        __syncthreads();
        if (it + 2 < NIT) {
            int ns = stage + 2; if (ns >= 3) ns -= 3;
            gemm_load_stage(sm_u32, ns, Ah, Bh, m0, n0, (it+2)*64, t);
        }
        CP_COMMIT();

        uint32_t S   = sm_u32 + (uint32_t)stage * STAGE_BYTES;
        uint32_t uAh = S;
        uint32_t uBh = S + ARR_BYTES;

        #pragma unroll
        for (int kk = 0; kk < 64; kk += 16) {
            uint32_t ah[4][4];
            #pragma unroll
            for (int mi = 0; mi < 4; mi++) {
                uint32_t off = (uint32_t)(((wm*64 + mi*16 + a_rsel) * PAD_K + kk + a_ksel) * 2);
                LDMX4(ah[mi][0], ah[mi][1], ah[mi][2], ah[mi][3], uAh + off);
            }
            uint32_t bh[4][2];
            #pragma unroll
            for (int np = 0; np < 2; np++) {
                uint32_t off = (uint32_t)(((wn*32 + (np*2 + b_msel)*8 + b_row) * PAD_K + kk + b_ksel) * 2);
                uint32_t r0, r1, r2, r3;
                LDMX4(r0, r1, r2, r3, uBh + off);
                bh[np*2][0]=r0; bh[np*2][1]=r1; bh[np*2+1][0]=r2; bh[np*2+1][1]=r3;
            }
            #pragma unroll
            for (int ni = 0; ni < 4; ni++)
                #pragma unroll
                for (int mi = 0; mi < 4; mi++)
                    MMA16816(acc[mi][ni], ah[mi][0], ah[mi][1], ah[mi][2], ah[mi][3], bh[ni][0], bh[ni][1]);
        }
        if (++stage == 3) stage = 0;
    }

    #pragma unroll
    for (int mi = 0; mi < 4; mi++) {
        int row = m0 + wm*64 + mi*16 + g;
        #pragma unroll
        for (int ni = 0; ni < 4; ni++) {
            int col = n0 + wn*32 + ni*8 + tq*2;
            float b0 = 0.f, b1 = 0.f;
            if (bias) { b0 = bias[col]; b1 = bias[col+1]; }
            float2 v0 = { acc[mi][ni][0] + b0, acc[mi][ni][1] + b1 };
            float2 v1 = { acc[mi][ni][2] + b0, acc[mi][ni][3] + b1 };
            *(float2*)(C + (size_t)row * GN + col)       = v0;
            *(float2*)(C + (size_t)(row+8) * GN + col)   = v1;
        }
    }
}

// ======== l2-normalize + gate for BOTH q and k (y-indexed); emits fp16 ========
__global__ __launch_bounds__(256) void norm_gate2_kernel(const float* __restrict__ qraw,
                                                         const float* __restrict__ kraw,
                                                         const float* __restrict__ gqv,
                                                         const float* __restrict__ gkv) {
    bool isq = (blockIdx.y == 0);
    const float* raw = isq ? qraw : kraw;
    const float* g   = isq ? gqv : gkv;
    __half* oh       = isq ? g_qbh : g_kbh;
    float* gate      = isq ? g_gateq : g_gatek;

    int task = blockIdx.x * 8 + (threadIdx.x >> 5);
    int lane = threadIdx.x & 31;
    int token = task >> 4;
    int h = task & 15;
    size_t base = (size_t)token * DD + h * HD;
    float2 v = ((const float2*)(raw + base))[lane];
    float sq = v.x*v.x + v.y*v.y;
    #pragma unroll
    for (int o = 16; o > 0; o >>= 1) sq += __shfl_xor_sync(0xffffffffu, sq, o);
    float nrm = sqrtf(sq);
    float inv = 1.0f / fmaxf(nrm, 1e-12f);
    float nx = v.x * inv, ny = v.y * inv;
    ((uint32_t*)(oh + base))[lane] = packh2(nx, ny);
    float2 gv = ((const float2*)g)[lane];
    float gp = nx*gv.x + ny*gv.y;
    #pragma unroll
    for (int o = 16; o > 0; o >>= 1) gp += __shfl_xor_sync(0xffffffffu, gp, o);
    if (lane == 0) {
        int b = token / TT, t = token % TT;
        gate[((size_t)(b*HH + h)) * TT + t] = gp;
    }
}

// ================= attention: mma.sync fp16 (all 1-term), 4-stage pipeline =================
#define SC 64
#define ATTN_STG 18432              // Kh (9216) + Vh (9216)
#define ATTN_SMEM (4*ATTN_STG)      // 73728

__device__ __forceinline__ void attn_load_stage(uint32_t sb, int stage,
        int b, int h, int s0, int t,
        const __half* __restrict__ Kh, const __half* __restrict__ Vh) {
    uint32_t base = sb + (uint32_t)stage * ATTN_STG;
    int row_lo = t >> 3;
    int c = t & 7;
    #pragma unroll
    for (int i = 0; i < 4; i++) {
        int arr = i >> 1;
        int row = ((i & 1) << 5) + row_lo;
        uint32_t dst = base + (uint32_t)(arr*9216 + row*144 + c*16);
        const __half* src = (arr == 0)
            ? Kh + ((size_t)(b*TT + s0 + row))*DD + h*64 + c*8
            : Vh + ((size_t)(b*DD + h*64 + row))*TT + s0 + c*8;
        CP_ASYNC16(dst, src);
    }
}

__global__ __launch_bounds__(256) void attn_mma_kernel(
        const __half* __restrict__ Qh,
        const __half* __restrict__ Kh, const __half* __restrict__ Vh,
        const float* __restrict__ gateq) {
    extern __shared__ char smc[];
    uint32_t sb = smem_to_u32(smc);
    int t = threadIdx.x;
    int w = t >> 5, lane = t & 31;
    int g = lane >> 2, tq = lane & 3;
    int bh = blockIdx.y;
    int b = bh >> 4, h = bh & 15;
    int t0 = blockIdx.x * 128;
    int trow = t0 + w*16 + g;

    int b_row  = lane & 7;
    int b_msel = (lane >> 4);
    int b_ksel = ((lane >> 3) & 1) * 8;

    uint32_t aqh[4][4];
    {
        size_t r0 = ((size_t)(b*TT + trow))*DD + h*64;
        size_t r8 = r0 + 8*(size_t)DD;
        #pragma unroll
        for (int kq = 0; kq < 4; kq++) {
            int c = kq*16 + tq*2;
            aqh[kq][0] = *(const uint32_t*)(Qh + r0 + c);
            aqh[kq][1] = *(const uint32_t*)(Qh + r8 + c);
            aqh[kq][2] = *(const uint32_t*)(Qh + r0 + c + 8);
            aqh[kq][3] = *(const uint32_t*)(Qh + r8 + c + 8);
        }
    }
    float gq0 = gateq[(size_t)bh*TT + trow];
    float gq1 = gateq[(size_t)bh*TT + trow + 8];

    float cacc[8][4];
    #pragma unroll
    for (int di = 0; di < 8; di++)
        #pragma unroll
        for (int r = 0; r < 4; r++) cacc[di][r] = 0.f;

    const int NCH = TT / SC;
    attn_load_stage(sb, 0, b, h, 0,    t, Kh, Vh); CP_COMMIT();
    attn_load_stage(sb, 1, b, h, SC,   t, Kh, Vh); CP_COMMIT();
    attn_load_stage(sb, 2, b, h, 2*SC, t, Kh, Vh); CP_COMMIT();

    for (int ic = 0; ic < NCH; ic++) {
        CP_WAIT2();
        __syncthreads();
        if (ic + 3 < NCH)
            attn_load_stage(sb, (ic+3) & 3, b, h, (ic+3)*SC, t, Kh, Vh);
        CP_COMMIT();

        uint32_t stg = sb + (uint32_t)(ic & 3) * ATTN_STG;
        uint32_t uKh = stg;
        uint32_t uVh = stg + 9216;

        // ---- GEMM1: S = Q . K^T (1-term) ----
        float sacc[8][4];
        #pragma unroll
        for (int si = 0; si < 8; si++)
            #pragma unroll
            for (int r = 0; r < 4; r++) sacc[si][r] = 0.f;

        #pragma unroll
        for (int kk = 0; kk < 4; kk++) {
            uint32_t kfh[4][4];
            #pragma unroll
            for (int sp = 0; sp < 4; sp++) {
                uint32_t off = (uint32_t)(((sp*2 + b_msel)*8 + b_row)*144 + (kk*16 + b_ksel)*2);
                LDMX4(kfh[sp][0], kfh[sp][1], kfh[sp][2], kfh[sp][3], uKh + off);
            }
            #pragma unroll
            for (int sp = 0; sp < 4; sp++) {
                MMA16816(sacc[2*sp],   aqh[kk][0], aqh[kk][1], aqh[kk][2], aqh[kk][3], kfh[sp][0], kfh[sp][1]);
                MMA16816(sacc[2*sp+1], aqh[kk][0], aqh[kk][1], aqh[kk][2], aqh[kk][3], kfh[sp][2], kfh[sp][3]);
            }
        }

        // ---- modulation: sigmoid, fp16 pack ----
        uint32_t mh[4][4];
        #pragma unroll
        for (int j = 0; j < 4; j++) {
            #pragma unroll
            for (int half = 0; half < 2; half++) {
                int si = 2*j + half;
                float z00 = (sacc[si][0] - THRESH_C) * SHARP_C;
                float z01 = (sacc[si][1] - THRESH_C) * SHARP_C;
                float z10 = (sacc[si][2] - THRESH_C) * SHARP_C;
                float z11 = (sacc[si][3] - THRESH_C) * SHARP_C;
                float m00 = __fdividef(1.f, 1.f + __expf(-z00));
                float m01 = __fdividef(1.f, 1.f + __expf(-z01));
                float m10 = __fdividef(1.f, 1.f + __expf(-z10));
                float m11 = __fdividef(1.f, 1.f + __expf(-z11));
                mh[j][half*2 + 0] = packh2(m00, m01);
                mh[j][half*2 + 1] = packh2(m10, m11);
            }
        }

        // ---- GEMM2: C += M . (gk*V), 1-term ----
        #pragma unroll
        for (int j = 0; j < 4; j++) {
            uint32_t vfh[4][4];
            #pragma unroll
            for (int dp = 0; dp < 4; dp++) {
                uint32_t off = (uint32_t)(((dp*2 + b_msel)*8 + b_row)*144 + (j*16 + b_ksel)*2);
                LDMX4(vfh[dp][0], vfh[dp][1], vfh[dp][2], vfh[dp][3], uVh + off);
            }
            #pragma unroll
            for (int dp = 0; dp < 4; dp++) {
                MMA16816(cacc[2*dp],   mh[j][0], mh[j][1], mh[j][2], mh[j][3], vfh[dp][0], vfh[dp][1]);
                MMA16816(cacc[2*dp+1], mh[j][0], mh[j][1], mh[j][2], mh[j][3], vfh[dp][2], vfh[dp][3]);
            }
        }
    }

    // epilogue: apply gq, emit fp16 collapse (out-proj 1-term)
    size_t obase = ((size_t)(b*TT + trow))*DD + h*64;
    #pragma unroll
    for (int di = 0; di < 8; di++) {
        int col = di*8 + tq*2;
        float c00 = cacc[di][0]*gq0, c01 = cacc[di][1]*gq0;
        float c10 = cacc[di][2]*gq1, c11 = cacc[di][3]*gq1;
        *(uint32_t*)(g_ch + obase + col)                = packh2(c00, c01);
        *(uint32_t*)(g_ch + obase + 8*(size_t)DD + col) = packh2(c10, c11);
    }
}

// ================= launch =================
extern "C" void kernel_launch(void* const* d_in, const int* in_sizes, int n_in,
                              void* d_out, int out_size) {
    const float* x    = (const float*)d_in[0];
    const float* Wq   = (const float*)d_in[1];
    const float* Wk   = (const float*)d_in[2];
    const float* Wv   = (const float*)d_in[3];
    const float* gq   = (const float*)d_in[4];
    const float* gk   = (const float*)d_in[5];
    const float* Wo   = (const float*)d_in[6];
    const float* bo   = (const float*)d_in[7];
    const float* ln_w = (const float*)d_in[8];
    const float* ln_b = (const float*)d_in[9];
    float* out = (float*)d_out;

    float *p_qraw, *p_kraw, *p_v, *p_gq, *p_gk;
    cudaGetSymbolAddress((void**)&p_qraw, g_qraw);
    cudaGetSymbolAddress((void**)&p_kraw, g_kraw);
    cudaGetSymbolAddress((void**)&p_v,    g_v);
    cudaGetSymbolAddress((void**)&p_gq,   g_gateq);
    cudaGetSymbolAddress((void**)&p_gk,   g_gatek);

    __half *p_xh,*p_xnh,*p_ch;
    __half *p_wqh,*p_wkh,*p_wvh,*p_woh;
    __half *p_qbh,*p_kbh,*p_vth;
    cudaGetSymbolAddress((void**)&p_xh,  g_xh);
    cudaGetSymbolAddress((void**)&p_xnh, g_xnh);
    cudaGetSymbolAddress((void**)&p_ch,  g_ch);
    cudaGetSymbolAddress((void**)&p_wqh, g_wqh);
    cudaGetSymbolAddress((void**)&p_wkh, g_wkh);
    cudaGetSymbolAddress((void**)&p_wvh, g_wvh);
    cudaGetSymbolAddress((void**)&p_woh, g_woh);
    cudaGetSymbolAddress((void**)&p_qbh, g_qbh);
    cudaGetSymbolAddress((void**)&p_kbh, g_kbh);
    cudaGetSymbolAddress((void**)&p_vth, g_vth);

    cudaFuncSetAttribute(mma_gemm, cudaFuncAttributeMaxDynamicSharedMemorySize, GEMM_SMEM_BYTES);
    cudaFuncSetAttribute(attn_mma_kernel, cudaFuncAttributeMaxDynamicSharedMemorySize, ATTN_SMEM);

    // 1. LayerNorm + fp16 conversions
    ln_kernel<<<NTOK, 256>>>(x, ln_w, ln_b);

    // 2. weight transpose (fp16), z-indexed
    tsplit4_kernel<<<dim3(DD/32, DD/32, 4), 256>>>(Wq, Wk, Wv, Wo);

    // 3. QKV projections (1-term, BK=64)
    dim3 ggrid(GN/128, GM/128);
    mma_gemm<<<ggrid, 256, GEMM_SMEM_BYTES>>>(p_xnh, p_wqh, p_qraw, nullptr);
    mma_gemm<<<ggrid, 256, GEMM_SMEM_BYTES>>>(p_xnh, p_wkh, p_kraw, nullptr);
    mma_gemm<<<ggrid, 256, GEMM_SMEM_BYTES>>>(p_xh,  p_wvh, p_v,    nullptr);

    // 4. normalize + gates (q & k fused); V transpose
    norm_gate2_kernel<<<dim3((NTOK*HH)/8, 2), 256>>>(p_qraw, p_kraw, gq, gk);
    vtsplit_kernel<<<dim3(TT/32, DD/32, BB), 256>>>(p_v, p_gk, p_vth);

    // 5. attention (all 1-term)
    attn_mma_kernel<<<dim3(TT/128, BB*HH), 256, ATTN_SMEM>>>(
        p_qbh, p_kbh, p_vth, p_gq);

    // 6. output projection (1-term, BK=64)
    mma_gemm<<<ggrid, 256, GEMM_SMEM_BYTES>>>(p_ch, p_woh, out, bo);
}

// round 12
// speedup vs baseline: 6.8083x; 1.0516x over previous
#include <cuda_runtime.h>
#include <cuda_fp16.h>
#include <cstdint>
#include <math.h>

#define BB 2
#define TT 2048
#define DD 1024
#define HH 16
#define HD 64
#define NTOK (BB*TT)

#define GM 4096
#define GN 1024
#define GK 1024

#define THRESH_C 0.29514f
#define SHARP_C  15.0f

// ================= low-level helpers =================
#define CP_ASYNC16(dst_u32, src_ptr) \
    asm volatile("cp.async.cg.shared.global [%0], [%1], 16;" \
        :: "r"(dst_u32), "l"(src_ptr) : "memory")
#define CP_COMMIT() asm volatile("cp.async.commit_group;" ::: "memory")
#define CP_WAIT0()  asm volatile("cp.async.wait_group 0;" ::: "memory")

__device__ __forceinline__ uint32_t smem_to_u32(const void* smem_ptr) {
    uint32_t addr;
    asm("{ .reg .u64 tmp; cvta.to.shared.u64 tmp, %1; cvt.u32.u64 %0, tmp; }"
        : "=r"(addr) : "l"(smem_ptr));
    return addr;
}

#define MMA16816(d, a0, a1, a2, a3, b0, b1) \
    asm volatile("mma.sync.aligned.m16n8k16.row.col.f32.f16.f16.f32 " \
        "{%0,%1,%2,%3}, {%4,%5,%6,%7}, {%8,%9}, {%0,%1,%2,%3};" \
        : "+f"((d)[0]), "+f"((d)[1]), "+f"((d)[2]), "+f"((d)[3]) \
        : "r"(a0), "r"(a1), "r"(a2), "r"(a3), "r"(b0), "r"(b1))

#define LDMX4(r0, r1, r2, r3, addr) \
    asm volatile("ldmatrix.sync.aligned.m8n8.x4.shared.b16 {%0,%1,%2,%3}, [%4];" \
        : "=r"(r0), "=r"(r1), "=r"(r2), "=r"(r3) : "r"(addr))

__device__ __forceinline__ uint32_t packh2(float x, float y) {
    __half2 hp = __floats2half2_rn(x, y);
    return *(uint32_t*)&hp;
}

// ================= scratch =================
__device__ float g_qraw[NTOK*DD];
__device__ float g_kraw[NTOK*DD];
__device__ float g_v[NTOK*DD];
__device__ float g_gateq[BB*HH*TT];
__device__ float g_gatek[BB*HH*TT];

__device__ __half g_xh[NTOK*DD];      // raw x fp16 (A of V-proj)
__device__ __half g_xnh[NTOK*DD];     // layernormed x fp16 (A of Q/K-proj)
__device__ __half g_ch[NTOK*DD];      // collapse fp16 (A of out-proj)
__device__ __half g_wqh[DD*DD], g_wkh[DD*DD], g_wvh[DD*DD], g_woh[DD*DD];  // B fp16
__device__ __half g_qbh[NTOK*DD];     // normalized q fp16 (GEMM1 A)
__device__ __half g_kbh[NTOK*DD];     // normalized k fp16 (B side)
__device__ __half g_vth[BB*DD*TT];    // gk*V transposed fp16 (B side)

// ================= LayerNorm fused with fp16 conversions =================
__global__ __launch_bounds__(256) void ln_kernel(const float* __restrict__ x,
                                                 const float* __restrict__ w,
                                                 const float* __restrict__ b) {
    int row = blockIdx.x;
    int tid = threadIdx.x;
    const float4* xr = (const float4*)(x + (size_t)row * DD);
    float4 v = xr[tid];
    float s  = v.x + v.y + v.z + v.w;
    float sq = v.x*v.x + v.y*v.y + v.z*v.z + v.w*v.w;
    #pragma unroll
    for (int o = 16; o > 0; o >>= 1) {
        s  += __shfl_xor_sync(0xffffffffu, s,  o);
        sq += __shfl_xor_sync(0xffffffffu, sq, o);
    }
    __shared__ float ss[8], ssq[8];
    int wid = tid >> 5, lid = tid & 31;
    if (lid == 0) { ss[wid] = s; ssq[wid] = sq; }
    __syncthreads();
    float ts = 0.f, tsq = 0.f;
    #pragma unroll
    for (int i = 0; i < 8; i++) { ts += ss[i]; tsq += ssq[i]; }
    float mu  = ts * (1.0f/DD);
    float var = tsq * (1.0f/DD) - mu*mu;
    float inv = rsqrtf(var + 1e-5f);
    float4 wv = ((const float4*)w)[tid];
    float4 bv = ((const float4*)b)[tid];
    float4 o;
    o.x = (v.x - mu) * inv * wv.x + bv.x;
    o.y = (v.y - mu) * inv * wv.y + bv.y;
    o.z = (v.z - mu) * inv * wv.z + bv.z;
    o.w = (v.w - mu) * inv * wv.w + bv.w;

    int i4 = row * (DD/4) + tid;
    {
        uint2 hw = { packh2(v.x, v.y), packh2(v.z, v.w) };
        ((uint2*)g_xh)[i4] = hw;
    }
    {
        uint2 hw = { packh2(o.x, o.y), packh2(o.z, o.w) };
        ((uint2*)g_xnh)[i4] = hw;
    }
}

// ===== all 4 weights: W[K,N] -> Wt[N,K] transpose, fp16 (z-indexed) =====
__global__ __launch_bounds__(256) void tsplit4_kernel(const float* __restrict__ W0,
                                                      const float* __restrict__ W1,
                                                      const float* __restrict__ W2,
                                                      const float* __restrict__ W3) {
    __shared__ float tile[32][33];
    const float* W;
    __half* th;
    switch (blockIdx.z) {
        case 0: W = W0; th = g_wqh; break;
        case 1: W = W1; th = g_wkh; break;
        case 2: W = W2; th = g_wvh; break;
        default: W = W3; th = g_woh; break;
    }
    int bx = blockIdx.x * 32;
    int by = blockIdx.y * 32;
    int tx = threadIdx.x & 31;
    int ty = threadIdx.x >> 5;
    #pragma unroll
    for (int i = 0; i < 4; i++) {
        int k = by + ty + i*8;
        tile[ty + i*8][tx] = W[(size_t)k * DD + bx + tx];
    }
    __syncthreads();
    #pragma unroll
    for (int i = 0; i < 4; i++) {
        int n = bx + ty + i*8;
        int k = by + tx;
        th[(size_t)n * DD + k] = __float2half_rn(tile[tx][ty + i*8]);
    }
}

// ========== V[b][t][d] -> Vt[b*DD+d][t] transpose, gate_k premultiplied, fp16 ==========
__global__ __launch_bounds__(256) void vtsplit_kernel(const float* __restrict__ V,
                                                      const float* __restrict__ gatek,
                                                      __half* __restrict__ th) {
    __shared__ float tile[32][33];
    int b  = blockIdx.z;
    int t0 = blockIdx.x * 32;
    int d0 = blockIdx.y * 32;
    int tx = threadIdx.x & 31;
    int ty = threadIdx.x >> 5;
    #pragma unroll
    for (int i = 0; i < 4; i++) {
        int tt = t0 + ty + i*8;
        tile[ty + i*8][tx] = V[((size_t)(b*TT + tt)) * DD + d0 + tx];
    }
    __syncthreads();
    int h = d0 >> 6;
    float gk = gatek[((size_t)(b*HH + h)) * TT + t0 + tx];
    #pragma unroll
    for (int i = 0; i < 4; i++) {
        int d = d0 + ty + i*8;
        int tt = t0 + tx;
        th[((size_t)(b*DD + d)) * TT + tt] = __float2half_rn(tile[tx][ty + i*8] * gk);
    }
}

// ================= mma.sync GEMM body, BK=64, 2-stage cp.async pipeline =================
#define PAD_K 72
#define ARR_BYTES (128*PAD_K*2)              // 18432
#define STAGE_BYTES (2*ARR_BYTES)            // 36864 (A + B)
#define GEMM_SMEM_BYTES (2*STAGE_BYTES)      // 73728 -> 3 CTAs/SM resident

__device__ __forceinline__ void gemm_load_stage(uint32_t sm_u32, int stage,
        const __half* __restrict__ Ah, const __half* __restrict__ Bh,
        int m0, int n0, int k0, int t) {
    uint32_t sbase = sm_u32 + (uint32_t)stage * STAGE_BYTES;
    #pragma unroll
    for (int o = 0; o < 4; o++) {
        int linear = t + o*256;          // 0..1023
        int r  = linear >> 3;            // 0..127
        int c8 = linear & 7;             // 16B chunk in 128B row
        uint32_t soff = (uint32_t)(r*(PAD_K*2) + c8*16);
        size_t goffA = (size_t)(m0 + r) * GK + k0 + c8*8;
        size_t goffB = (size_t)(n0 + r) * GK + k0 + c8*8;
        CP_ASYNC16(sbase +             soff, Ah + goffA);
        CP_ASYNC16(sbase + ARR_BYTES + soff, Bh + goffB);
    }
}

__device__ __forceinline__ void gemm_body(uint32_t sm_u32,
        const __half* __restrict__ Ah, const __half* __restrict__ Bh,
        float* __restrict__ C, const float* __restrict__ bias,
        int m0, int n0, int t) {
    int wid = t >> 5, lane = t & 31;
    int wm = wid & 1;
    int wn = wid >> 1;
    int g  = lane >> 2;
    int tq = lane & 3;

    float acc[4][4][4];
    #pragma unroll
    for (int mi = 0; mi < 4; mi++)
        #pragma unroll
        for (int ni = 0; ni < 4; ni++)
            #pragma unroll
            for (int r = 0; r < 4; r++) acc[mi][ni][r] = 0.f;

    int a_rsel = lane & 15;
    int a_ksel = (lane >> 4) * 8;
    int b_row  = lane & 7;
    int b_msel = (lane >> 4);
    int b_ksel = ((lane >> 3) & 1) * 8;

    const int NIT = GK / 64;   // 16
    gemm_load_stage(sm_u32, 0, Ah, Bh, m0, n0, 0, t);
    CP_COMMIT();

    for (int it = 0; it < NIT; it++) {
        CP_WAIT0();
        __syncthreads();
        if (it + 1 < NIT) {
            gemm_load_stage(sm_u32, (it+1) & 1, Ah, Bh, m0, n0, (it+1)*64, t);
            CP_COMMIT();
        }
        uint32_t S   = sm_u32 + (uint32_t)(it & 1) * STAGE_BYTES;
        uint32_t uAh = S;
        uint32_t uBh = S + ARR_BYTES;

        #pragma unroll
        for (int kk = 0; kk < 64; kk += 16) {
            uint32_t ah[4][4];
            #pragma unroll
            for (int mi = 0; mi < 4; mi++) {
                uint32_t off = (uint32_t)(((wm*64 + mi*16 + a_rsel) * PAD_K + kk + a_ksel) * 2);
                LDMX4(ah[mi][0], ah[mi][1], ah[mi][2], ah[mi][3], uAh + off);
            }
            uint32_t bh[4][2];
            #pragma unroll
            for (int np = 0; np < 2; np++) {
                uint32_t off = (uint32_t)(((wn*32 + (np*2 + b_msel)*8 + b_row) * PAD_K + kk + b_ksel) * 2);
                uint32_t r0, r1, r2, r3;
                LDMX4(r0, r1, r2, r3, uBh + off);
                bh[np*2][0]=r0; bh[np*2][1]=r1; bh[np*2+1][0]=r2; bh[np*2+1][1]=r3;
            }
            #pragma unroll
            for (int ni = 0; ni < 4; ni++)
                #pragma unroll
                for (int mi = 0; mi < 4; mi++)
                    MMA16816(acc[mi][ni], ah[mi][0], ah[mi][1], ah[mi][2], ah[mi][3], bh[ni][0], bh[ni][1]);
        }
    }

    #pragma unroll
    for (int mi = 0; mi < 4; mi++) {
        int row = m0 + wm*64 + mi*16 + g;
        #pragma unroll
        for (int ni = 0; ni < 4; ni++) {
            int col = n0 + wn*32 + ni*8 + tq*2;
            float b0 = 0.f, b1 = 0.f;
            if (bias) { b0 = bias[col]; b1 = bias[col+1]; }
            float2 v0 = { acc[mi][ni][0] + b0, acc[mi][ni][1] + b1 };
            float2 v1 = { acc[mi][ni][2] + b0, acc[mi][ni][3] + b1 };
            *(float2*)(C + (size_t)row * GN + col)       = v0;
            *(float2*)(C + (size_t)(row+8) * GN + col)   = v1;
        }
    }
}

// ---- fused Q/K/V projection: z selects (A, B, C) ----
__global__ __launch_bounds__(256) void qkv_gemm() {
    extern __shared__ __half smb[];
    uint32_t sm_u32 = smem_to_u32(smb);
    const __half *Ah, *Bh;
    float* C;
    switch (blockIdx.z) {
        case 0:  Ah = g_xnh; Bh = g_wqh; C = g_qraw; break;
        case 1:  Ah = g_xnh; Bh = g_wkh; C = g_kraw; break;
        default: Ah = g_xh;  Bh = g_wvh; C = g_v;    break;
    }
    gemm_body(sm_u32, Ah, Bh, C, nullptr, blockIdx.y * 128, blockIdx.x * 128, threadIdx.x);
}

// ---- output projection (with bias) ----
__global__ __launch_bounds__(256) void out_gemm(float* __restrict__ C,
                                                const float* __restrict__ bias) {
    extern __shared__ __half smb[];
    uint32_t sm_u32 = smem_to_u32(smb);
    gemm_body(sm_u32, g_ch, g_woh, C, bias, blockIdx.y * 128, blockIdx.x * 128, threadIdx.x);
}

// ======== l2-normalize + gate for BOTH q and k (y-indexed); emits fp16 ========
__global__ __launch_bounds__(256) void norm_gate2_kernel(const float* __restrict__ qraw,
                                                         const float* __restrict__ kraw,
                                                         const float* __restrict__ gqv,
                                                         const float* __restrict__ gkv) {
    bool isq = (blockIdx.y == 0);
    const float* raw = isq ? qraw : kraw;
    const float* g   = isq ? gqv : gkv;
    __half* oh       = isq ? g_qbh : g_kbh;
    float* gate      = isq ? g_gateq : g_gatek;

    int task = blockIdx.x * 8 + (threadIdx.x >> 5);
    int lane = threadIdx.x & 31;
    int token = task >> 4;
    int h = task & 15;
    size_t base = (size_t)token * DD + h * HD;
    float2 v = ((const float2*)(raw + base))[lane];
    float sq = v.x*v.x + v.y*v.y;
    #pragma unroll
    for (int o = 16; o > 0; o >>= 1) sq += __shfl_xor_sync(0xffffffffu, sq, o);
    float nrm = sqrtf(sq);
    float inv = 1.0f / fmaxf(nrm, 1e-12f);
    float nx = v.x * inv, ny = v.y * inv;
    ((uint32_t*)(oh + base))[lane] = packh2(nx, ny);
    float2 gv = ((const float2*)g)[lane];
    float gp = nx*gv.x + ny*gv.y;
    #pragma unroll
    for (int o = 16; o > 0; o >>= 1) gp += __shfl_xor_sync(0xffffffffu, gp, o);
    if (lane == 0) {
        int b = token / TT, t = token % TT;
        gate[((size_t)(b*HH + h)) * TT + t] = gp;
    }
}

// ======== attention: mma.sync fp16, 2-stage x 128-s stages (two 64-s halves) ========
#define HSTG 18432                  // one 64-s half: Kh (9216) + Vh (9216)
#define ATTN_STG (2*HSTG)           // 36864 per 128-s stage
#define ATTN_SMEM (2*ATTN_STG)      // 73728 -> 3 CTAs/SM resident

__device__ __forceinline__ void attn_load_half(uint32_t hbase,
        int b, int h, int s0, int t,
        const __half* __restrict__ Kh, const __half* __restrict__ Vh) {
    int row_lo = t >> 3;
    int c = t & 7;
    #pragma unroll
    for (int i = 0; i < 4; i++) {
        int arr = i >> 1;
        int row = ((i & 1) << 5) + row_lo;
        uint32_t dst = hbase + (uint32_t)(arr*9216 + row*144 + c*16);
        const __half* src = (arr == 0)
            ? Kh + ((size_t)(b*TT + s0 + row))*DD + h*64 + c*8
            : Vh + ((size_t)(b*DD + h*64 + row))*TT + s0 + c*8;
        CP_ASYNC16(dst, src);
    }
}

__global__ __launch_bounds__(256) void attn_mma_kernel(
        const __half* __restrict__ Qh,
        const __half* __restrict__ Kh, const __half* __restrict__ Vh,
        const float* __restrict__ gateq) {
    extern __shared__ char smc[];
    uint32_t sb = smem_to_u32(smc);
    int t = threadIdx.x;
    int w = t >> 5, lane = t & 31;
    int g = lane >> 2, tq = lane & 3;
    int bh = blockIdx.y;
    int b = bh >> 4, h = bh & 15;
    int t0 = blockIdx.x * 128;
    int trow = t0 + w*16 + g;

    int b_row  = lane & 7;
    int b_msel = (lane >> 4);
    int b_ksel = ((lane >> 3) & 1) * 8;

    uint32_t aqh[4][4];
    {
        size_t r0 = ((size_t)(b*TT + trow))*DD + h*64;
        size_t r8 = r0 + 8*(size_t)DD;
        #pragma unroll
        for (int kq = 0; kq < 4; kq++) {
            int c = kq*16 + tq*2;
            aqh[kq][0] = *(const uint32_t*)(Qh + r0 + c);
            aqh[kq][1] = *(const uint32_t*)(Qh + r8 + c);
            aqh[kq][2] = *(const uint32_t*)(Qh + r0 + c + 8);
            aqh[kq][3] = *(const uint32_t*)(Qh + r8 + c + 8);
        }
    }
    float gq0 = gateq[(size_t)bh*TT + trow];
    float gq1 = gateq[(size_t)bh*TT + trow + 8];

    float cacc[8][4];
    #pragma unroll
    for (int di = 0; di < 8; di++)
        #pragma unroll
        for (int r = 0; r < 4; r++) cacc[di][r] = 0.f;

    const int NCH = TT / 128;   // 16 stages of 128 s
    // prologue: stage 0 (both halves)
    attn_load_half(sb,        b, h, 0,  t, Kh, Vh);
    attn_load_half(sb + HSTG, b, h, 64, t, Kh, Vh);
    CP_COMMIT();

    for (int ic = 0; ic < NCH; ic++) {
        CP_WAIT0();
        __syncthreads();
        if (ic + 1 < NCH) {
            uint32_t nbase = sb + (uint32_t)((ic+1) & 1) * ATTN_STG;
            attn_load_half(nbase,        b, h, (ic+1)*128,      t, Kh, Vh);
            attn_load_half(nbase + HSTG, b, h, (ic+1)*128 + 64, t, Kh, Vh);
            CP_COMMIT();
        }
        uint32_t stg = sb + (uint32_t)(ic & 1) * ATTN_STG;

        #pragma unroll
        for (int half = 0; half < 2; half++) {
            uint32_t uKh = stg + (uint32_t)half * HSTG;
            uint32_t uVh = uKh + 9216;

            // ---- GEMM1: S = Q . K^T ----
            float sacc[8][4];
            #pragma unroll
            for (int si = 0; si < 8; si++)
                #pragma unroll
                for (int r = 0; r < 4; r++) sacc[si][r] = 0.f;

            #pragma unroll
            for (int kk = 0; kk < 4; kk++) {
                uint32_t kfh[4][4];
                #pragma unroll
                for (int sp = 0; sp < 4; sp++) {
                    uint32_t off = (uint32_t)(((sp*2 + b_msel)*8 + b_row)*144 + (kk*16 + b_ksel)*2);
                    LDMX4(kfh[sp][0], kfh[sp][1], kfh[sp][2], kfh[sp][3], uKh + off);
                }
                #pragma unroll
                for (int sp = 0; sp < 4; sp++) {
                    MMA16816(sacc[2*sp],   aqh[kk][0], aqh[kk][1], aqh[kk][2], aqh[kk][3], kfh[sp][0], kfh[sp][1]);
                    MMA16816(sacc[2*sp+1], aqh[kk][0], aqh[kk][1], aqh[kk][2], aqh[kk][3], kfh[sp][2], kfh[sp][3]);
                }
            }

            // ---- modulation: sigmoid, fp16 pack ----
            uint32_t mh[4][4];
            #pragma unroll
            for (int j = 0; j < 4; j++) {
                #pragma unroll
                for (int hv = 0; hv < 2; hv++) {
                    int si = 2*j + hv;
                    float z00 = (sacc[si][0] - THRESH_C) * SHARP_C;
                    float z01 = (sacc[si][1] - THRESH_C) * SHARP_C;
                    float z10 = (sacc[si][2] - THRESH_C) * SHARP_C;
                    float z11 = (sacc[si][3] - THRESH_C) * SHARP_C;
                    float m00 = __fdividef(1.f, 1.f + __expf(-z00));
                    float m01 = __fdividef(1.f, 1.f + __expf(-z01));
                    float m10 = __fdividef(1.f, 1.f + __expf(-z10));
                    float m11 = __fdividef(1.f, 1.f + __expf(-z11));
                    mh[j][hv*2 + 0] = packh2(m00, m01);
                    mh[j][hv*2 + 1] = packh2(m10, m11);
                }
            }

            // ---- GEMM2: C += M . (gk*V) ----
            #pragma unroll
            for (int j = 0; j < 4; j++) {
                uint32_t vfh[4][4];
                #pragma unroll
                for (int dp = 0; dp < 4; dp++) {
                    uint32_t off = (uint32_t)(((dp*2 + b_msel)*8 + b_row)*144 + (j*16 + b_ksel)*2);
                    LDMX4(vfh[dp][0], vfh[dp][1], vfh[dp][2], vfh[dp][3], uVh + off);
                }
                #pragma unroll
                for (int dp = 0; dp < 4; dp++) {
                    MMA16816(cacc[2*dp],   mh[j][0], mh[j][1], mh[j][2], mh[j][3], vfh[dp][0], vfh[dp][1]);
                    MMA16816(cacc[2*dp+1], mh[j][0], mh[j][1], mh[j][2], mh[j][3], vfh[dp][2], vfh[dp][3]);
                }
            }
        }
    }

    // epilogue: apply gq, emit fp16 collapse
    size_t obase = ((size_t)(b*TT + trow))*DD + h*64;
    #pragma unroll
    for (int di = 0; di < 8; di++) {
        int col = di*8 + tq*2;
        float c00 = cacc[di][0]*gq0, c01 = cacc[di][1]*gq0;
        float c10 = cacc[di][2]*gq1, c11 = cacc[di][3]*gq1;
        *(uint32_t*)(g_ch + obase + col)                = packh2(c00, c01);
        *(uint32_t*)(g_ch + obase + 8*(size_t)DD + col) = packh2(c10, c11);
    }
}

// ================= launch =================
extern "C" void kernel_launch(void* const* d_in, const int* in_sizes, int n_in,
                              void* d_out, int out_size) {
    const float* x    = (const float*)d_in[0];
    const float* Wq   = (const float*)d_in[1];
    const float* Wk   = (const float*)d_in[2];
    const float* Wv   = (const float*)d_in[3];
    const float* gq   = (const float*)d_in[4];
    const float* gk   = (const float*)d_in[5];
    const float* Wo   = (const float*)d_in[6];
    const float* bo   = (const float*)d_in[7];
    const float* ln_w = (const float*)d_in[8];
    const float* ln_b = (const float*)d_in[9];
    float* out = (float*)d_out;

    float *p_qraw, *p_kraw, *p_v, *p_gq, *p_gk;
    cudaGetSymbolAddress((void**)&p_qraw, g_qraw);
    cudaGetSymbolAddress((void**)&p_kraw, g_kraw);
    cudaGetSymbolAddress((void**)&p_v,    g_v);
    cudaGetSymbolAddress((void**)&p_gq,   g_gateq);
    cudaGetSymbolAddress((void**)&p_gk,   g_gatek);

    __half *p_qbh,*p_kbh,*p_vth;
    cudaGetSymbolAddress((void**)&p_qbh, g_qbh);
    cudaGetSymbolAddress((void**)&p_kbh, g_kbh);
    cudaGetSymbolAddress((void**)&p_vth, g_vth);

    cudaFuncSetAttribute(qkv_gemm, cudaFuncAttributeMaxDynamicSharedMemorySize, GEMM_SMEM_BYTES);
    cudaFuncSetAttribute(out_gemm, cudaFuncAttributeMaxDynamicSharedMemorySize, GEMM_SMEM_BYTES);
    cudaFuncSetAttribute(attn_mma_kernel, cudaFuncAttributeMaxDynamicSharedMemorySize, ATTN_SMEM);

    // 1. LayerNorm + fp16 conversions
    ln_kernel<<<NTOK, 256>>>(x, ln_w, ln_b);

    // 2. weight transpose (fp16), z-indexed
    tsplit4_kernel<<<dim3(DD/32, DD/32, 4), 256>>>(Wq, Wk, Wv, Wo);

    // 3. fused QKV projections (768 CTAs, 3 resident/SM)
    qkv_gemm<<<dim3(GN/128, GM/128, 3), 256, GEMM_SMEM_BYTES>>>();

    // 4. normalize + gates (q & k fused); V transpose
    norm_gate2_kernel<<<dim3((NTOK*HH)/8, 2), 256>>>(p_qraw, p_kraw, gq, gk);
    vtsplit_kernel<<<dim3(TT/32, DD/32, BB), 256>>>(p_v, p_gk, p_vth);

    // 5. attention (2-stage x 128-s)
    attn_mma_kernel<<<dim3(TT/128, BB*HH), 256, ATTN_SMEM>>>(
        p_qbh, p_kbh, p_vth, p_gq);

    // 6. output projection
    out_gemm<<<dim3(GN/128, GM/128), 256, GEMM_SMEM_BYTES>>>(out, bo);
}